// round 2
// baseline (speedup 1.0000x reference)
#include <cuda_runtime.h>
#include <math.h>

#define Bc 8
#define Lc 1024
#define Ec 512
#define Hc 8
#define Pc 2047
#define BHc (Bc * Hc)

#define OUT_ELEMS  (Bc * Lc * Ec)
#define ATTN_ELEMS (BHc * Lc * Lc)

typedef unsigned long long u64;

__device__ float g_proj[(size_t)Bc * Lc * 3 * Ec];   // (8192, 1536)
__device__ float g_pk[(size_t)Pc * Ec];              // (2047, 512)
__device__ float g_ctx[(size_t)Bc * Lc * Ec];        // (8192, 512)
__device__ float g_attn_scratch[(size_t)ATTN_ELEMS];

// ---------------- f32x2 helpers ----------------
__device__ __forceinline__ u64 dup2(float v) {
    u64 r; asm("mov.b64 %0, {%1, %1};" : "=l"(r) : "f"(v)); return r;
}
__device__ __forceinline__ void fma2(u64& d, u64 a, u64 b) {
    asm("fma.rn.f32x2 %0, %1, %2, %0;" : "+l"(d) : "l"(a), "l"(b));
}
__device__ __forceinline__ float2 unpk(u64 v) {
    float2 f; asm("mov.b64 {%0, %1}, %2;" : "=f"(f.x), "=f"(f.y) : "l"(v)); return f;
}

// ---------------------------------------------------------------------------
// SGEMM: C[M,N] = A[M,K] @ W[N,K]^T (+bias). 128x128 tile, 8x8 micro, FFMA2.
// A stored duplicated in smem so dup pairs load as one LDS.
// ---------------------------------------------------------------------------
__global__ __launch_bounds__(256) void sgemm_nt(
    const float* __restrict__ A_ext, int src_sel,
    const float* __restrict__ W, const float* __restrict__ bias,
    float* __restrict__ C_ext, int dst_sel, int M, int N, int K) {
    const float* A = (src_sel == 1) ? g_ctx : A_ext;
    float* C = (dst_sel == 1) ? g_proj : (dst_sel == 2) ? g_pk : C_ext;

    __shared__ float AsD[16][260];   // dup pairs: [k][2*m]
    __shared__ float Ws[16][132];    // [k][n]

    const int tid = threadIdx.x;
    const int tx = tid & 15, ty = tid >> 4;
    const int m0 = blockIdx.y << 7, n0 = blockIdx.x << 7;
    const int lr = tid >> 1;           // 0..127 row
    const int lq = (tid & 1) << 3;     // 0 or 8 (k offset)

    u64 acc[8][4];
#pragma unroll
    for (int i = 0; i < 8; i++)
#pragma unroll
        for (int j = 0; j < 4; j++) acc[i][j] = 0ull;

    for (int k0 = 0; k0 < K; k0 += 16) {
        float4 av0 = make_float4(0.f, 0.f, 0.f, 0.f), av1 = av0;
        if (m0 + lr < M) {
            const float* ap = &A[(size_t)(m0 + lr) * K + k0 + lq];
            av0 = *reinterpret_cast<const float4*>(ap);
            av1 = *reinterpret_cast<const float4*>(ap + 4);
        }
        const float* wp = &W[(size_t)(n0 + lr) * K + k0 + lq];
        float4 wv0 = *reinterpret_cast<const float4*>(wp);
        float4 wv1 = *reinterpret_cast<const float4*>(wp + 4);
        __syncthreads();
        float aw[8] = {av0.x, av0.y, av0.z, av0.w, av1.x, av1.y, av1.z, av1.w};
        float ww[8] = {wv0.x, wv0.y, wv0.z, wv0.w, wv1.x, wv1.y, wv1.z, wv1.w};
#pragma unroll
        for (int c = 0; c < 8; c++) {
            *reinterpret_cast<float2*>(&AsD[lq + c][2 * lr]) =
                make_float2(aw[c], aw[c]);
            Ws[lq + c][lr] = ww[c];
        }
        __syncthreads();
#pragma unroll
        for (int kk = 0; kk < 16; kk++) {
            ulonglong2 a01 = *reinterpret_cast<const ulonglong2*>(&AsD[kk][(ty << 4)]);
            ulonglong2 a23 = *reinterpret_cast<const ulonglong2*>(&AsD[kk][(ty << 4) + 4]);
            ulonglong2 a45 = *reinterpret_cast<const ulonglong2*>(&AsD[kk][(ty << 4) + 8]);
            ulonglong2 a67 = *reinterpret_cast<const ulonglong2*>(&AsD[kk][(ty << 4) + 12]);
            ulonglong2 w01 = *reinterpret_cast<const ulonglong2*>(&Ws[kk][(tx << 3)]);
            ulonglong2 w23 = *reinterpret_cast<const ulonglong2*>(&Ws[kk][(tx << 3) + 4]);
            u64 ad[8] = {a01.x, a01.y, a23.x, a23.y, a45.x, a45.y, a67.x, a67.y};
            u64 wd[4] = {w01.x, w01.y, w23.x, w23.y};
#pragma unroll
            for (int i = 0; i < 8; i++)
#pragma unroll
                for (int j = 0; j < 4; j++) fma2(acc[i][j], ad[i], wd[j]);
        }
    }

#pragma unroll
    for (int i = 0; i < 8; i++) {
        int m = m0 + (ty << 3) + i;
        if (m >= M) continue;
#pragma unroll
        for (int jp = 0; jp < 4; jp++) {
            int n = n0 + (tx << 3) + (jp << 1);
            float2 v = unpk(acc[i][jp]);
            if (bias) { v.x += bias[n]; v.y += bias[n + 1]; }
            *reinterpret_cast<float2*>(&C[(size_t)m * N + n]) = v;
        }
    }
}

// ---------------------------------------------------------------------------
// Fused attention. Grid (L/128, B*H), 256 threads.
// Tile 128q x 64k, micro 8q x 4k, all dot products in FFMA2.
// ---------------------------------------------------------------------------
#define O_QU  0
#define O_QV  8704
#define O_KT  17408
#define O_PKA 22016
#define O_PKB 34816
#define O_RM  47616
#define O_RS  47744
#define SMF   47872
#define SM_BYTES (SMF * 4)

__global__ __launch_bounds__(256, 1) void attn_kernel(
    const float* __restrict__ ubias, const float* __restrict__ vbias,
    float* __restrict__ attn_ext, int use_scratch) {
    extern __shared__ float sm[];
    float* attn = use_scratch ? g_attn_scratch : attn_ext;

    const int tid = threadIdx.x;
    const int tx = tid & 15, ty = tid >> 4;
    const int bh = blockIdx.y;
    const int b = bh >> 3, h = bh & 7;
    const int q0 = blockIdx.x << 7;
    const int qbase = ty << 3;      // 8 q rows/thread
    const int kbase = tx << 2;      // 4 k cols/thread
    const float scale = 0.04419417382415922f;  // 1/sqrt(512)

    // ---- load q tiles: QU (natural, d-major) and QV (lane-swapped) ----
    for (int idx = tid; idx < 128 * 64; idx += 256) {
        int qi = idx >> 6, d = idx & 63;
        float qv = g_proj[((size_t)(b * Lc + q0 + qi)) * 1536 + h * 192 + d];
        sm[O_QU + d * 136 + qi] = (qv + ubias[h * 64 + d]) * scale;
        sm[O_QV + d * 136 + (qi ^ 1)] = (qv + vbias[h * 64 + d]) * scale;
    }

    float m_run[8], s_run[8];
#pragma unroll
    for (int i = 0; i < 8; i++) { m_run[i] = -INFINITY; s_run[i] = 0.f; }

    // bd pv addressing, per j (parity fixed per thread per j)
    int pkoff[4];
#pragma unroll
    for (int j = 0; j < 4; j++) {
        int rs = kbase + j - qbase + 126;   // load start row for ip=0
        pkoff[j] = (rs & 1) ? (O_PKB + rs - 1) : (O_PKA + rs);
    }

    // ================= Phase 1: scores + streaming (m,s) =================
    for (int kt0 = 0; kt0 < Lc; kt0 += 64) {
        __syncthreads();
        // k tile, transposed [d][k]
        for (int idx = tid; idx < 64 * 64; idx += 256) {
            int kk = idx >> 6, d = idx & 63;
            sm[O_KT + d * 72 + kk] =
                g_proj[((size_t)(b * Lc + kt0 + kk)) * 1536 + h * 192 + 64 + d];
        }
        // p_k window [d][r], r=0..191; PKB = shifted-by-one copy
        int pbase = kt0 - q0 + 896;
        for (int idx = tid; idx < 192 * 64; idx += 256) {
            int r = idx >> 6, d = idx & 63;
            int pr = pbase + r;
            float v = (pr < Pc) ? g_pk[(size_t)pr * 512 + h * 64 + d] : 0.f;
            sm[O_PKA + d * 200 + r] = v;
            if (r >= 1) sm[O_PKB + d * 200 + r - 1] = v;
        }
        __syncthreads();

        u64 aAC[4][4], aBD[4][4];
#pragma unroll
        for (int p = 0; p < 4; p++)
#pragma unroll
            for (int j = 0; j < 4; j++) { aAC[p][j] = 0ull; aBD[p][j] = 0ull; }

#pragma unroll 4
        for (int d = 0; d < 64; d++) {
            const float* QUd = sm + O_QU + d * 136 + qbase;
            ulonglong2 qa = *reinterpret_cast<const ulonglong2*>(QUd);
            ulonglong2 qb = *reinterpret_cast<const ulonglong2*>(QUd + 4);
            u64 ap[4] = {qa.x, qa.y, qb.x, qb.y};
            const float* KTd = sm + O_KT + d * 72 + kbase;
            u64 kd0 = dup2(KTd[0]), kd1 = dup2(KTd[1]);
            u64 kd2 = dup2(KTd[2]), kd3 = dup2(KTd[3]);
#pragma unroll
            for (int p = 0; p < 4; p++) {
                fma2(aAC[p][0], ap[p], kd0);
                fma2(aAC[p][1], ap[p], kd1);
                fma2(aAC[p][2], ap[p], kd2);
                fma2(aAC[p][3], ap[p], kd3);
            }
            const float* QVd = sm + O_QV + d * 136 + qbase;
            ulonglong2 va = *reinterpret_cast<const ulonglong2*>(QVd);
            ulonglong2 vb = *reinterpret_cast<const ulonglong2*>(QVd + 4);
            u64 vp[4] = {va.x, va.y, vb.x, vb.y};
            const float* pd = sm + d * 200;
#pragma unroll
            for (int j = 0; j < 4; j++) {
                const float* pj = pd + pkoff[j];
#pragma unroll
                for (int p = 0; p < 4; p++) {
                    u64 pv = *reinterpret_cast<const u64*>(pj - 2 * p);
                    fma2(aBD[p][j], vp[p], pv);
                }
            }
        }

        // unpack (bd lanes are swapped), softmax stats, write raw scores
        float sc[8][4];
#pragma unroll
        for (int p = 0; p < 4; p++)
#pragma unroll
            for (int j = 0; j < 4; j++) {
                float2 A = unpk(aAC[p][j]);
                float2 Bd = unpk(aBD[p][j]);
                sc[2 * p][j] = A.x + Bd.y;
                sc[2 * p + 1][j] = A.y + Bd.x;
            }
#pragma unroll
        for (int i = 0; i < 8; i++) {
            float mloc = fmaxf(fmaxf(sc[i][0], sc[i][1]), fmaxf(sc[i][2], sc[i][3]));
            float mnew = fmaxf(m_run[i], mloc);
            float sl = __expf(sc[i][0] - mnew) + __expf(sc[i][1] - mnew) +
                       __expf(sc[i][2] - mnew) + __expf(sc[i][3] - mnew);
            s_run[i] = s_run[i] * __expf(m_run[i] - mnew) + sl;
            m_run[i] = mnew;
            *reinterpret_cast<float4*>(
                &attn[((size_t)bh * Lc + (q0 + qbase + i)) * Lc + kt0 + kbase]) =
                make_float4(sc[i][0], sc[i][1], sc[i][2], sc[i][3]);
        }
    }

    // ---- combine (m,s) across 16 tx groups per q row ----
    __syncthreads();
    float* redm = sm + O_KT;    // 128*16
    float* reds = sm + O_PKA;   // 128*16
#pragma unroll
    for (int i = 0; i < 8; i++) {
        redm[(qbase + i) * 16 + tx] = m_run[i];
        reds[(qbase + i) * 16 + tx] = s_run[i];
    }
    __syncthreads();
    if (tid < 128) {
        float m = -INFINITY;
#pragma unroll
        for (int t = 0; t < 16; t++) m = fmaxf(m, redm[tid * 16 + t]);
        float s = 0.f;
#pragma unroll
        for (int t = 0; t < 16; t++)
            s += reds[tid * 16 + t] * __expf(redm[tid * 16 + t] - m);
        sm[O_RM + tid] = m;
        sm[O_RS + tid] = 1.f / s;
    }
    __syncthreads();

    // ================= Phase 2: normalize attn, ctx = attn @ v ===========
    u64 aCT[4][4];
#pragma unroll
    for (int p = 0; p < 4; p++)
#pragma unroll
        for (int j = 0; j < 4; j++) aCT[p][j] = 0ull;

    for (int kt0 = 0; kt0 < Lc; kt0 += 64) {
        __syncthreads();
        // attn tile: normalize raw -> write back + transposed smem [k][q]
        for (int idx = tid; idx < 128 * 64; idx += 256) {
            int qi = idx >> 6, kk = idx & 63;
            size_t gi = ((size_t)bh * Lc + (q0 + qi)) * Lc + kt0 + kk;
            float a = __expf(attn[gi] - sm[O_RM + qi]) * sm[O_RS + qi];
            attn[gi] = a;
            sm[O_PKA + kk * 136 + qi] = a;
        }
        // v tile [k][d]
        for (int idx = tid; idx < 64 * 64; idx += 256) {
            int kk = idx >> 6, d = idx & 63;
            sm[O_KT + kk * 68 + d] =
                g_proj[((size_t)(b * Lc + kt0 + kk)) * 1536 + h * 192 + 128 + d];
        }
        __syncthreads();
#pragma unroll 4
        for (int kk = 0; kk < 64; kk++) {
            const float* Ad = sm + O_PKA + kk * 136 + qbase;
            ulonglong2 a01 = *reinterpret_cast<const ulonglong2*>(Ad);
            ulonglong2 a23 = *reinterpret_cast<const ulonglong2*>(Ad + 4);
            u64 ap[4] = {a01.x, a01.y, a23.x, a23.y};
            const float* Vd = sm + O_KT + kk * 68 + kbase;
            u64 v0 = dup2(Vd[0]), v1 = dup2(Vd[1]);
            u64 v2 = dup2(Vd[2]), v3 = dup2(Vd[3]);
#pragma unroll
            for (int p = 0; p < 4; p++) {
                fma2(aCT[p][0], ap[p], v0);
                fma2(aCT[p][1], ap[p], v1);
                fma2(aCT[p][2], ap[p], v2);
                fma2(aCT[p][3], ap[p], v3);
            }
        }
    }

#pragma unroll
    for (int p = 0; p < 4; p++) {
        float2 r0 = unpk(aCT[p][0]), r1 = unpk(aCT[p][1]);
        float2 r2 = unpk(aCT[p][2]), r3 = unpk(aCT[p][3]);
        size_t base0 =
            ((size_t)(b * Lc + q0 + qbase + 2 * p)) * 512 + h * 64 + kbase;
        *reinterpret_cast<float4*>(&g_ctx[base0]) =
            make_float4(r0.x, r1.x, r2.x, r3.x);
        *reinterpret_cast<float4*>(&g_ctx[base0 + 512]) =
            make_float4(r0.y, r1.y, r2.y, r3.y);
    }
}

// ---------------------------------------------------------------------------
extern "C" void kernel_launch(void* const* d_in, const int* in_sizes, int n_in,
                              void* d_out, int out_size) {
    const float* x    = (const float*)d_in[0];
    const float* pos  = (const float*)d_in[1];
    const float* wqkv = (const float*)d_in[2];
    const float* wpos = (const float*)d_in[3];
    const float* wout = (const float*)d_in[4];
    const float* bout = (const float*)d_in[5];
    const float* ub   = (const float*)d_in[6];
    const float* vb   = (const float*)d_in[7];
    float* out = (float*)d_out;

    int attn_in_out = ((long long)out_size >= (long long)OUT_ELEMS + ATTN_ELEMS);
    float* attn_buf = attn_in_out ? (out + OUT_ELEMS) : nullptr;

    dim3 blk(256);
    // proj = x @ wqkv^T : (8192,1536)
    sgemm_nt<<<dim3(12, 64), blk>>>(x, 0, wqkv, nullptr, nullptr, 1,
                                    Bc * Lc, 3 * Ec, Ec);
    // p_k = pos @ wpos^T : (2047,512)
    sgemm_nt<<<dim3(4, 16), blk>>>(pos, 0, wpos, nullptr, nullptr, 2,
                                   Pc, Ec, Ec);

    cudaFuncSetAttribute(attn_kernel, cudaFuncAttributeMaxDynamicSharedMemorySize,
                         SM_BYTES);
    attn_kernel<<<dim3(Lc / 128, BHc), blk, SM_BYTES>>>(ub, vb, attn_buf,
                                                        attn_in_out ? 0 : 1);

    // out = ctx @ wout^T + bout : (8192,512)
    sgemm_nt<<<dim3(4, 64), blk>>>(nullptr, 1, wout, bout, out, 0,
                                   Bc * Lc, Ec, Ec);
}

// round 3
// speedup vs baseline: 1.0010x; 1.0010x over previous
#include <cuda_runtime.h>
#include <math.h>

#define Bc 8
#define Lc 1024
#define Ec 512
#define Hc 8
#define Pc 2047
#define BHc (Bc * Hc)

#define OUT_ELEMS  (Bc * Lc * Ec)
#define ATTN_ELEMS (BHc * Lc * Lc)

typedef unsigned long long u64;

__device__ float g_proj[(size_t)Bc * Lc * 3 * Ec];   // (8192, 1536)
__device__ float g_pk[(size_t)Pc * Ec];              // (2047, 512)
__device__ float g_ctx[(size_t)Bc * Lc * Ec];        // (8192, 512)
__device__ float g_attn_scratch[(size_t)ATTN_ELEMS];

// ---------------- f32x2 helpers ----------------
__device__ __forceinline__ u64 dup2(float v) {
    u64 r; asm("mov.b64 %0, {%1, %1};" : "=l"(r) : "f"(v)); return r;
}
__device__ __forceinline__ void fma2(u64& d, u64 a, u64 b) {
    asm("fma.rn.f32x2 %0, %1, %2, %0;" : "+l"(d) : "l"(a), "l"(b));
}
__device__ __forceinline__ float2 unpk(u64 v) {
    float2 f; asm("mov.b64 {%0, %1}, %2;" : "=f"(f.x), "=f"(f.y) : "l"(v)); return f;
}

// ---------------------------------------------------------------------------
// SGEMM: C[M,N] = A[M,K] @ W[N,K]^T (+bias). 128x128 tile, 8x8 micro, FFMA2.
// A stored duplicated in smem so dup pairs load as one LDS.
// ---------------------------------------------------------------------------
__global__ __launch_bounds__(256) void sgemm_nt(
    const float* __restrict__ A_ext, int src_sel,
    const float* __restrict__ W, const float* __restrict__ bias,
    float* __restrict__ C_ext, int dst_sel, int M, int N, int K) {
    const float* A = (src_sel == 1) ? g_ctx : A_ext;
    float* C = (dst_sel == 1) ? g_proj : (dst_sel == 2) ? g_pk : C_ext;

    __shared__ float AsD[16][260];   // dup pairs: [k][2*m]
    __shared__ float Ws[16][132];    // [k][n]

    const int tid = threadIdx.x;
    const int tx = tid & 15, ty = tid >> 4;
    const int m0 = blockIdx.y << 7, n0 = blockIdx.x << 7;
    const int lr = tid >> 1;           // 0..127 row
    const int lq = (tid & 1) << 3;     // 0 or 8 (k offset)

    u64 acc[8][4];
#pragma unroll
    for (int i = 0; i < 8; i++)
#pragma unroll
        for (int j = 0; j < 4; j++) acc[i][j] = 0ull;

    for (int k0 = 0; k0 < K; k0 += 16) {
        float4 av0 = make_float4(0.f, 0.f, 0.f, 0.f), av1 = av0;
        if (m0 + lr < M) {
            const float* ap = &A[(size_t)(m0 + lr) * K + k0 + lq];
            av0 = *reinterpret_cast<const float4*>(ap);
            av1 = *reinterpret_cast<const float4*>(ap + 4);
        }
        const float* wp = &W[(size_t)(n0 + lr) * K + k0 + lq];
        float4 wv0 = *reinterpret_cast<const float4*>(wp);
        float4 wv1 = *reinterpret_cast<const float4*>(wp + 4);
        __syncthreads();
        float aw[8] = {av0.x, av0.y, av0.z, av0.w, av1.x, av1.y, av1.z, av1.w};
        float ww[8] = {wv0.x, wv0.y, wv0.z, wv0.w, wv1.x, wv1.y, wv1.z, wv1.w};
#pragma unroll
        for (int c = 0; c < 8; c++) {
            *reinterpret_cast<float2*>(&AsD[lq + c][2 * lr]) =
                make_float2(aw[c], aw[c]);
            Ws[lq + c][lr] = ww[c];
        }
        __syncthreads();
#pragma unroll
        for (int kk = 0; kk < 16; kk++) {
            ulonglong2 a01 = *reinterpret_cast<const ulonglong2*>(&AsD[kk][(ty << 4)]);
            ulonglong2 a23 = *reinterpret_cast<const ulonglong2*>(&AsD[kk][(ty << 4) + 4]);
            ulonglong2 a45 = *reinterpret_cast<const ulonglong2*>(&AsD[kk][(ty << 4) + 8]);
            ulonglong2 a67 = *reinterpret_cast<const ulonglong2*>(&AsD[kk][(ty << 4) + 12]);
            ulonglong2 w01 = *reinterpret_cast<const ulonglong2*>(&Ws[kk][(tx << 3)]);
            ulonglong2 w23 = *reinterpret_cast<const ulonglong2*>(&Ws[kk][(tx << 3) + 4]);
            u64 ad[8] = {a01.x, a01.y, a23.x, a23.y, a45.x, a45.y, a67.x, a67.y};
            u64 wd[4] = {w01.x, w01.y, w23.x, w23.y};
#pragma unroll
            for (int i = 0; i < 8; i++)
#pragma unroll
                for (int j = 0; j < 4; j++) fma2(acc[i][j], ad[i], wd[j]);
        }
    }

#pragma unroll
    for (int i = 0; i < 8; i++) {
        int m = m0 + (ty << 3) + i;
        if (m >= M) continue;
#pragma unroll
        for (int jp = 0; jp < 4; jp++) {
            int n = n0 + (tx << 3) + (jp << 1);
            float2 v = unpk(acc[i][jp]);
            if (bias) { v.x += bias[n]; v.y += bias[n + 1]; }
            *reinterpret_cast<float2*>(&C[(size_t)m * N + n]) = v;
        }
    }
}

// ---------------------------------------------------------------------------
// Fused attention. Grid (L/128, B*H), 256 threads.
// Tile 128q x 64k, micro 8q x 4k, all dot products in FFMA2.
// ---------------------------------------------------------------------------
#define O_QU  0
#define O_QV  8704
#define O_KT  17408
#define O_PKA 22016
#define O_PKB 34816
#define O_RM  47616
#define O_RS  47744
#define SMF   47872
#define SM_BYTES (SMF * 4)

__global__ __launch_bounds__(256, 1) void attn_kernel(
    const float* __restrict__ ubias, const float* __restrict__ vbias,
    float* __restrict__ attn_ext, int use_scratch) {
    extern __shared__ float sm[];
    float* attn = use_scratch ? g_attn_scratch : attn_ext;

    const int tid = threadIdx.x;
    const int tx = tid & 15, ty = tid >> 4;
    const int bh = blockIdx.y;
    const int b = bh >> 3, h = bh & 7;
    const int q0 = blockIdx.x << 7;
    const int qbase = ty << 3;      // 8 q rows/thread
    const int kbase = tx << 2;      // 4 k cols/thread
    const float scale = 0.04419417382415922f;  // 1/sqrt(512)

    // ---- load q tiles: QU (natural, d-major) and QV (lane-swapped) ----
    for (int idx = tid; idx < 128 * 64; idx += 256) {
        int qi = idx >> 6, d = idx & 63;
        float qv = g_proj[((size_t)(b * Lc + q0 + qi)) * 1536 + h * 192 + d];
        sm[O_QU + d * 136 + qi] = (qv + ubias[h * 64 + d]) * scale;
        sm[O_QV + d * 136 + (qi ^ 1)] = (qv + vbias[h * 64 + d]) * scale;
    }

    float m_run[8], s_run[8];
#pragma unroll
    for (int i = 0; i < 8; i++) { m_run[i] = -INFINITY; s_run[i] = 0.f; }

    // bd pv addressing, per j (parity fixed per thread per j)
    int pkoff[4];
#pragma unroll
    for (int j = 0; j < 4; j++) {
        int rs = kbase + j - qbase + 126;   // load start row for ip=0
        pkoff[j] = (rs & 1) ? (O_PKB + rs - 1) : (O_PKA + rs);
    }

    // ================= Phase 1: scores + streaming (m,s) =================
    for (int kt0 = 0; kt0 < Lc; kt0 += 64) {
        __syncthreads();
        // k tile, transposed [d][k]
        for (int idx = tid; idx < 64 * 64; idx += 256) {
            int kk = idx >> 6, d = idx & 63;
            sm[O_KT + d * 72 + kk] =
                g_proj[((size_t)(b * Lc + kt0 + kk)) * 1536 + h * 192 + 64 + d];
        }
        // p_k window [d][r], r=0..191; PKB = shifted-by-one copy
        int pbase = kt0 - q0 + 896;
        for (int idx = tid; idx < 192 * 64; idx += 256) {
            int r = idx >> 6, d = idx & 63;
            int pr = pbase + r;
            float v = (pr < Pc) ? g_pk[(size_t)pr * 512 + h * 64 + d] : 0.f;
            sm[O_PKA + d * 200 + r] = v;
            if (r >= 1) sm[O_PKB + d * 200 + r - 1] = v;
        }
        __syncthreads();

        u64 aAC[4][4], aBD[4][4];
#pragma unroll
        for (int p = 0; p < 4; p++)
#pragma unroll
            for (int j = 0; j < 4; j++) { aAC[p][j] = 0ull; aBD[p][j] = 0ull; }

#pragma unroll 4
        for (int d = 0; d < 64; d++) {
            const float* QUd = sm + O_QU + d * 136 + qbase;
            ulonglong2 qa = *reinterpret_cast<const ulonglong2*>(QUd);
            ulonglong2 qb = *reinterpret_cast<const ulonglong2*>(QUd + 4);
            u64 ap[4] = {qa.x, qa.y, qb.x, qb.y};
            const float* KTd = sm + O_KT + d * 72 + kbase;
            u64 kd0 = dup2(KTd[0]), kd1 = dup2(KTd[1]);
            u64 kd2 = dup2(KTd[2]), kd3 = dup2(KTd[3]);
#pragma unroll
            for (int p = 0; p < 4; p++) {
                fma2(aAC[p][0], ap[p], kd0);
                fma2(aAC[p][1], ap[p], kd1);
                fma2(aAC[p][2], ap[p], kd2);
                fma2(aAC[p][3], ap[p], kd3);
            }
            const float* QVd = sm + O_QV + d * 136 + qbase;
            ulonglong2 va = *reinterpret_cast<const ulonglong2*>(QVd);
            ulonglong2 vb = *reinterpret_cast<const ulonglong2*>(QVd + 4);
            u64 vp[4] = {va.x, va.y, vb.x, vb.y};
            const float* pd = sm + d * 200;
#pragma unroll
            for (int j = 0; j < 4; j++) {
                const float* pj = pd + pkoff[j];
#pragma unroll
                for (int p = 0; p < 4; p++) {
                    u64 pv = *reinterpret_cast<const u64*>(pj - 2 * p);
                    fma2(aBD[p][j], vp[p], pv);
                }
            }
        }

        // unpack (bd lanes are swapped), softmax stats, write raw scores
        float sc[8][4];
#pragma unroll
        for (int p = 0; p < 4; p++)
#pragma unroll
            for (int j = 0; j < 4; j++) {
                float2 A = unpk(aAC[p][j]);
                float2 Bd = unpk(aBD[p][j]);
                sc[2 * p][j] = A.x + Bd.y;
                sc[2 * p + 1][j] = A.y + Bd.x;
            }
#pragma unroll
        for (int i = 0; i < 8; i++) {
            float mloc = fmaxf(fmaxf(sc[i][0], sc[i][1]), fmaxf(sc[i][2], sc[i][3]));
            float mnew = fmaxf(m_run[i], mloc);
            float sl = __expf(sc[i][0] - mnew) + __expf(sc[i][1] - mnew) +
                       __expf(sc[i][2] - mnew) + __expf(sc[i][3] - mnew);
            s_run[i] = s_run[i] * __expf(m_run[i] - mnew) + sl;
            m_run[i] = mnew;
            *reinterpret_cast<float4*>(
                &attn[((size_t)bh * Lc + (q0 + qbase + i)) * Lc + kt0 + kbase]) =
                make_float4(sc[i][0], sc[i][1], sc[i][2], sc[i][3]);
        }
    }

    // ---- combine (m,s) across 16 tx groups per q row ----
    __syncthreads();
    float* redm = sm + O_KT;    // 128*16
    float* reds = sm + O_PKA;   // 128*16
#pragma unroll
    for (int i = 0; i < 8; i++) {
        redm[(qbase + i) * 16 + tx] = m_run[i];
        reds[(qbase + i) * 16 + tx] = s_run[i];
    }
    __syncthreads();
    if (tid < 128) {
        float m = -INFINITY;
#pragma unroll
        for (int t = 0; t < 16; t++) m = fmaxf(m, redm[tid * 16 + t]);
        float s = 0.f;
#pragma unroll
        for (int t = 0; t < 16; t++)
            s += reds[tid * 16 + t] * __expf(redm[tid * 16 + t] - m);
        sm[O_RM + tid] = m;
        sm[O_RS + tid] = 1.f / s;
    }
    __syncthreads();

    // ================= Phase 2: normalize attn, ctx = attn @ v ===========
    u64 aCT[4][4];
#pragma unroll
    for (int p = 0; p < 4; p++)
#pragma unroll
        for (int j = 0; j < 4; j++) aCT[p][j] = 0ull;

    for (int kt0 = 0; kt0 < Lc; kt0 += 64) {
        __syncthreads();
        // attn tile: normalize raw -> write back + transposed smem [k][q]
        for (int idx = tid; idx < 128 * 64; idx += 256) {
            int qi = idx >> 6, kk = idx & 63;
            size_t gi = ((size_t)bh * Lc + (q0 + qi)) * Lc + kt0 + kk;
            float a = __expf(attn[gi] - sm[O_RM + qi]) * sm[O_RS + qi];
            attn[gi] = a;
            sm[O_PKA + kk * 136 + qi] = a;
        }
        // v tile [k][d]
        for (int idx = tid; idx < 64 * 64; idx += 256) {
            int kk = idx >> 6, d = idx & 63;
            sm[O_KT + kk * 68 + d] =
                g_proj[((size_t)(b * Lc + kt0 + kk)) * 1536 + h * 192 + 128 + d];
        }
        __syncthreads();
#pragma unroll 4
        for (int kk = 0; kk < 64; kk++) {
            const float* Ad = sm + O_PKA + kk * 136 + qbase;
            ulonglong2 a01 = *reinterpret_cast<const ulonglong2*>(Ad);
            ulonglong2 a23 = *reinterpret_cast<const ulonglong2*>(Ad + 4);
            u64 ap[4] = {a01.x, a01.y, a23.x, a23.y};
            const float* Vd = sm + O_KT + kk * 68 + kbase;
            u64 v0 = dup2(Vd[0]), v1 = dup2(Vd[1]);
            u64 v2 = dup2(Vd[2]), v3 = dup2(Vd[3]);
#pragma unroll
            for (int p = 0; p < 4; p++) {
                fma2(aCT[p][0], ap[p], v0);
                fma2(aCT[p][1], ap[p], v1);
                fma2(aCT[p][2], ap[p], v2);
                fma2(aCT[p][3], ap[p], v3);
            }
        }
    }

#pragma unroll
    for (int p = 0; p < 4; p++) {
        float2 r0 = unpk(aCT[p][0]), r1 = unpk(aCT[p][1]);
        float2 r2 = unpk(aCT[p][2]), r3 = unpk(aCT[p][3]);
        size_t base0 =
            ((size_t)(b * Lc + q0 + qbase + 2 * p)) * 512 + h * 64 + kbase;
        *reinterpret_cast<float4*>(&g_ctx[base0]) =
            make_float4(r0.x, r1.x, r2.x, r3.x);
        *reinterpret_cast<float4*>(&g_ctx[base0 + 512]) =
            make_float4(r0.y, r1.y, r2.y, r3.y);
    }
}

// ---------------------------------------------------------------------------
extern "C" void kernel_launch(void* const* d_in, const int* in_sizes, int n_in,
                              void* d_out, int out_size) {
    const float* x    = (const float*)d_in[0];
    const float* pos  = (const float*)d_in[1];
    const float* wqkv = (const float*)d_in[2];
    const float* wpos = (const float*)d_in[3];
    const float* wout = (const float*)d_in[4];
    const float* bout = (const float*)d_in[5];
    const float* ub   = (const float*)d_in[6];
    const float* vb   = (const float*)d_in[7];
    float* out = (float*)d_out;

    int attn_in_out = ((long long)out_size >= (long long)OUT_ELEMS + ATTN_ELEMS);
    float* attn_buf = attn_in_out ? (out + OUT_ELEMS) : nullptr;

    dim3 blk(256);
    // proj = x @ wqkv^T : (8192,1536)
    sgemm_nt<<<dim3(12, 64), blk>>>(x, 0, wqkv, nullptr, nullptr, 1,
                                    Bc * Lc, 3 * Ec, Ec);
    // p_k = pos @ wpos^T : (2047,512)
    sgemm_nt<<<dim3(4, 16), blk>>>(pos, 0, wpos, nullptr, nullptr, 2,
                                   Pc, Ec, Ec);

    cudaFuncSetAttribute(attn_kernel, cudaFuncAttributeMaxDynamicSharedMemorySize,
                         SM_BYTES);
    attn_kernel<<<dim3(Lc / 128, BHc), blk, SM_BYTES>>>(ub, vb, attn_buf,
                                                        attn_in_out ? 0 : 1);

    // out = ctx @ wout^T + bout : (8192,512)
    sgemm_nt<<<dim3(4, 64), blk>>>(nullptr, 1, wout, bout, out, 0,
                                   Bc * Lc, Ec, Ec);
}

// round 4
// speedup vs baseline: 2.7788x; 2.7761x over previous
#include <cuda_runtime.h>
#include <cuda_bf16.h>
#include <math.h>

#define Lc 1024
#define Pc 2047

#define OUT_ELEMS  (8 * 1024 * 512)
#define ATTN_ELEMS (64LL * 1024 * 1024)

__device__ float g_proj[(size_t)8192 * 1536];
__device__ float g_pk[(size_t)2048 * 512];
__device__ float g_ctx[(size_t)8192 * 512];
__device__ float g_inv[65536];
__device__ float g_attn_scratch[(size_t)ATTN_ELEMS];

// ------------------------- warp MMA helpers -------------------------------
__device__ __forceinline__ void mma_bf16(float* c, const unsigned* a,
                                         const unsigned* b) {
    asm volatile(
        "mma.sync.aligned.m16n8k16.row.col.f32.bf16.bf16.f32 "
        "{%0,%1,%2,%3}, {%4,%5,%6,%7}, {%8,%9}, {%0,%1,%2,%3};\n"
        : "+f"(c[0]), "+f"(c[1]), "+f"(c[2]), "+f"(c[3])
        : "r"(a[0]), "r"(a[1]), "r"(a[2]), "r"(a[3]), "r"(b[0]), "r"(b[1]));
}
__device__ __forceinline__ void ldsm4(unsigned addr, unsigned& r0, unsigned& r1,
                                      unsigned& r2, unsigned& r3) {
    asm volatile("ldmatrix.sync.aligned.m8n8.x4.shared.b16 {%0,%1,%2,%3}, [%4];"
                 : "=r"(r0), "=r"(r1), "=r"(r2), "=r"(r3) : "r"(addr));
}
__device__ __forceinline__ void ldsm4t(unsigned addr, unsigned& r0, unsigned& r1,
                                       unsigned& r2, unsigned& r3) {
    asm volatile(
        "ldmatrix.sync.aligned.m8n8.x4.trans.shared.b16 {%0,%1,%2,%3}, [%4];"
        : "=r"(r0), "=r"(r1), "=r"(r2), "=r"(r3) : "r"(addr));
}
__device__ __forceinline__ unsigned s2u(const void* p) {
    return (unsigned)__cvta_generic_to_shared(p);
}
__device__ __forceinline__ void sstore4(__nv_bfloat16* h, __nv_bfloat16* l,
                                        float4 v) {
    __nv_bfloat162 h0 = __floats2bfloat162_rn(v.x, v.y);
    __nv_bfloat162 h1 = __floats2bfloat162_rn(v.z, v.w);
    float2 f0 = __bfloat1622float2(h0), f1 = __bfloat1622float2(h1);
    __nv_bfloat162 l0 = __floats2bfloat162_rn(v.x - f0.x, v.y - f0.y);
    __nv_bfloat162 l1 = __floats2bfloat162_rn(v.z - f1.x, v.w - f1.y);
    *(__nv_bfloat162*)(h) = h0; *(__nv_bfloat162*)(h + 2) = h1;
    *(__nv_bfloat162*)(l) = l0; *(__nv_bfloat162*)(l + 2) = l1;
}
__device__ __forceinline__ void pack_split(float x0, float x1, unsigned& h,
                                           unsigned& l) {
    __nv_bfloat162 hb = __floats2bfloat162_rn(x0, x1);
    float2 hf = __bfloat1622float2(hb);
    __nv_bfloat162 lb = __floats2bfloat162_rn(x0 - hf.x, x1 - hf.y);
    h = *(unsigned*)&hb; l = *(unsigned*)&lb;
}

// ---------------------------------------------------------------------------
// Split-bf16 GEMM: C[M,N] = A[M,K] @ W[N,K]^T (+bias). Tile 128x128.
// ---------------------------------------------------------------------------
__global__ __launch_bounds__(256) void gemm_bf16s(
    const float* __restrict__ A_ext, int src_sel, const float* __restrict__ W,
    const float* __restrict__ bias, float* __restrict__ C_ext, int dst_sel,
    int M, int N, int K) {
    const float* A = (src_sel == 1) ? g_ctx : A_ext;
    float* C = (dst_sel == 1) ? g_proj : (dst_sel == 2) ? g_pk : C_ext;

    __shared__ __align__(16) __nv_bfloat16 sAh[128][40], sAl[128][40];
    __shared__ __align__(16) __nv_bfloat16 sWh[128][40], sWl[128][40];

    const int tid = threadIdx.x, l = tid & 31, w = tid >> 5;
    const int wm = w >> 2, wn = w & 3;
    const int m0 = blockIdx.y << 7, n0 = blockIdx.x << 7;

    float acc[4][4][4];
#pragma unroll
    for (int i = 0; i < 4; i++)
#pragma unroll
        for (int j = 0; j < 4; j++)
#pragma unroll
            for (int e = 0; e < 4; e++) acc[i][j][e] = 0.f;

    const unsigned aBaseH = s2u(&sAh[0][0]), aBaseL = s2u(&sAl[0][0]);
    const unsigned wBaseH = s2u(&sWh[0][0]), wBaseL = s2u(&sWl[0][0]);
    const int aRow = wm * 64 + (l & 15);
    const int aCol = (l & 16) >> 1;
    const int bRow = wn * 32 + (l & 7) + ((l & 16) >> 1);
    const int bCol = l & 8;

    for (int k0 = 0; k0 < K; k0 += 32) {
        __syncthreads();
#pragma unroll
        for (int t = 0; t < 4; t++) {
            int fi = tid + t * 256;
            int row = fi >> 3, c4 = (fi & 7) << 2;
            float4 av = make_float4(0.f, 0.f, 0.f, 0.f);
            if (m0 + row < M)
                av = *(const float4*)&A[(size_t)(m0 + row) * K + k0 + c4];
            sstore4(&sAh[row][c4], &sAl[row][c4], av);
            float4 wv = *(const float4*)&W[(size_t)(n0 + row) * K + k0 + c4];
            sstore4(&sWh[row][c4], &sWl[row][c4], wv);
        }
        __syncthreads();
#pragma unroll
        for (int kc = 0; kc < 2; kc++) {
            const int kk = kc << 4;
            unsigned ah[4][4], al[4][4], bh[4][2], bl[4][2];
#pragma unroll
            for (int mt = 0; mt < 4; mt++) {
                unsigned off = ((aRow + mt * 16) * 40 + kk + aCol) * 2;
                ldsm4(aBaseH + off, ah[mt][0], ah[mt][1], ah[mt][2], ah[mt][3]);
                ldsm4(aBaseL + off, al[mt][0], al[mt][1], al[mt][2], al[mt][3]);
            }
#pragma unroll
            for (int np = 0; np < 2; np++) {
                unsigned off = ((bRow + np * 16) * 40 + kk + bCol) * 2;
                unsigned r0, r1, r2, r3;
                ldsm4(wBaseH + off, r0, r1, r2, r3);
                bh[np * 2][0] = r0; bh[np * 2][1] = r1;
                bh[np * 2 + 1][0] = r2; bh[np * 2 + 1][1] = r3;
                ldsm4(wBaseL + off, r0, r1, r2, r3);
                bl[np * 2][0] = r0; bl[np * 2][1] = r1;
                bl[np * 2 + 1][0] = r2; bl[np * 2 + 1][1] = r3;
            }
#pragma unroll
            for (int mt = 0; mt < 4; mt++)
#pragma unroll
                for (int nt = 0; nt < 4; nt++) {
                    mma_bf16(acc[mt][nt], ah[mt], bh[nt]);
                    mma_bf16(acc[mt][nt], al[mt], bh[nt]);
                    mma_bf16(acc[mt][nt], ah[mt], bl[nt]);
                }
        }
    }

    const int er = m0 + wm * 64 + (l >> 2);
    const int ec = n0 + wn * 32 + ((l & 3) << 1);
#pragma unroll
    for (int mt = 0; mt < 4; mt++) {
#pragma unroll
        for (int nt = 0; nt < 4; nt++) {
            int col = ec + nt * 8;
            float bx = 0.f, by = 0.f;
            if (bias) { float2 bb = *(const float2*)&bias[col]; bx = bb.x; by = bb.y; }
            int r = er + mt * 16;
            if (r < M)
                *(float2*)&C[(size_t)r * N + col] =
                    make_float2(acc[mt][nt][0] + bx, acc[mt][nt][1] + by);
            if (r + 8 < M)
                *(float2*)&C[(size_t)(r + 8) * N + col] =
                    make_float2(acc[mt][nt][2] + bx, acc[mt][nt][3] + by);
        }
    }
}

// ---------------------------------------------------------------------------
// Fused attention (tensor-core, split bf16). Grid (8, 64), 256 threads.
// Per 128q x 64k tile: ac via MMA, bd via per-warp 16x80 banded MMA strip,
// unnormalized exp written to attn, ctx accumulated with FA2 register repack.
// ---------------------------------------------------------------------------
#define OFF_QUH 0
#define OFF_QUL 18432
#define OFF_QVH 36864
#define OFF_QVL 55296
#define OFF_KH  73728
#define OFF_KL  82944
#define OFF_PH  92160
#define OFF_PL  119808
#define OFF_VH  147456
#define OFF_VL  156672
#define OFF_SCR 165888
#define SM_BYTES (165888 + 8 * 16 * 92 * 4)

__global__ __launch_bounds__(256, 1) void attn_kernel(
    const float* __restrict__ ubias, const float* __restrict__ vbias,
    float* __restrict__ attn_ext, int use_scratch) {
    extern __shared__ char smem[];
    float* attn = use_scratch ? g_attn_scratch : attn_ext;

    __nv_bfloat16* QUh = (__nv_bfloat16*)(smem + OFF_QUH);
    __nv_bfloat16* QUl = (__nv_bfloat16*)(smem + OFF_QUL);
    __nv_bfloat16* QVh = (__nv_bfloat16*)(smem + OFF_QVH);
    __nv_bfloat16* QVl = (__nv_bfloat16*)(smem + OFF_QVL);
    __nv_bfloat16* Kh  = (__nv_bfloat16*)(smem + OFF_KH);
    __nv_bfloat16* Kl  = (__nv_bfloat16*)(smem + OFF_KL);
    __nv_bfloat16* Ph  = (__nv_bfloat16*)(smem + OFF_PH);
    __nv_bfloat16* Pl  = (__nv_bfloat16*)(smem + OFF_PL);
    __nv_bfloat16* Vh  = (__nv_bfloat16*)(smem + OFF_VH);
    __nv_bfloat16* Vl  = (__nv_bfloat16*)(smem + OFF_VL);

    const int tid = threadIdx.x, l = tid & 31, w = tid >> 5;
    const int bh = blockIdx.y, b = bh >> 3, h = bh & 7;
    const int q0 = blockIdx.x << 7;
    const int qs = w << 4;
    const float scale = 0.04419417382415922f;  // 1/sqrt(512)

    // ---- load QU/QV tiles, split bf16, [q][d] stride 72 ----
    for (int idx = tid; idx < 4096; idx += 256) {
        int qi = idx >> 5, d2 = (idx & 31) << 1;
        float2 qv = *(const float2*)&g_proj[((size_t)(b * Lc + q0 + qi)) * 1536 +
                                            h * 192 + d2];
        float u0 = (qv.x + ubias[h * 64 + d2]) * scale;
        float u1 = (qv.y + ubias[h * 64 + d2 + 1]) * scale;
        float v0 = (qv.x + vbias[h * 64 + d2]) * scale;
        float v1 = (qv.y + vbias[h * 64 + d2 + 1]) * scale;
        unsigned hh, ll;
        pack_split(u0, u1, hh, ll);
        *(unsigned*)&QUh[qi * 72 + d2] = hh; *(unsigned*)&QUl[qi * 72 + d2] = ll;
        pack_split(v0, v1, hh, ll);
        *(unsigned*)&QVh[qi * 72 + d2] = hh; *(unsigned*)&QVl[qi * 72 + d2] = ll;
    }
    __syncthreads();

    // ---- preload Q fragments (persist in registers) ----
    unsigned auh[4][4], aul[4][4], avh[4][4], avl[4][4];
    {
        unsigned baseUH = s2u(QUh), baseUL = s2u(QUl);
        unsigned baseVH = s2u(QVh), baseVL = s2u(QVl);
        int row = qs + (l & 15), colp = (l & 16) >> 1;
#pragma unroll
        for (int kc = 0; kc < 4; kc++) {
            unsigned off = (row * 72 + kc * 16 + colp) * 2;
            ldsm4(baseUH + off, auh[kc][0], auh[kc][1], auh[kc][2], auh[kc][3]);
            ldsm4(baseUL + off, aul[kc][0], aul[kc][1], aul[kc][2], aul[kc][3]);
            ldsm4(baseVH + off, avh[kc][0], avh[kc][1], avh[kc][2], avh[kc][3]);
            ldsm4(baseVL + off, avl[kc][0], avl[kc][1], avl[kc][2], avl[kc][3]);
        }
    }

    float ct[8][4];
#pragma unroll
    for (int nt = 0; nt < 8; nt++)
#pragma unroll
        for (int e = 0; e < 4; e++) ct[nt][e] = 0.f;
    float rs_lo = 0.f, rs_hi = 0.f;

    const unsigned kBH = s2u(Kh), kBL = s2u(Kl);
    const unsigned pBH = s2u(Ph), pBL = s2u(Pl);
    const unsigned vBH = s2u(Vh), vBL = s2u(Vl);
    float* scr = (float*)(smem + OFF_SCR) + w * 16 * 92;
    const int nlane = (l & 7) + ((l & 16) >> 1);
    const int klane = l & 8;
    const int tkl = (l & 7) + (l & 8);
    const int tnl = (l & 16) >> 1;
    const int r0w = 112 - qs;

    for (int kt0 = 0; kt0 < Lc; kt0 += 64) {
        __syncthreads();
        for (int idx = tid; idx < 1024; idx += 256) {
            int kk = idx >> 4, dg = (idx & 15) << 2;
            size_t base = ((size_t)(b * Lc + kt0 + kk)) * 1536 + h * 192 + dg;
            float4 kv = *(const float4*)&g_proj[base + 64];
            sstore4(&Kh[kk * 72 + dg], &Kl[kk * 72 + dg], kv);
            float4 vv = *(const float4*)&g_proj[base + 128];
            sstore4(&Vh[kk * 72 + dg], &Vl[kk * 72 + dg], vv);
        }
        int pbase = kt0 - q0 + 896;
        for (int idx = tid; idx < 3072; idx += 256) {
            int r = idx >> 4, dg = (idx & 15) << 2;
            int p = pbase + r;
            float4 pv = make_float4(0.f, 0.f, 0.f, 0.f);
            if (p <= 2046) pv = *(const float4*)&g_pk[(size_t)p * 512 + h * 64 + dg];
            sstore4(&Ph[r * 72 + dg], &Pl[r * 72 + dg], pv);
        }
        __syncthreads();

        // ---- bd strip: 16x80 per warp ----
        float bd[10][4];
#pragma unroll
        for (int nt = 0; nt < 10; nt++)
#pragma unroll
            for (int e = 0; e < 4; e++) bd[nt][e] = 0.f;
#pragma unroll
        for (int np = 0; np < 5; np++) {
            int nb = r0w + np * 16 + nlane;
#pragma unroll
            for (int kc = 0; kc < 4; kc++) {
                unsigned off = (nb * 72 + kc * 16 + klane) * 2;
                unsigned h0, h1, h2, h3, l0, l1, l2, l3;
                ldsm4(pBH + off, h0, h1, h2, h3);
                ldsm4(pBL + off, l0, l1, l2, l3);
                unsigned b0h[2] = {h0, h1}, b1h[2] = {h2, h3};
                unsigned b0l[2] = {l0, l1}, b1l[2] = {l2, l3};
                mma_bf16(bd[np * 2], avh[kc], b0h);
                mma_bf16(bd[np * 2], avl[kc], b0h);
                mma_bf16(bd[np * 2], avh[kc], b0l);
                mma_bf16(bd[np * 2 + 1], avh[kc], b1h);
                mma_bf16(bd[np * 2 + 1], avl[kc], b1h);
                mma_bf16(bd[np * 2 + 1], avh[kc], b1l);
            }
        }
        {
            int r = l >> 2, col = ((l & 3) << 1);
#pragma unroll
            for (int nt = 0; nt < 10; nt++) {
                *(float2*)&scr[r * 92 + nt * 8 + col] =
                    make_float2(bd[nt][0], bd[nt][1]);
                *(float2*)&scr[(r + 8) * 92 + nt * 8 + col] =
                    make_float2(bd[nt][2], bd[nt][3]);
            }
        }
        __syncwarp();

        // ---- ac ----
        float sc[8][4];
#pragma unroll
        for (int nt = 0; nt < 8; nt++)
#pragma unroll
            for (int e = 0; e < 4; e++) sc[nt][e] = 0.f;
#pragma unroll
        for (int np = 0; np < 4; np++) {
            int nb = np * 16 + nlane;
#pragma unroll
            for (int kc = 0; kc < 4; kc++) {
                unsigned off = (nb * 72 + kc * 16 + klane) * 2;
                unsigned h0, h1, h2, h3, l0, l1, l2, l3;
                ldsm4(kBH + off, h0, h1, h2, h3);
                ldsm4(kBL + off, l0, l1, l2, l3);
                unsigned b0h[2] = {h0, h1}, b1h[2] = {h2, h3};
                unsigned b0l[2] = {l0, l1}, b1l[2] = {l2, l3};
                mma_bf16(sc[np * 2], auh[kc], b0h);
                mma_bf16(sc[np * 2], aul[kc], b0h);
                mma_bf16(sc[np * 2], auh[kc], b0l);
                mma_bf16(sc[np * 2 + 1], auh[kc], b1h);
                mma_bf16(sc[np * 2 + 1], aul[kc], b1h);
                mma_bf16(sc[np * 2 + 1], auh[kc], b1l);
            }
        }

        // ---- add banded bd, exp, rowsum, store unnormalized probs ----
        {
            int r = l >> 2;
#pragma unroll
            for (int nt = 0; nt < 8; nt++) {
                int kk = nt * 8 + ((l & 3) << 1);
                int j = kk - r + 15;
                sc[nt][0] += scr[r * 92 + j];
                sc[nt][1] += scr[r * 92 + j + 1];
                int j2 = kk - (r + 8) + 15;
                sc[nt][2] += scr[(r + 8) * 92 + j2];
                sc[nt][3] += scr[(r + 8) * 92 + j2 + 1];
            }
#pragma unroll
            for (int nt = 0; nt < 8; nt++) {
#pragma unroll
                for (int e = 0; e < 4; e++) sc[nt][e] = __expf(sc[nt][e]);
                rs_lo += sc[nt][0] + sc[nt][1];
                rs_hi += sc[nt][2] + sc[nt][3];
            }
            size_t rbase =
                ((size_t)bh * Lc + (q0 + qs + r)) * Lc + kt0 + ((l & 3) << 1);
#pragma unroll
            for (int nt = 0; nt < 8; nt++) {
                *(float2*)&attn[rbase + nt * 8] = make_float2(sc[nt][0], sc[nt][1]);
                *(float2*)&attn[rbase + 8 * Lc + nt * 8] =
                    make_float2(sc[nt][2], sc[nt][3]);
            }
        }

        // ---- ctx += P @ V (register repack, split) ----
#pragma unroll
        for (int kc = 0; kc < 4; kc++) {
            unsigned pah[4], pal[4];
            pack_split(sc[2 * kc][0], sc[2 * kc][1], pah[0], pal[0]);
            pack_split(sc[2 * kc][2], sc[2 * kc][3], pah[1], pal[1]);
            pack_split(sc[2 * kc + 1][0], sc[2 * kc + 1][1], pah[2], pal[2]);
            pack_split(sc[2 * kc + 1][2], sc[2 * kc + 1][3], pah[3], pal[3]);
            int krow = kc * 16 + tkl;
#pragma unroll
            for (int np = 0; np < 4; np++) {
                unsigned off = (krow * 72 + np * 16 + tnl) * 2;
                unsigned h0, h1, h2, h3, l0, l1, l2, l3;
                ldsm4t(vBH + off, h0, h1, h2, h3);
                ldsm4t(vBL + off, l0, l1, l2, l3);
                unsigned b0h[2] = {h0, h1}, b1h[2] = {h2, h3};
                unsigned b0l[2] = {l0, l1}, b1l[2] = {l2, l3};
                mma_bf16(ct[np * 2], pah, b0h);
                mma_bf16(ct[np * 2], pal, b0h);
                mma_bf16(ct[np * 2], pah, b0l);
                mma_bf16(ct[np * 2 + 1], pah, b1h);
                mma_bf16(ct[np * 2 + 1], pal, b1h);
                mma_bf16(ct[np * 2 + 1], pah, b1l);
            }
        }
    }

    // ---- rowsum reduce, write inv, scale ctx, store ----
    rs_lo += __shfl_xor_sync(0xffffffffu, rs_lo, 1);
    rs_lo += __shfl_xor_sync(0xffffffffu, rs_lo, 2);
    rs_hi += __shfl_xor_sync(0xffffffffu, rs_hi, 1);
    rs_hi += __shfl_xor_sync(0xffffffffu, rs_hi, 2);
    float inv_lo = 1.f / rs_lo, inv_hi = 1.f / rs_hi;
    int r = l >> 2;
    if ((l & 3) == 0) {
        g_inv[bh * Lc + q0 + qs + r] = inv_lo;
        g_inv[bh * Lc + q0 + qs + r + 8] = inv_hi;
    }
    size_t cbase = ((size_t)(b * Lc + q0 + qs + r)) * 512 + h * 64 + ((l & 3) << 1);
#pragma unroll
    for (int nt = 0; nt < 8; nt++) {
        *(float2*)&g_ctx[cbase + nt * 8] =
            make_float2(ct[nt][0] * inv_lo, ct[nt][1] * inv_lo);
        *(float2*)&g_ctx[cbase + 8 * 512 + nt * 8] =
            make_float2(ct[nt][2] * inv_hi, ct[nt][3] * inv_hi);
    }
}

// ---------------------------------------------------------------------------
__global__ void norm_attn(float* __restrict__ attn) {
    size_t n4 = (size_t)ATTN_ELEMS / 4;
    for (size_t i = blockIdx.x * blockDim.x + threadIdx.x; i < n4;
         i += (size_t)gridDim.x * blockDim.x) {
        float inv = g_inv[i >> 8];
        float4 v = ((float4*)attn)[i];
        v.x *= inv; v.y *= inv; v.z *= inv; v.w *= inv;
        ((float4*)attn)[i] = v;
    }
}

// ---------------------------------------------------------------------------
extern "C" void kernel_launch(void* const* d_in, const int* in_sizes, int n_in,
                              void* d_out, int out_size) {
    const float* x    = (const float*)d_in[0];
    const float* pos  = (const float*)d_in[1];
    const float* wqkv = (const float*)d_in[2];
    const float* wpos = (const float*)d_in[3];
    const float* wout = (const float*)d_in[4];
    const float* bout = (const float*)d_in[5];
    const float* ub   = (const float*)d_in[6];
    const float* vb   = (const float*)d_in[7];
    float* out = (float*)d_out;

    int attn_in_out = ((long long)out_size >= (long long)OUT_ELEMS + ATTN_ELEMS);
    float* attn_buf = attn_in_out ? (out + OUT_ELEMS) : nullptr;

    dim3 blk(256);
    gemm_bf16s<<<dim3(12, 64), blk>>>(x, 0, wqkv, nullptr, nullptr, 1,
                                      8192, 1536, 512);
    gemm_bf16s<<<dim3(4, 16), blk>>>(pos, 0, wpos, nullptr, nullptr, 2,
                                     2047, 512, 512);

    cudaFuncSetAttribute(attn_kernel, cudaFuncAttributeMaxDynamicSharedMemorySize,
                         SM_BYTES);
    attn_kernel<<<dim3(8, 64), blk, SM_BYTES>>>(ub, vb, attn_buf,
                                                attn_in_out ? 0 : 1);
    norm_attn<<<4096, 256>>>(attn_in_out ? attn_buf : g_attn_scratch);

    gemm_bf16s<<<dim3(4, 64), blk>>>(nullptr, 1, wout, bout, out, 0,
                                     8192, 512, 512);
}

// round 6
// speedup vs baseline: 3.1287x; 1.1259x over previous
#include <cuda_runtime.h>
#include <cuda_bf16.h>
#include <math.h>

#define Lc 1024
#define Pc 2047

#define OUT_ELEMS  (8 * 1024 * 512)
#define ATTN_ELEMS (64LL * 1024 * 1024)

__device__ float g_q[(size_t)8192 * 512];
__device__ float g_ctx[(size_t)8192 * 512];
__device__ float g_inv[65536];
__device__ float g_attn_scratch[(size_t)ATTN_ELEMS];
// split-bf16 planes, [bh][k][64]
__device__ __nv_bfloat16 g_kh[(size_t)64 * 1024 * 64];
__device__ __nv_bfloat16 g_kl[(size_t)64 * 1024 * 64];
__device__ __nv_bfloat16 g_vh[(size_t)64 * 1024 * 64];
__device__ __nv_bfloat16 g_vl[(size_t)64 * 1024 * 64];
// [h][p(2048)][64] ; row 2047 never written -> stays zero
__device__ __nv_bfloat16 g_ph[(size_t)8 * 2048 * 64];
__device__ __nv_bfloat16 g_pl[(size_t)8 * 2048 * 64];

// ------------------------- warp MMA helpers -------------------------------
__device__ __forceinline__ void mma_bf16(float* c, const unsigned* a,
                                         const unsigned* b) {
    asm volatile(
        "mma.sync.aligned.m16n8k16.row.col.f32.bf16.bf16.f32 "
        "{%0,%1,%2,%3}, {%4,%5,%6,%7}, {%8,%9}, {%0,%1,%2,%3};\n"
        : "+f"(c[0]), "+f"(c[1]), "+f"(c[2]), "+f"(c[3])
        : "r"(a[0]), "r"(a[1]), "r"(a[2]), "r"(a[3]), "r"(b[0]), "r"(b[1]));
}
__device__ __forceinline__ void ldsm4(unsigned addr, unsigned& r0, unsigned& r1,
                                      unsigned& r2, unsigned& r3) {
    asm volatile("ldmatrix.sync.aligned.m8n8.x4.shared.b16 {%0,%1,%2,%3}, [%4];"
                 : "=r"(r0), "=r"(r1), "=r"(r2), "=r"(r3) : "r"(addr));
}
__device__ __forceinline__ void ldsm4t(unsigned addr, unsigned& r0, unsigned& r1,
                                       unsigned& r2, unsigned& r3) {
    asm volatile(
        "ldmatrix.sync.aligned.m8n8.x4.trans.shared.b16 {%0,%1,%2,%3}, [%4];"
        : "=r"(r0), "=r"(r1), "=r"(r2), "=r"(r3) : "r"(addr));
}
__device__ __forceinline__ unsigned s2u(const void* p) {
    return (unsigned)__cvta_generic_to_shared(p);
}
__device__ __forceinline__ void sstore4(__nv_bfloat16* h, __nv_bfloat16* l,
                                        float4 v) {
    __nv_bfloat162 h0 = __floats2bfloat162_rn(v.x, v.y);
    __nv_bfloat162 h1 = __floats2bfloat162_rn(v.z, v.w);
    float2 f0 = __bfloat1622float2(h0), f1 = __bfloat1622float2(h1);
    __nv_bfloat162 l0 = __floats2bfloat162_rn(v.x - f0.x, v.y - f0.y);
    __nv_bfloat162 l1 = __floats2bfloat162_rn(v.z - f1.x, v.w - f1.y);
    *(__nv_bfloat162*)(h) = h0; *(__nv_bfloat162*)(h + 2) = h1;
    *(__nv_bfloat162*)(l) = l0; *(__nv_bfloat162*)(l + 2) = l1;
}
__device__ __forceinline__ void pack_split(float x0, float x1, unsigned& h,
                                           unsigned& l) {
    __nv_bfloat162 hb = __floats2bfloat162_rn(x0, x1);
    float2 hf = __bfloat1622float2(hb);
    __nv_bfloat162 lb = __floats2bfloat162_rn(x0 - hf.x, x1 - hf.y);
    h = *(unsigned*)&hb; l = *(unsigned*)&lb;
}

// ---------------------------------------------------------------------------
// Split-bf16 GEMM: C[M,N] = A[M,K] @ W[N,K]^T. Tile 128x128.
// mode 0: fp32 C (+bias). mode 1: qkv epilogue (per-head q|k|v interleave:
//   col = h*192 + part*64 + d). mode 2: pos epilogue (split planes [h][p][d]).
// ---------------------------------------------------------------------------
__global__ __launch_bounds__(256) void gemm_bf16s(
    const float* __restrict__ A_ext, int src_sel, const float* __restrict__ W,
    const float* __restrict__ bias, float* __restrict__ C_ext, int mode,
    int M, int N, int K) {
    const float* A = (src_sel == 1) ? g_ctx : A_ext;

    __shared__ __align__(16) __nv_bfloat16 sAh[128][40], sAl[128][40];
    __shared__ __align__(16) __nv_bfloat16 sWh[128][40], sWl[128][40];

    const int tid = threadIdx.x, l = tid & 31, w = tid >> 5;
    const int wm = w >> 2, wn = w & 3;
    const int m0 = blockIdx.y << 7, n0 = blockIdx.x << 7;

    float acc[4][4][4];
#pragma unroll
    for (int i = 0; i < 4; i++)
#pragma unroll
        for (int j = 0; j < 4; j++)
#pragma unroll
            for (int e = 0; e < 4; e++) acc[i][j][e] = 0.f;

    const unsigned aBaseH = s2u(&sAh[0][0]), aBaseL = s2u(&sAl[0][0]);
    const unsigned wBaseH = s2u(&sWh[0][0]), wBaseL = s2u(&sWl[0][0]);
    const int aRow = wm * 64 + (l & 15);
    const int aCol = (l & 16) >> 1;
    const int bRow = wn * 32 + (l & 7) + ((l & 16) >> 1);
    const int bCol = l & 8;

    for (int k0 = 0; k0 < K; k0 += 32) {
        __syncthreads();
#pragma unroll
        for (int t = 0; t < 4; t++) {
            int fi = tid + t * 256;
            int row = fi >> 3, c4 = (fi & 7) << 2;
            float4 av = make_float4(0.f, 0.f, 0.f, 0.f);
            if (m0 + row < M)
                av = *(const float4*)&A[(size_t)(m0 + row) * K + k0 + c4];
            sstore4(&sAh[row][c4], &sAl[row][c4], av);
            float4 wv = *(const float4*)&W[(size_t)(n0 + row) * K + k0 + c4];
            sstore4(&sWh[row][c4], &sWl[row][c4], wv);
        }
        __syncthreads();
#pragma unroll
        for (int kc = 0; kc < 2; kc++) {
            const int kk = kc << 4;
            unsigned ah[4][4], al[4][4], bh[4][2], bl[4][2];
#pragma unroll
            for (int mt = 0; mt < 4; mt++) {
                unsigned off = ((aRow + mt * 16) * 40 + kk + aCol) * 2;
                ldsm4(aBaseH + off, ah[mt][0], ah[mt][1], ah[mt][2], ah[mt][3]);
                ldsm4(aBaseL + off, al[mt][0], al[mt][1], al[mt][2], al[mt][3]);
            }
#pragma unroll
            for (int np = 0; np < 2; np++) {
                unsigned off = ((bRow + np * 16) * 40 + kk + bCol) * 2;
                unsigned r0, r1, r2, r3;
                ldsm4(wBaseH + off, r0, r1, r2, r3);
                bh[np * 2][0] = r0; bh[np * 2][1] = r1;
                bh[np * 2 + 1][0] = r2; bh[np * 2 + 1][1] = r3;
                ldsm4(wBaseL + off, r0, r1, r2, r3);
                bl[np * 2][0] = r0; bl[np * 2][1] = r1;
                bl[np * 2 + 1][0] = r2; bl[np * 2 + 1][1] = r3;
            }
#pragma unroll
            for (int mt = 0; mt < 4; mt++)
#pragma unroll
                for (int nt = 0; nt < 4; nt++) {
                    mma_bf16(acc[mt][nt], ah[mt], bh[nt]);
                    mma_bf16(acc[mt][nt], al[mt], bh[nt]);
                    mma_bf16(acc[mt][nt], ah[mt], bl[nt]);
                }
        }
    }

    const int er = m0 + wm * 64 + (l >> 2);
    const int ec = n0 + wn * 32 + ((l & 3) << 1);
#pragma unroll
    for (int mt = 0; mt < 4; mt++) {
#pragma unroll
        for (int nt = 0; nt < 4; nt++) {
            int col = ec + nt * 8;
#pragma unroll
            for (int half = 0; half < 2; half++) {
                int r = er + mt * 16 + half * 8;
                if (r >= M) continue;
                float a0 = acc[mt][nt][half * 2];
                float a1 = acc[mt][nt][half * 2 + 1];
                if (mode == 0) {
                    float bx = 0.f, by = 0.f;
                    if (bias) {
                        float2 bb = *(const float2*)&bias[col];
                        bx = bb.x; by = bb.y;
                    }
                    *(float2*)&C_ext[(size_t)r * N + col] =
                        make_float2(a0 + bx, a1 + by);
                } else if (mode == 1) {
                    // torch chunk layout: col = h*192 + part*64 + d
                    int hh_ = col / 192;
                    int rem = col - hh_ * 192;
                    int part = rem >> 6, d = rem & 63;
                    if (part == 0) {
                        *(float2*)&g_q[(size_t)r * 512 + hh_ * 64 + d] =
                            make_float2(a0, a1);
                    } else {
                        int b = r >> 10, ll2 = r & 1023;
                        size_t idx =
                            (((size_t)(b * 8 + hh_)) * 1024 + ll2) * 64 + d;
                        unsigned hh, lo;
                        pack_split(a0, a1, hh, lo);
                        if (part == 1) {
                            *(unsigned*)&g_kh[idx] = hh;
                            *(unsigned*)&g_kl[idx] = lo;
                        } else {
                            *(unsigned*)&g_vh[idx] = hh;
                            *(unsigned*)&g_vl[idx] = lo;
                        }
                    }
                } else {
                    int hh_ = col >> 6, d = col & 63;
                    size_t idx = (((size_t)hh_) * 2048 + r) * 64 + d;
                    unsigned hh, lo;
                    pack_split(a0, a1, hh, lo);
                    *(unsigned*)&g_ph[idx] = hh;
                    *(unsigned*)&g_pl[idx] = lo;
                }
            }
        }
    }
}

// ---------------------------------------------------------------------------
// Fused attention. Grid (8, 64), 256 threads. Tiles are pure bf16 copies.
// ---------------------------------------------------------------------------
#define OFF_QUH 0
#define OFF_QUL 18432
#define OFF_QVH 36864
#define OFF_QVL 55296
#define OFF_KH  73728
#define OFF_KL  82944
#define OFF_PH  92160
#define OFF_PL  119808
#define OFF_VH  147456
#define OFF_VL  156672
#define OFF_SCR 165888
#define SM_BYTES (165888 + 8 * 16 * 92 * 4)

__global__ __launch_bounds__(256, 1) void attn_kernel(
    const float* __restrict__ ubias, const float* __restrict__ vbias,
    float* __restrict__ attn_ext, int use_scratch) {
    extern __shared__ char smem[];
    float* attn = use_scratch ? g_attn_scratch : attn_ext;

    __nv_bfloat16* QUh = (__nv_bfloat16*)(smem + OFF_QUH);
    __nv_bfloat16* QUl = (__nv_bfloat16*)(smem + OFF_QUL);
    __nv_bfloat16* QVh = (__nv_bfloat16*)(smem + OFF_QVH);
    __nv_bfloat16* QVl = (__nv_bfloat16*)(smem + OFF_QVL);
    __nv_bfloat16* Kh  = (__nv_bfloat16*)(smem + OFF_KH);
    __nv_bfloat16* Kl  = (__nv_bfloat16*)(smem + OFF_KL);
    __nv_bfloat16* Ph  = (__nv_bfloat16*)(smem + OFF_PH);
    __nv_bfloat16* Pl  = (__nv_bfloat16*)(smem + OFF_PL);
    __nv_bfloat16* Vh  = (__nv_bfloat16*)(smem + OFF_VH);
    __nv_bfloat16* Vl  = (__nv_bfloat16*)(smem + OFF_VL);

    const int tid = threadIdx.x, l = tid & 31, w = tid >> 5;
    const int bh = blockIdx.y, b = bh >> 3, h = bh & 7;
    const int q0 = blockIdx.x << 7;
    const int qs = w << 4;
    const float scale = 0.04419417382415922f;  // 1/sqrt(512)

    // ---- load QU/QV tiles (only conversion left in this kernel) ----
    for (int idx = tid; idx < 4096; idx += 256) {
        int qi = idx >> 5, d2 = (idx & 31) << 1;
        float2 qv =
            *(const float2*)&g_q[((size_t)(b * Lc + q0 + qi)) * 512 + h * 64 + d2];
        float u0 = (qv.x + ubias[h * 64 + d2]) * scale;
        float u1 = (qv.y + ubias[h * 64 + d2 + 1]) * scale;
        float v0 = (qv.x + vbias[h * 64 + d2]) * scale;
        float v1 = (qv.y + vbias[h * 64 + d2 + 1]) * scale;
        unsigned hh, ll;
        pack_split(u0, u1, hh, ll);
        *(unsigned*)&QUh[qi * 72 + d2] = hh; *(unsigned*)&QUl[qi * 72 + d2] = ll;
        pack_split(v0, v1, hh, ll);
        *(unsigned*)&QVh[qi * 72 + d2] = hh; *(unsigned*)&QVl[qi * 72 + d2] = ll;
    }
    __syncthreads();

    // ---- preload Q fragments ----
    unsigned auh[4][4], aul[4][4], avh[4][4], avl[4][4];
    {
        unsigned baseUH = s2u(QUh), baseUL = s2u(QUl);
        unsigned baseVH = s2u(QVh), baseVL = s2u(QVl);
        int row = qs + (l & 15), colp = (l & 16) >> 1;
#pragma unroll
        for (int kc = 0; kc < 4; kc++) {
            unsigned off = (row * 72 + kc * 16 + colp) * 2;
            ldsm4(baseUH + off, auh[kc][0], auh[kc][1], auh[kc][2], auh[kc][3]);
            ldsm4(baseUL + off, aul[kc][0], aul[kc][1], aul[kc][2], aul[kc][3]);
            ldsm4(baseVH + off, avh[kc][0], avh[kc][1], avh[kc][2], avh[kc][3]);
            ldsm4(baseVL + off, avl[kc][0], avl[kc][1], avl[kc][2], avl[kc][3]);
        }
    }

    float ct[8][4];
#pragma unroll
    for (int nt = 0; nt < 8; nt++)
#pragma unroll
        for (int e = 0; e < 4; e++) ct[nt][e] = 0.f;
    float rs_lo = 0.f, rs_hi = 0.f;

    const unsigned kBH = s2u(Kh), kBL = s2u(Kl);
    const unsigned pBH = s2u(Ph), pBL = s2u(Pl);
    const unsigned vBH = s2u(Vh), vBL = s2u(Vl);
    float* scr = (float*)(smem + OFF_SCR) + w * 16 * 92;
    const int nlane = (l & 7) + ((l & 16) >> 1);
    const int klane = l & 8;
    const int tkl = (l & 7) + (l & 8);
    const int tnl = (l & 16) >> 1;
    const int r0w = 112 - qs;

    uint4* SKh = (uint4*)Kh; uint4* SKl = (uint4*)Kl;
    uint4* SVh = (uint4*)Vh; uint4* SVl = (uint4*)Vl;
    uint4* SPh = (uint4*)Ph; uint4* SPl = (uint4*)Pl;

    for (int kt0 = 0; kt0 < Lc; kt0 += 64) {
        __syncthreads();
        {
            size_t gb = (((size_t)bh) * 1024 + kt0) * 64;
            const uint4* GKh = (const uint4*)(g_kh + gb);
            const uint4* GKl = (const uint4*)(g_kl + gb);
            const uint4* GVh = (const uint4*)(g_vh + gb);
            const uint4* GVl = (const uint4*)(g_vl + gb);
#pragma unroll
            for (int t = 0; t < 2; t++) {
                int i = tid + t * 256;
                int so = (i >> 3) * 9 + (i & 7);
                SKh[so] = GKh[i]; SKl[so] = GKl[i];
                SVh[so] = GVh[i]; SVl[so] = GVl[i];
            }
            int pbase = kt0 - q0 + 896;   // [0,1856]; rows pbase..pbase+191 <= 2047
            size_t pb = (((size_t)h) * 2048 + pbase) * 64;
            const uint4* GPh = (const uint4*)(g_ph + pb);
            const uint4* GPl = (const uint4*)(g_pl + pb);
#pragma unroll
            for (int t = 0; t < 6; t++) {
                int i = tid + t * 256;
                int so = (i >> 3) * 9 + (i & 7);
                SPh[so] = GPh[i]; SPl[so] = GPl[i];
            }
        }
        __syncthreads();

        // ---- bd strip: 16x80 per warp ----
        float bd[10][4];
#pragma unroll
        for (int nt = 0; nt < 10; nt++)
#pragma unroll
            for (int e = 0; e < 4; e++) bd[nt][e] = 0.f;
#pragma unroll
        for (int np = 0; np < 5; np++) {
            int nb = r0w + np * 16 + nlane;
#pragma unroll
            for (int kc = 0; kc < 4; kc++) {
                unsigned off = (nb * 72 + kc * 16 + klane) * 2;
                unsigned h0, h1, h2, h3, l0, l1, l2, l3;
                ldsm4(pBH + off, h0, h1, h2, h3);
                ldsm4(pBL + off, l0, l1, l2, l3);
                unsigned b0h[2] = {h0, h1}, b1h[2] = {h2, h3};
                unsigned b0l[2] = {l0, l1}, b1l[2] = {l2, l3};
                mma_bf16(bd[np * 2], avh[kc], b0h);
                mma_bf16(bd[np * 2], avl[kc], b0h);
                mma_bf16(bd[np * 2], avh[kc], b0l);
                mma_bf16(bd[np * 2 + 1], avh[kc], b1h);
                mma_bf16(bd[np * 2 + 1], avl[kc], b1h);
                mma_bf16(bd[np * 2 + 1], avh[kc], b1l);
            }
        }
        {
            int r = l >> 2, col = ((l & 3) << 1);
#pragma unroll
            for (int nt = 0; nt < 10; nt++) {
                *(float2*)&scr[r * 92 + nt * 8 + col] =
                    make_float2(bd[nt][0], bd[nt][1]);
                *(float2*)&scr[(r + 8) * 92 + nt * 8 + col] =
                    make_float2(bd[nt][2], bd[nt][3]);
            }
        }
        __syncwarp();

        // ---- ac ----
        float sc[8][4];
#pragma unroll
        for (int nt = 0; nt < 8; nt++)
#pragma unroll
            for (int e = 0; e < 4; e++) sc[nt][e] = 0.f;
#pragma unroll
        for (int np = 0; np < 4; np++) {
            int nb = np * 16 + nlane;
#pragma unroll
            for (int kc = 0; kc < 4; kc++) {
                unsigned off = (nb * 72 + kc * 16 + klane) * 2;
                unsigned h0, h1, h2, h3, l0, l1, l2, l3;
                ldsm4(kBH + off, h0, h1, h2, h3);
                ldsm4(kBL + off, l0, l1, l2, l3);
                unsigned b0h[2] = {h0, h1}, b1h[2] = {h2, h3};
                unsigned b0l[2] = {l0, l1}, b1l[2] = {l2, l3};
                mma_bf16(sc[np * 2], auh[kc], b0h);
                mma_bf16(sc[np * 2], aul[kc], b0h);
                mma_bf16(sc[np * 2], auh[kc], b0l);
                mma_bf16(sc[np * 2 + 1], auh[kc], b1h);
                mma_bf16(sc[np * 2 + 1], aul[kc], b1h);
                mma_bf16(sc[np * 2 + 1], auh[kc], b1l);
            }
        }

        // ---- add banded bd, exp, rowsum, store unnormalized probs ----
        {
            int r = l >> 2;
#pragma unroll
            for (int nt = 0; nt < 8; nt++) {
                int kk = nt * 8 + ((l & 3) << 1);
                int j = kk - r + 15;
                sc[nt][0] += scr[r * 92 + j];
                sc[nt][1] += scr[r * 92 + j + 1];
                int j2 = kk - (r + 8) + 15;
                sc[nt][2] += scr[(r + 8) * 92 + j2];
                sc[nt][3] += scr[(r + 8) * 92 + j2 + 1];
            }
#pragma unroll
            for (int nt = 0; nt < 8; nt++) {
#pragma unroll
                for (int e = 0; e < 4; e++) sc[nt][e] = __expf(sc[nt][e]);
                rs_lo += sc[nt][0] + sc[nt][1];
                rs_hi += sc[nt][2] + sc[nt][3];
            }
            size_t rbase =
                ((size_t)bh * Lc + (q0 + qs + r)) * Lc + kt0 + ((l & 3) << 1);
#pragma unroll
            for (int nt = 0; nt < 8; nt++) {
                *(float2*)&attn[rbase + nt * 8] = make_float2(sc[nt][0], sc[nt][1]);
                *(float2*)&attn[rbase + 8 * Lc + nt * 8] =
                    make_float2(sc[nt][2], sc[nt][3]);
            }
        }

        // ---- ctx += P @ V ----
#pragma unroll
        for (int kc = 0; kc < 4; kc++) {
            unsigned pah[4], pal[4];
            pack_split(sc[2 * kc][0], sc[2 * kc][1], pah[0], pal[0]);
            pack_split(sc[2 * kc][2], sc[2 * kc][3], pah[1], pal[1]);
            pack_split(sc[2 * kc + 1][0], sc[2 * kc + 1][1], pah[2], pal[2]);
            pack_split(sc[2 * kc + 1][2], sc[2 * kc + 1][3], pah[3], pal[3]);
            int krow = kc * 16 + tkl;
#pragma unroll
            for (int np = 0; np < 4; np++) {
                unsigned off = (krow * 72 + np * 16 + tnl) * 2;
                unsigned h0, h1, h2, h3, l0, l1, l2, l3;
                ldsm4t(vBH + off, h0, h1, h2, h3);
                ldsm4t(vBL + off, l0, l1, l2, l3);
                unsigned b0h[2] = {h0, h1}, b1h[2] = {h2, h3};
                unsigned b0l[2] = {l0, l1}, b1l[2] = {l2, l3};
                mma_bf16(ct[np * 2], pah, b0h);
                mma_bf16(ct[np * 2], pal, b0h);
                mma_bf16(ct[np * 2], pah, b0l);
                mma_bf16(ct[np * 2 + 1], pah, b1h);
                mma_bf16(ct[np * 2 + 1], pal, b1h);
                mma_bf16(ct[np * 2 + 1], pah, b1l);
            }
        }
    }

    // ---- rowsum reduce, write inv, scale ctx, store ----
    rs_lo += __shfl_xor_sync(0xffffffffu, rs_lo, 1);
    rs_lo += __shfl_xor_sync(0xffffffffu, rs_lo, 2);
    rs_hi += __shfl_xor_sync(0xffffffffu, rs_hi, 1);
    rs_hi += __shfl_xor_sync(0xffffffffu, rs_hi, 2);
    float inv_lo = 1.f / rs_lo, inv_hi = 1.f / rs_hi;
    int r = l >> 2;
    if ((l & 3) == 0) {
        g_inv[bh * Lc + q0 + qs + r] = inv_lo;
        g_inv[bh * Lc + q0 + qs + r + 8] = inv_hi;
    }
    size_t cbase = ((size_t)(b * Lc + q0 + qs + r)) * 512 + h * 64 + ((l & 3) << 1);
#pragma unroll
    for (int nt = 0; nt < 8; nt++) {
        *(float2*)&g_ctx[cbase + nt * 8] =
            make_float2(ct[nt][0] * inv_lo, ct[nt][1] * inv_lo);
        *(float2*)&g_ctx[cbase + 8 * 512 + nt * 8] =
            make_float2(ct[nt][2] * inv_hi, ct[nt][3] * inv_hi);
    }
}

// ---------------------------------------------------------------------------
__global__ void norm_attn(float* __restrict__ attn) {
    size_t n4 = (size_t)ATTN_ELEMS / 4;
    for (size_t i = blockIdx.x * blockDim.x + threadIdx.x; i < n4;
         i += (size_t)gridDim.x * blockDim.x) {
        float inv = g_inv[i >> 8];
        float4 v = ((float4*)attn)[i];
        v.x *= inv; v.y *= inv; v.z *= inv; v.w *= inv;
        ((float4*)attn)[i] = v;
    }
}

// ---------------------------------------------------------------------------
extern "C" void kernel_launch(void* const* d_in, const int* in_sizes, int n_in,
                              void* d_out, int out_size) {
    const float* x    = (const float*)d_in[0];
    const float* pos  = (const float*)d_in[1];
    const float* wqkv = (const float*)d_in[2];
    const float* wpos = (const float*)d_in[3];
    const float* wout = (const float*)d_in[4];
    const float* bout = (const float*)d_in[5];
    const float* ub   = (const float*)d_in[6];
    const float* vb   = (const float*)d_in[7];
    float* out = (float*)d_out;

    int attn_in_out = ((long long)out_size >= (long long)OUT_ELEMS + ATTN_ELEMS);
    float* attn_buf = attn_in_out ? (out + OUT_ELEMS) : nullptr;

    dim3 blk(256);
    gemm_bf16s<<<dim3(12, 64), blk>>>(x, 0, wqkv, nullptr, nullptr, 1,
                                      8192, 1536, 512);
    gemm_bf16s<<<dim3(4, 16), blk>>>(pos, 0, wpos, nullptr, nullptr, 2,
                                     2047, 512, 512);

    cudaFuncSetAttribute(attn_kernel, cudaFuncAttributeMaxDynamicSharedMemorySize,
                         SM_BYTES);
    attn_kernel<<<dim3(8, 64), blk, SM_BYTES>>>(ub, vb, attn_buf,
                                                attn_in_out ? 0 : 1);
    norm_attn<<<4096, 256>>>(attn_in_out ? attn_buf : g_attn_scratch);

    gemm_bf16s<<<dim3(4, 64), blk>>>(nullptr, 1, wout, bout, out, 0,
                                     8192, 512, 512);
}

// round 7
// speedup vs baseline: 4.1190x; 1.3165x over previous
#include <cuda_runtime.h>
#include <cuda_bf16.h>
#include <cuda_fp16.h>
#include <math.h>

#define Lc 1024
#define Pc 2047

#define OUT_ELEMS  (8 * 1024 * 512)
#define ATTN_ELEMS (64LL * 1024 * 1024)

__device__ float g_q[(size_t)8192 * 512];
__device__ float g_ctx[(size_t)8192 * 512];
__device__ float g_inv[65536];
__device__ float g_attn_scratch[(size_t)ATTN_ELEMS];
// single fp16 planes
__device__ __half g_k[(size_t)64 * 1024 * 64];   // [bh][k][64]
__device__ __half g_v[(size_t)64 * 1024 * 64];   // [bh][k][64]
__device__ __half g_p[(size_t)8 * 2048 * 64];    // [h][p][64]; row 2047 stays zero

// ------------------------- warp MMA helpers -------------------------------
__device__ __forceinline__ void mma_bf16(float* c, const unsigned* a,
                                         const unsigned* b) {
    asm volatile(
        "mma.sync.aligned.m16n8k16.row.col.f32.bf16.bf16.f32 "
        "{%0,%1,%2,%3}, {%4,%5,%6,%7}, {%8,%9}, {%0,%1,%2,%3};\n"
        : "+f"(c[0]), "+f"(c[1]), "+f"(c[2]), "+f"(c[3])
        : "r"(a[0]), "r"(a[1]), "r"(a[2]), "r"(a[3]), "r"(b[0]), "r"(b[1]));
}
__device__ __forceinline__ void mma_f16(float* c, const unsigned* a,
                                        const unsigned* b) {
    asm volatile(
        "mma.sync.aligned.m16n8k16.row.col.f32.f16.f16.f32 "
        "{%0,%1,%2,%3}, {%4,%5,%6,%7}, {%8,%9}, {%0,%1,%2,%3};\n"
        : "+f"(c[0]), "+f"(c[1]), "+f"(c[2]), "+f"(c[3])
        : "r"(a[0]), "r"(a[1]), "r"(a[2]), "r"(a[3]), "r"(b[0]), "r"(b[1]));
}
__device__ __forceinline__ void ldsm4(unsigned addr, unsigned& r0, unsigned& r1,
                                      unsigned& r2, unsigned& r3) {
    asm volatile("ldmatrix.sync.aligned.m8n8.x4.shared.b16 {%0,%1,%2,%3}, [%4];"
                 : "=r"(r0), "=r"(r1), "=r"(r2), "=r"(r3) : "r"(addr));
}
__device__ __forceinline__ void ldsm4t(unsigned addr, unsigned& r0, unsigned& r1,
                                       unsigned& r2, unsigned& r3) {
    asm volatile(
        "ldmatrix.sync.aligned.m8n8.x4.trans.shared.b16 {%0,%1,%2,%3}, [%4];"
        : "=r"(r0), "=r"(r1), "=r"(r2), "=r"(r3) : "r"(addr));
}
__device__ __forceinline__ unsigned s2u(const void* p) {
    return (unsigned)__cvta_generic_to_shared(p);
}
__device__ __forceinline__ void cpa16(unsigned dst, const void* src) {
    asm volatile("cp.async.cg.shared.global [%0], [%1], 16;\n" ::"r"(dst),
                 "l"(src));
}
__device__ __forceinline__ void sstore4(__nv_bfloat16* h, __nv_bfloat16* l,
                                        float4 v) {
    __nv_bfloat162 h0 = __floats2bfloat162_rn(v.x, v.y);
    __nv_bfloat162 h1 = __floats2bfloat162_rn(v.z, v.w);
    float2 f0 = __bfloat1622float2(h0), f1 = __bfloat1622float2(h1);
    __nv_bfloat162 l0 = __floats2bfloat162_rn(v.x - f0.x, v.y - f0.y);
    __nv_bfloat162 l1 = __floats2bfloat162_rn(v.z - f1.x, v.w - f1.y);
    *(__nv_bfloat162*)(h) = h0; *(__nv_bfloat162*)(h + 2) = h1;
    *(__nv_bfloat162*)(l) = l0; *(__nv_bfloat162*)(l + 2) = l1;
}
__device__ __forceinline__ unsigned packh2(float x0, float x1) {
    __half2 t = __floats2half2_rn(x0, x1);
    return *(unsigned*)&t;
}

// ---------------------------------------------------------------------------
// Split-bf16 GEMM: C[M,N] = A[M,K] @ W[N,K]^T. Tile 128x128.
// mode 0: fp32 C (+bias). mode 1: qkv epilogue (col = h*192 + part*64 + d;
//   q fp32, k/v fp16). mode 2: pos epilogue (fp16 [h][p][d]).
// ---------------------------------------------------------------------------
__global__ __launch_bounds__(256) void gemm_bf16s(
    const float* __restrict__ A_ext, int src_sel, const float* __restrict__ W,
    const float* __restrict__ bias, float* __restrict__ C_ext, int mode,
    int M, int N, int K) {
    const float* A = (src_sel == 1) ? g_ctx : A_ext;

    __shared__ __align__(16) __nv_bfloat16 sAh[128][40], sAl[128][40];
    __shared__ __align__(16) __nv_bfloat16 sWh[128][40], sWl[128][40];

    const int tid = threadIdx.x, l = tid & 31, w = tid >> 5;
    const int wm = w >> 2, wn = w & 3;
    const int m0 = blockIdx.y << 7, n0 = blockIdx.x << 7;

    float acc[4][4][4];
#pragma unroll
    for (int i = 0; i < 4; i++)
#pragma unroll
        for (int j = 0; j < 4; j++)
#pragma unroll
            for (int e = 0; e < 4; e++) acc[i][j][e] = 0.f;

    const unsigned aBaseH = s2u(&sAh[0][0]), aBaseL = s2u(&sAl[0][0]);
    const unsigned wBaseH = s2u(&sWh[0][0]), wBaseL = s2u(&sWl[0][0]);
    const int aRow = wm * 64 + (l & 15);
    const int aCol = (l & 16) >> 1;
    const int bRow = wn * 32 + (l & 7) + ((l & 16) >> 1);
    const int bCol = l & 8;

    for (int k0 = 0; k0 < K; k0 += 32) {
        __syncthreads();
#pragma unroll
        for (int t = 0; t < 4; t++) {
            int fi = tid + t * 256;
            int row = fi >> 3, c4 = (fi & 7) << 2;
            float4 av = make_float4(0.f, 0.f, 0.f, 0.f);
            if (m0 + row < M)
                av = *(const float4*)&A[(size_t)(m0 + row) * K + k0 + c4];
            sstore4(&sAh[row][c4], &sAl[row][c4], av);
            float4 wv = *(const float4*)&W[(size_t)(n0 + row) * K + k0 + c4];
            sstore4(&sWh[row][c4], &sWl[row][c4], wv);
        }
        __syncthreads();
#pragma unroll
        for (int kc = 0; kc < 2; kc++) {
            const int kk = kc << 4;
            unsigned ah[4][4], al[4][4], bh[4][2], bl[4][2];
#pragma unroll
            for (int mt = 0; mt < 4; mt++) {
                unsigned off = ((aRow + mt * 16) * 40 + kk + aCol) * 2;
                ldsm4(aBaseH + off, ah[mt][0], ah[mt][1], ah[mt][2], ah[mt][3]);
                ldsm4(aBaseL + off, al[mt][0], al[mt][1], al[mt][2], al[mt][3]);
            }
#pragma unroll
            for (int np = 0; np < 2; np++) {
                unsigned off = ((bRow + np * 16) * 40 + kk + bCol) * 2;
                unsigned r0, r1, r2, r3;
                ldsm4(wBaseH + off, r0, r1, r2, r3);
                bh[np * 2][0] = r0; bh[np * 2][1] = r1;
                bh[np * 2 + 1][0] = r2; bh[np * 2 + 1][1] = r3;
                ldsm4(wBaseL + off, r0, r1, r2, r3);
                bl[np * 2][0] = r0; bl[np * 2][1] = r1;
                bl[np * 2 + 1][0] = r2; bl[np * 2 + 1][1] = r3;
            }
#pragma unroll
            for (int mt = 0; mt < 4; mt++)
#pragma unroll
                for (int nt = 0; nt < 4; nt++) {
                    mma_bf16(acc[mt][nt], ah[mt], bh[nt]);
                    mma_bf16(acc[mt][nt], al[mt], bh[nt]);
                    mma_bf16(acc[mt][nt], ah[mt], bl[nt]);
                }
        }
    }

    const int er = m0 + wm * 64 + (l >> 2);
    const int ec = n0 + wn * 32 + ((l & 3) << 1);
#pragma unroll
    for (int mt = 0; mt < 4; mt++) {
#pragma unroll
        for (int nt = 0; nt < 4; nt++) {
            int col = ec + nt * 8;
#pragma unroll
            for (int half = 0; half < 2; half++) {
                int r = er + mt * 16 + half * 8;
                if (r >= M) continue;
                float a0 = acc[mt][nt][half * 2];
                float a1 = acc[mt][nt][half * 2 + 1];
                if (mode == 0) {
                    float bx = 0.f, by = 0.f;
                    if (bias) {
                        float2 bb = *(const float2*)&bias[col];
                        bx = bb.x; by = bb.y;
                    }
                    *(float2*)&C_ext[(size_t)r * N + col] =
                        make_float2(a0 + bx, a1 + by);
                } else if (mode == 1) {
                    int hh_ = col / 192;
                    int rem = col - hh_ * 192;
                    int part = rem >> 6, d = rem & 63;
                    if (part == 0) {
                        *(float2*)&g_q[(size_t)r * 512 + hh_ * 64 + d] =
                            make_float2(a0, a1);
                    } else {
                        int b = r >> 10, ll2 = r & 1023;
                        size_t idx =
                            (((size_t)(b * 8 + hh_)) * 1024 + ll2) * 64 + d;
                        __half2 hv = __floats2half2_rn(a0, a1);
                        if (part == 1) *(__half2*)&g_k[idx] = hv;
                        else           *(__half2*)&g_v[idx] = hv;
                    }
                } else {
                    int hh_ = col >> 6, d = col & 63;
                    size_t idx = (((size_t)hh_) * 2048 + r) * 64 + d;
                    __half2 hv = __floats2half2_rn(a0, a1);
                    *(__half2*)&g_p[idx] = hv;
                }
            }
        }
    }
}

// ---------------------------------------------------------------------------
// Fused attention, fp16 single-plane, cp.async double-buffered tiles.
// Grid (8, 64), 256 threads.
// ---------------------------------------------------------------------------
#define AQU 0
#define AQV 18432
#define AK0 36864            /* 2 x 9216  */
#define AV0 55296            /* 2 x 9216  */
#define AP0 73728            /* 2 x 27648 */
#define ASCR 129024          /* 8 x 16 x 92 floats = 47104 */
#define SM_BYTES_A (129024 + 47104)

__global__ __launch_bounds__(256, 1) void attn_kernel(
    const float* __restrict__ ubias, const float* __restrict__ vbias,
    float* __restrict__ attn_ext, int use_scratch) {
    extern __shared__ char smem[];
    float* attn = use_scratch ? g_attn_scratch : attn_ext;

    __half* QU = (__half*)(smem + AQU);
    __half* QV = (__half*)(smem + AQV);

    const int tid = threadIdx.x, l = tid & 31, w = tid >> 5;
    const int bh = blockIdx.y, b = bh >> 3, h = bh & 7;
    const int q0 = blockIdx.x << 7;
    const int qs = w << 4;
    const float scale = 0.04419417382415922f;  // 1/sqrt(512)

    const unsigned kB0 = s2u(smem + AK0);
    const unsigned vB0 = s2u(smem + AV0);
    const unsigned pB0 = s2u(smem + AP0);
    float* scr = (float*)(smem + ASCR) + w * 16 * 92;

    auto issue_tile = [&](int kt0, int bb) {
        size_t gb = (((size_t)bh) * 1024 + kt0) * 64;
        const uint4* GK = (const uint4*)(g_k + gb);
        const uint4* GV = (const uint4*)(g_v + gb);
        int pbase = kt0 - q0 + 896;
        const uint4* GP = (const uint4*)(g_p + (((size_t)h) * 2048 + pbase) * 64);
        unsigned kb = kB0 + bb * 9216;
        unsigned vb = vB0 + bb * 9216;
        unsigned pb = pB0 + bb * 27648;
#pragma unroll
        for (int t = 0; t < 2; t++) {
            int i = tid + t * 256;
            unsigned so = (unsigned)((i >> 3) * 9 + (i & 7)) * 16;
            cpa16(kb + so, GK + i);
            cpa16(vb + so, GV + i);
        }
#pragma unroll
        for (int t = 0; t < 6; t++) {
            int i = tid + t * 256;
            unsigned so = (unsigned)((i >> 3) * 9 + (i & 7)) * 16;
            cpa16(pb + so, GP + i);
        }
        asm volatile("cp.async.commit_group;\n" ::: "memory");
    };

    issue_tile(0, 0);

    // ---- QU/QV tiles (fp16, stride 72) ----
    for (int idx = tid; idx < 4096; idx += 256) {
        int qi = idx >> 5, d2 = (idx & 31) << 1;
        float2 qv =
            *(const float2*)&g_q[((size_t)(b * Lc + q0 + qi)) * 512 + h * 64 + d2];
        *(unsigned*)&QU[qi * 72 + d2] =
            packh2((qv.x + ubias[h * 64 + d2]) * scale,
                   (qv.y + ubias[h * 64 + d2 + 1]) * scale);
        *(unsigned*)&QV[qi * 72 + d2] =
            packh2((qv.x + vbias[h * 64 + d2]) * scale,
                   (qv.y + vbias[h * 64 + d2 + 1]) * scale);
    }
    __syncthreads();

    // ---- persistent Q fragments ----
    unsigned au[4][4], av[4][4];
    {
        unsigned baseU = s2u(QU), baseV = s2u(QV);
        int row = qs + (l & 15), colp = (l & 16) >> 1;
#pragma unroll
        for (int kc = 0; kc < 4; kc++) {
            unsigned off = (row * 72 + kc * 16 + colp) * 2;
            ldsm4(baseU + off, au[kc][0], au[kc][1], au[kc][2], au[kc][3]);
            ldsm4(baseV + off, av[kc][0], av[kc][1], av[kc][2], av[kc][3]);
        }
    }

    float ct[8][4];
#pragma unroll
    for (int nt = 0; nt < 8; nt++)
#pragma unroll
        for (int e = 0; e < 4; e++) ct[nt][e] = 0.f;
    float rs_lo = 0.f, rs_hi = 0.f;

    const int nlane = (l & 7) + ((l & 16) >> 1);
    const int klane = l & 8;
    const int tkl = (l & 7) + (l & 8);
    const int tnl = (l & 16) >> 1;
    const int r0w = 112 - qs;

    for (int kt = 0; kt < 16; kt++) {
        const int bb = kt & 1;
        const int kt0 = kt << 6;
        __syncthreads();                      // everyone done with buf bb^1
        if (kt < 15) {
            issue_tile(kt0 + 64, bb ^ 1);
            asm volatile("cp.async.wait_group 1;\n" ::: "memory");
        } else {
            asm volatile("cp.async.wait_group 0;\n" ::: "memory");
        }
        __syncthreads();                      // buf bb visible to all

        const unsigned kB = kB0 + bb * 9216;
        const unsigned vB = vB0 + bb * 9216;
        const unsigned pB = pB0 + bb * 27648;

        // ---- bd strip: 16x80 per warp ----
        float bd[10][4];
#pragma unroll
        for (int nt = 0; nt < 10; nt++)
#pragma unroll
            for (int e = 0; e < 4; e++) bd[nt][e] = 0.f;
#pragma unroll
        for (int np = 0; np < 5; np++) {
            int nb = r0w + np * 16 + nlane;
#pragma unroll
            for (int kc = 0; kc < 4; kc++) {
                unsigned r0, r1, r2, r3;
                ldsm4(pB + (nb * 72 + kc * 16 + klane) * 2, r0, r1, r2, r3);
                unsigned b0[2] = {r0, r1}, b1[2] = {r2, r3};
                mma_f16(bd[np * 2], av[kc], b0);
                mma_f16(bd[np * 2 + 1], av[kc], b1);
            }
        }
        {
            int r = l >> 2, col = ((l & 3) << 1);
#pragma unroll
            for (int nt = 0; nt < 10; nt++) {
                *(float2*)&scr[r * 92 + nt * 8 + col] =
                    make_float2(bd[nt][0], bd[nt][1]);
                *(float2*)&scr[(r + 8) * 92 + nt * 8 + col] =
                    make_float2(bd[nt][2], bd[nt][3]);
            }
        }
        __syncwarp();

        // ---- ac ----
        float sc[8][4];
#pragma unroll
        for (int nt = 0; nt < 8; nt++)
#pragma unroll
            for (int e = 0; e < 4; e++) sc[nt][e] = 0.f;
#pragma unroll
        for (int np = 0; np < 4; np++) {
            int nb = np * 16 + nlane;
#pragma unroll
            for (int kc = 0; kc < 4; kc++) {
                unsigned r0, r1, r2, r3;
                ldsm4(kB + (nb * 72 + kc * 16 + klane) * 2, r0, r1, r2, r3);
                unsigned b0[2] = {r0, r1}, b1[2] = {r2, r3};
                mma_f16(sc[np * 2], au[kc], b0);
                mma_f16(sc[np * 2 + 1], au[kc], b1);
            }
        }

        // ---- add banded bd, exp, rowsum, store unnormalized probs ----
        {
            int r = l >> 2;
#pragma unroll
            for (int nt = 0; nt < 8; nt++) {
                int kk = nt * 8 + ((l & 3) << 1);
                int j = kk - r + 15;
                sc[nt][0] += scr[r * 92 + j];
                sc[nt][1] += scr[r * 92 + j + 1];
                int j2 = kk - (r + 8) + 15;
                sc[nt][2] += scr[(r + 8) * 92 + j2];
                sc[nt][3] += scr[(r + 8) * 92 + j2 + 1];
            }
#pragma unroll
            for (int nt = 0; nt < 8; nt++) {
#pragma unroll
                for (int e = 0; e < 4; e++) sc[nt][e] = __expf(sc[nt][e]);
                rs_lo += sc[nt][0] + sc[nt][1];
                rs_hi += sc[nt][2] + sc[nt][3];
            }
            size_t rbase =
                ((size_t)bh * Lc + (q0 + qs + r)) * Lc + kt0 + ((l & 3) << 1);
#pragma unroll
            for (int nt = 0; nt < 8; nt++) {
                *(float2*)&attn[rbase + nt * 8] = make_float2(sc[nt][0], sc[nt][1]);
                *(float2*)&attn[rbase + 8 * Lc + nt * 8] =
                    make_float2(sc[nt][2], sc[nt][3]);
            }
        }

        // ---- ctx += P @ V ----
#pragma unroll
        for (int kc = 0; kc < 4; kc++) {
            unsigned pa[4];
            pa[0] = packh2(sc[2 * kc][0], sc[2 * kc][1]);
            pa[1] = packh2(sc[2 * kc][2], sc[2 * kc][3]);
            pa[2] = packh2(sc[2 * kc + 1][0], sc[2 * kc + 1][1]);
            pa[3] = packh2(sc[2 * kc + 1][2], sc[2 * kc + 1][3]);
            int krow = kc * 16 + tkl;
#pragma unroll
            for (int np = 0; np < 4; np++) {
                unsigned r0, r1, r2, r3;
                ldsm4t(vB + (krow * 72 + np * 16 + tnl) * 2, r0, r1, r2, r3);
                unsigned b0[2] = {r0, r1}, b1[2] = {r2, r3};
                mma_f16(ct[np * 2], pa, b0);
                mma_f16(ct[np * 2 + 1], pa, b1);
            }
        }
    }

    // ---- rowsum reduce, write inv, scale ctx, store ----
    rs_lo += __shfl_xor_sync(0xffffffffu, rs_lo, 1);
    rs_lo += __shfl_xor_sync(0xffffffffu, rs_lo, 2);
    rs_hi += __shfl_xor_sync(0xffffffffu, rs_hi, 1);
    rs_hi += __shfl_xor_sync(0xffffffffu, rs_hi, 2);
    float inv_lo = 1.f / rs_lo, inv_hi = 1.f / rs_hi;
    int r = l >> 2;
    if ((l & 3) == 0) {
        g_inv[bh * Lc + q0 + qs + r] = inv_lo;
        g_inv[bh * Lc + q0 + qs + r + 8] = inv_hi;
    }
    size_t cbase = ((size_t)(b * Lc + q0 + qs + r)) * 512 + h * 64 + ((l & 3) << 1);
#pragma unroll
    for (int nt = 0; nt < 8; nt++) {
        *(float2*)&g_ctx[cbase + nt * 8] =
            make_float2(ct[nt][0] * inv_lo, ct[nt][1] * inv_lo);
        *(float2*)&g_ctx[cbase + 8 * 512 + nt * 8] =
            make_float2(ct[nt][2] * inv_hi, ct[nt][3] * inv_hi);
    }
}

// ---------------------------------------------------------------------------
__global__ void norm_attn(float* __restrict__ attn) {
    size_t n4 = (size_t)ATTN_ELEMS / 4;
    for (size_t i = blockIdx.x * blockDim.x + threadIdx.x; i < n4;
         i += (size_t)gridDim.x * blockDim.x) {
        float inv = g_inv[i >> 8];
        float4 v = ((float4*)attn)[i];
        v.x *= inv; v.y *= inv; v.z *= inv; v.w *= inv;
        ((float4*)attn)[i] = v;
    }
}

// ---------------------------------------------------------------------------
extern "C" void kernel_launch(void* const* d_in, const int* in_sizes, int n_in,
                              void* d_out, int out_size) {
    const float* x    = (const float*)d_in[0];
    const float* pos  = (const float*)d_in[1];
    const float* wqkv = (const float*)d_in[2];
    const float* wpos = (const float*)d_in[3];
    const float* wout = (const float*)d_in[4];
    const float* bout = (const float*)d_in[5];
    const float* ub   = (const float*)d_in[6];
    const float* vb   = (const float*)d_in[7];
    float* out = (float*)d_out;

    int attn_in_out = ((long long)out_size >= (long long)OUT_ELEMS + ATTN_ELEMS);
    float* attn_buf = attn_in_out ? (out + OUT_ELEMS) : nullptr;

    dim3 blk(256);
    gemm_bf16s<<<dim3(12, 64), blk>>>(x, 0, wqkv, nullptr, nullptr, 1,
                                      8192, 1536, 512);
    gemm_bf16s<<<dim3(4, 16), blk>>>(pos, 0, wpos, nullptr, nullptr, 2,
                                     2047, 512, 512);

    cudaFuncSetAttribute(attn_kernel, cudaFuncAttributeMaxDynamicSharedMemorySize,
                         SM_BYTES_A);
    attn_kernel<<<dim3(8, 64), blk, SM_BYTES_A>>>(ub, vb, attn_buf,
                                                  attn_in_out ? 0 : 1);
    norm_attn<<<4096, 256>>>(attn_in_out ? attn_buf : g_attn_scratch);

    gemm_bf16s<<<dim3(4, 64), blk>>>(nullptr, 1, wout, bout, out, 0,
                                     8192, 512, 512);
}

// round 8
// speedup vs baseline: 4.7031x; 1.1418x over previous
#include <cuda_runtime.h>
#include <cuda_bf16.h>
#include <cuda_fp16.h>
#include <math.h>

#define Lc 1024
#define Pc 2047

#define OUT_ELEMS  (8 * 1024 * 512)
#define ATTN_ELEMS (64LL * 1024 * 1024)

__device__ float g_q[(size_t)8192 * 512];
__device__ float g_inv[65536];
__device__ float g_attn_scratch[(size_t)ATTN_ELEMS];
// fp16 single planes for attention operands
__device__ __half g_k[(size_t)64 * 1024 * 64];   // [bh][k][64]
__device__ __half g_v[(size_t)64 * 1024 * 64];   // [bh][k][64]
__device__ __half g_p[(size_t)8 * 2048 * 64];    // [h][p][64]; row 2047 stays zero
// split-bf16 planes (hi/lo) for GEMM operands
__device__ __nv_bfloat16 g_xh[(size_t)8192 * 512],  g_xl[(size_t)8192 * 512];
__device__ __nv_bfloat16 g_psh[(size_t)2048 * 512], g_psl[(size_t)2048 * 512];
__device__ __nv_bfloat16 g_cth[(size_t)8192 * 512], g_ctl[(size_t)8192 * 512];
__device__ __nv_bfloat16 g_wqh[(size_t)1536 * 512], g_wql[(size_t)1536 * 512];
__device__ __nv_bfloat16 g_wph[(size_t)512 * 512],  g_wpl[(size_t)512 * 512];
__device__ __nv_bfloat16 g_woh[(size_t)512 * 512],  g_wol[(size_t)512 * 512];

// ------------------------- helpers -------------------------------
__device__ __forceinline__ void mma_bf16(float* c, const unsigned* a,
                                         const unsigned* b) {
    asm volatile(
        "mma.sync.aligned.m16n8k16.row.col.f32.bf16.bf16.f32 "
        "{%0,%1,%2,%3}, {%4,%5,%6,%7}, {%8,%9}, {%0,%1,%2,%3};\n"
        : "+f"(c[0]), "+f"(c[1]), "+f"(c[2]), "+f"(c[3])
        : "r"(a[0]), "r"(a[1]), "r"(a[2]), "r"(a[3]), "r"(b[0]), "r"(b[1]));
}
__device__ __forceinline__ void mma_f16(float* c, const unsigned* a,
                                        const unsigned* b) {
    asm volatile(
        "mma.sync.aligned.m16n8k16.row.col.f32.f16.f16.f32 "
        "{%0,%1,%2,%3}, {%4,%5,%6,%7}, {%8,%9}, {%0,%1,%2,%3};\n"
        : "+f"(c[0]), "+f"(c[1]), "+f"(c[2]), "+f"(c[3])
        : "r"(a[0]), "r"(a[1]), "r"(a[2]), "r"(a[3]), "r"(b[0]), "r"(b[1]));
}
__device__ __forceinline__ void ldsm4(unsigned addr, unsigned& r0, unsigned& r1,
                                      unsigned& r2, unsigned& r3) {
    asm volatile("ldmatrix.sync.aligned.m8n8.x4.shared.b16 {%0,%1,%2,%3}, [%4];"
                 : "=r"(r0), "=r"(r1), "=r"(r2), "=r"(r3) : "r"(addr));
}
__device__ __forceinline__ void ldsm4t(unsigned addr, unsigned& r0, unsigned& r1,
                                       unsigned& r2, unsigned& r3) {
    asm volatile(
        "ldmatrix.sync.aligned.m8n8.x4.trans.shared.b16 {%0,%1,%2,%3}, [%4];"
        : "=r"(r0), "=r"(r1), "=r"(r2), "=r"(r3) : "r"(addr));
}
__device__ __forceinline__ unsigned s2u(const void* p) {
    return (unsigned)__cvta_generic_to_shared(p);
}
__device__ __forceinline__ void cpa16(unsigned dst, const void* src) {
    asm volatile("cp.async.cg.shared.global [%0], [%1], 16;\n" ::"r"(dst),
                 "l"(src));
}
__device__ __forceinline__ void pack_split(float x0, float x1, unsigned& h,
                                           unsigned& l) {
    __nv_bfloat162 hb = __floats2bfloat162_rn(x0, x1);
    float2 hf = __bfloat1622float2(hb);
    __nv_bfloat162 lb = __floats2bfloat162_rn(x0 - hf.x, x1 - hf.y);
    h = *(unsigned*)&hb; l = *(unsigned*)&lb;
}
__device__ __forceinline__ unsigned packh2(float x0, float x1) {
    __half2 t = __floats2half2_rn(x0, x1);
    return *(unsigned*)&t;
}

// ---------------------------------------------------------------------------
// Convert fp32 -> split-bf16 planes. sel picks (src implicit via arg, dst).
// ---------------------------------------------------------------------------
__global__ void cvt_split(const float* __restrict__ src, int sel, int n2) {
    __nv_bfloat16 *dh, *dl;
    switch (sel) {
        case 0: dh = g_xh;  dl = g_xl;  break;
        case 1: dh = g_wqh; dl = g_wql; break;
        case 2: dh = g_wph; dl = g_wpl; break;
        case 3: dh = g_woh; dl = g_wol; break;
        default: dh = g_psh; dl = g_psl; break;
    }
    int i = blockIdx.x * blockDim.x + threadIdx.x;
    if (i < n2) {
        float2 v = ((const float2*)src)[i];
        unsigned h, l;
        pack_split(v.x, v.y, h, l);
        ((unsigned*)dh)[i] = h;
        ((unsigned*)dl)[i] = l;
    }
}

// ---------------------------------------------------------------------------
// Split-bf16 GEMM from pre-split planes, K=512, cp.async double-buffered.
// C[M,N] = A[M,K] @ W[N,K]^T. Tile 128x128. No bounds checks (dims padded).
// asel: 0=x, 1=pos, 2=ctx. wsel: 0=wqkv, 1=wpos, 2=wout.
// mode 0: fp32 C (+bias). mode 1: qkv epilogue. mode 2: pos epilogue.
// ---------------------------------------------------------------------------
#define GT 10240                  /* bytes per tile (128 rows x 40 elems x 2B) */
#define GSTAGE (4 * GT)           /* 4 tiles per stage */
#define GSM (2 * GSTAGE)

__global__ __launch_bounds__(256, 1) void gemm_planes(
    int asel, int wsel, const float* __restrict__ bias,
    float* __restrict__ C_ext, int mode, int N) {
    extern __shared__ char smem[];

    const __nv_bfloat16 *Ah, *Al, *Wh, *Wl;
    Ah = (asel == 0) ? g_xh : (asel == 1) ? g_psh : g_cth;
    Al = (asel == 0) ? g_xl : (asel == 1) ? g_psl : g_ctl;
    Wh = (wsel == 0) ? g_wqh : (wsel == 1) ? g_wph : g_woh;
    Wl = (wsel == 0) ? g_wql : (wsel == 1) ? g_wpl : g_wol;

    const int tid = threadIdx.x, l = tid & 31, w = tid >> 5;
    const int wm = w >> 2, wn = w & 3;
    const int m0 = blockIdx.y << 7, n0 = blockIdx.x << 7;
    const unsigned sb = s2u(smem);

    float acc[4][4][4];
#pragma unroll
    for (int i = 0; i < 4; i++)
#pragma unroll
        for (int j = 0; j < 4; j++)
#pragma unroll
            for (int e = 0; e < 4; e++) acc[i][j][e] = 0.f;

    const int aRow = wm * 64 + (l & 15);
    const int aCol = (l & 16) >> 1;
    const int bRow = wn * 32 + (l & 7) + ((l & 16) >> 1);
    const int bCol = l & 8;

    const int lrow = tid >> 2, lc = (tid & 3) << 3;  // 16B chunk: 8 elems

    auto issue = [&](int k0, int bb) {
        unsigned base = sb + bb * GSTAGE;
#pragma unroll
        for (int t = 0; t < 2; t++) {
            int row = lrow + t * 64;
            unsigned so = (unsigned)row * 80 + ((unsigned)lc << 1);
            size_t ao = (size_t)(m0 + row) * 512 + k0 + lc;
            size_t wo = (size_t)(n0 + row) * 512 + k0 + lc;
            cpa16(base + so, Ah + ao);
            cpa16(base + GT + so, Al + ao);
            cpa16(base + 2 * GT + so, Wh + wo);
            cpa16(base + 3 * GT + so, Wl + wo);
        }
        asm volatile("cp.async.commit_group;\n" ::: "memory");
    };

    issue(0, 0);
    for (int s = 0; s < 16; s++) {
        const int bb = s & 1;
        __syncthreads();
        if (s < 15) {
            issue((s + 1) << 5, bb ^ 1);
            asm volatile("cp.async.wait_group 1;\n" ::: "memory");
        } else {
            asm volatile("cp.async.wait_group 0;\n" ::: "memory");
        }
        __syncthreads();

        unsigned base = sb + bb * GSTAGE;
#pragma unroll
        for (int kc = 0; kc < 2; kc++) {
            const int kk = kc << 4;
            unsigned ah[4][4], al[4][4], bh[4][2], bl[4][2];
#pragma unroll
            for (int mt = 0; mt < 4; mt++) {
                unsigned off = ((aRow + mt * 16) * 40 + kk + aCol) * 2;
                ldsm4(base + off, ah[mt][0], ah[mt][1], ah[mt][2], ah[mt][3]);
                ldsm4(base + GT + off, al[mt][0], al[mt][1], al[mt][2],
                      al[mt][3]);
            }
#pragma unroll
            for (int np = 0; np < 2; np++) {
                unsigned off = ((bRow + np * 16) * 40 + kk + bCol) * 2;
                unsigned r0, r1, r2, r3;
                ldsm4(base + 2 * GT + off, r0, r1, r2, r3);
                bh[np * 2][0] = r0; bh[np * 2][1] = r1;
                bh[np * 2 + 1][0] = r2; bh[np * 2 + 1][1] = r3;
                ldsm4(base + 3 * GT + off, r0, r1, r2, r3);
                bl[np * 2][0] = r0; bl[np * 2][1] = r1;
                bl[np * 2 + 1][0] = r2; bl[np * 2 + 1][1] = r3;
            }
#pragma unroll
            for (int mt = 0; mt < 4; mt++)
#pragma unroll
                for (int nt = 0; nt < 4; nt++) {
                    mma_bf16(acc[mt][nt], ah[mt], bh[nt]);
                    mma_bf16(acc[mt][nt], al[mt], bh[nt]);
                    mma_bf16(acc[mt][nt], ah[mt], bl[nt]);
                }
        }
    }

    const int er = m0 + wm * 64 + (l >> 2);
    const int ec = n0 + wn * 32 + ((l & 3) << 1);
#pragma unroll
    for (int mt = 0; mt < 4; mt++) {
#pragma unroll
        for (int nt = 0; nt < 4; nt++) {
            int col = ec + nt * 8;
#pragma unroll
            for (int half = 0; half < 2; half++) {
                int r = er + mt * 16 + half * 8;
                float a0 = acc[mt][nt][half * 2];
                float a1 = acc[mt][nt][half * 2 + 1];
                if (mode == 0) {
                    float2 bb2 = *(const float2*)&bias[col];
                    *(float2*)&C_ext[(size_t)r * N + col] =
                        make_float2(a0 + bb2.x, a1 + bb2.y);
                } else if (mode == 1) {
                    int hh_ = col / 192;
                    int rem = col - hh_ * 192;
                    int part = rem >> 6, d = rem & 63;
                    if (part == 0) {
                        *(float2*)&g_q[(size_t)r * 512 + hh_ * 64 + d] =
                            make_float2(a0, a1);
                    } else {
                        int b = r >> 10, ll2 = r & 1023;
                        size_t idx =
                            (((size_t)(b * 8 + hh_)) * 1024 + ll2) * 64 + d;
                        __half2 hv = __floats2half2_rn(a0, a1);
                        if (part == 1) *(__half2*)&g_k[idx] = hv;
                        else           *(__half2*)&g_v[idx] = hv;
                    }
                } else {
                    int hh_ = col >> 6, d = col & 63;
                    size_t idx = (((size_t)hh_) * 2048 + r) * 64 + d;
                    *(__half2*)&g_p[idx] = __floats2half2_rn(a0, a1);
                }
            }
        }
    }
}

// ---------------------------------------------------------------------------
// Fused attention, fp16 single-plane, cp.async double-buffered tiles.
// Grid (8, 64), 256 threads. Writes ctx as split-bf16 planes.
// ---------------------------------------------------------------------------
#define AQU 0
#define AQV 18432
#define AK0 36864            /* 2 x 9216  */
#define AV0 55296            /* 2 x 9216  */
#define AP0 73728            /* 2 x 27648 */
#define ASCR 129024          /* 8 x 16 x 92 floats = 47104 */
#define SM_BYTES_A (129024 + 47104)

__global__ __launch_bounds__(256, 1) void attn_kernel(
    const float* __restrict__ ubias, const float* __restrict__ vbias,
    float* __restrict__ attn_ext, int use_scratch) {
    extern __shared__ char smem[];
    float* attn = use_scratch ? g_attn_scratch : attn_ext;

    __half* QU = (__half*)(smem + AQU);
    __half* QV = (__half*)(smem + AQV);

    const int tid = threadIdx.x, l = tid & 31, w = tid >> 5;
    const int bh = blockIdx.y, b = bh >> 3, h = bh & 7;
    const int q0 = blockIdx.x << 7;
    const int qs = w << 4;
    const float scale = 0.04419417382415922f;  // 1/sqrt(512)

    const unsigned kB0 = s2u(smem + AK0);
    const unsigned vB0 = s2u(smem + AV0);
    const unsigned pB0 = s2u(smem + AP0);
    float* scr = (float*)(smem + ASCR) + w * 16 * 92;

    auto issue_tile = [&](int kt0, int bb) {
        size_t gb = (((size_t)bh) * 1024 + kt0) * 64;
        const uint4* GK = (const uint4*)(g_k + gb);
        const uint4* GV = (const uint4*)(g_v + gb);
        int pbase = kt0 - q0 + 896;
        const uint4* GP = (const uint4*)(g_p + (((size_t)h) * 2048 + pbase) * 64);
        unsigned kb = kB0 + bb * 9216;
        unsigned vb = vB0 + bb * 9216;
        unsigned pb = pB0 + bb * 27648;
#pragma unroll
        for (int t = 0; t < 2; t++) {
            int i = tid + t * 256;
            unsigned so = (unsigned)((i >> 3) * 9 + (i & 7)) * 16;
            cpa16(kb + so, GK + i);
            cpa16(vb + so, GV + i);
        }
#pragma unroll
        for (int t = 0; t < 6; t++) {
            int i = tid + t * 256;
            unsigned so = (unsigned)((i >> 3) * 9 + (i & 7)) * 16;
            cpa16(pb + so, GP + i);
        }
        asm volatile("cp.async.commit_group;\n" ::: "memory");
    };

    issue_tile(0, 0);

    // ---- QU/QV tiles (fp16, stride 72) ----
    for (int idx = tid; idx < 4096; idx += 256) {
        int qi = idx >> 5, d2 = (idx & 31) << 1;
        float2 qv =
            *(const float2*)&g_q[((size_t)(b * Lc + q0 + qi)) * 512 + h * 64 + d2];
        *(unsigned*)&QU[qi * 72 + d2] =
            packh2((qv.x + ubias[h * 64 + d2]) * scale,
                   (qv.y + ubias[h * 64 + d2 + 1]) * scale);
        *(unsigned*)&QV[qi * 72 + d2] =
            packh2((qv.x + vbias[h * 64 + d2]) * scale,
                   (qv.y + vbias[h * 64 + d2 + 1]) * scale);
    }
    __syncthreads();

    // ---- persistent Q fragments ----
    unsigned au[4][4], av[4][4];
    {
        unsigned baseU = s2u(QU), baseV = s2u(QV);
        int row = qs + (l & 15), colp = (l & 16) >> 1;
#pragma unroll
        for (int kc = 0; kc < 4; kc++) {
            unsigned off = (row * 72 + kc * 16 + colp) * 2;
            ldsm4(baseU + off, au[kc][0], au[kc][1], au[kc][2], au[kc][3]);
            ldsm4(baseV + off, av[kc][0], av[kc][1], av[kc][2], av[kc][3]);
        }
    }

    float ct[8][4];
#pragma unroll
    for (int nt = 0; nt < 8; nt++)
#pragma unroll
        for (int e = 0; e < 4; e++) ct[nt][e] = 0.f;
    float rs_lo = 0.f, rs_hi = 0.f;

    const int nlane = (l & 7) + ((l & 16) >> 1);
    const int klane = l & 8;
    const int tkl = (l & 7) + (l & 8);
    const int tnl = (l & 16) >> 1;
    const int r0w = 112 - qs;

    for (int kt = 0; kt < 16; kt++) {
        const int bb = kt & 1;
        const int kt0 = kt << 6;
        __syncthreads();
        if (kt < 15) {
            issue_tile(kt0 + 64, bb ^ 1);
            asm volatile("cp.async.wait_group 1;\n" ::: "memory");
        } else {
            asm volatile("cp.async.wait_group 0;\n" ::: "memory");
        }
        __syncthreads();

        const unsigned kB = kB0 + bb * 9216;
        const unsigned vB = vB0 + bb * 9216;
        const unsigned pB = pB0 + bb * 27648;

        // ---- bd strip: 16x80 per warp ----
        float bd[10][4];
#pragma unroll
        for (int nt = 0; nt < 10; nt++)
#pragma unroll
            for (int e = 0; e < 4; e++) bd[nt][e] = 0.f;
#pragma unroll
        for (int np = 0; np < 5; np++) {
            int nb = r0w + np * 16 + nlane;
#pragma unroll
            for (int kc = 0; kc < 4; kc++) {
                unsigned r0, r1, r2, r3;
                ldsm4(pB + (nb * 72 + kc * 16 + klane) * 2, r0, r1, r2, r3);
                unsigned b0[2] = {r0, r1}, b1[2] = {r2, r3};
                mma_f16(bd[np * 2], av[kc], b0);
                mma_f16(bd[np * 2 + 1], av[kc], b1);
            }
        }
        {
            int r = l >> 2, col = ((l & 3) << 1);
#pragma unroll
            for (int nt = 0; nt < 10; nt++) {
                *(float2*)&scr[r * 92 + nt * 8 + col] =
                    make_float2(bd[nt][0], bd[nt][1]);
                *(float2*)&scr[(r + 8) * 92 + nt * 8 + col] =
                    make_float2(bd[nt][2], bd[nt][3]);
            }
        }
        __syncwarp();

        // ---- ac ----
        float sc[8][4];
#pragma unroll
        for (int nt = 0; nt < 8; nt++)
#pragma unroll
            for (int e = 0; e < 4; e++) sc[nt][e] = 0.f;
#pragma unroll
        for (int np = 0; np < 4; np++) {
            int nb = np * 16 + nlane;
#pragma unroll
            for (int kc = 0; kc < 4; kc++) {
                unsigned r0, r1, r2, r3;
                ldsm4(kB + (nb * 72 + kc * 16 + klane) * 2, r0, r1, r2, r3);
                unsigned b0[2] = {r0, r1}, b1[2] = {r2, r3};
                mma_f16(sc[np * 2], au[kc], b0);
                mma_f16(sc[np * 2 + 1], au[kc], b1);
            }
        }

        // ---- add banded bd, exp, rowsum, store unnormalized probs ----
        {
            int r = l >> 2;
#pragma unroll
            for (int nt = 0; nt < 8; nt++) {
                int kk = nt * 8 + ((l & 3) << 1);
                int j = kk - r + 15;
                sc[nt][0] += scr[r * 92 + j];
                sc[nt][1] += scr[r * 92 + j + 1];
                int j2 = kk - (r + 8) + 15;
                sc[nt][2] += scr[(r + 8) * 92 + j2];
                sc[nt][3] += scr[(r + 8) * 92 + j2 + 1];
            }
#pragma unroll
            for (int nt = 0; nt < 8; nt++) {
#pragma unroll
                for (int e = 0; e < 4; e++) sc[nt][e] = __expf(sc[nt][e]);
                rs_lo += sc[nt][0] + sc[nt][1];
                rs_hi += sc[nt][2] + sc[nt][3];
            }
            size_t rbase =
                ((size_t)bh * Lc + (q0 + qs + r)) * Lc + kt0 + ((l & 3) << 1);
#pragma unroll
            for (int nt = 0; nt < 8; nt++) {
                *(float2*)&attn[rbase + nt * 8] = make_float2(sc[nt][0], sc[nt][1]);
                *(float2*)&attn[rbase + 8 * Lc + nt * 8] =
                    make_float2(sc[nt][2], sc[nt][3]);
            }
        }

        // ---- ctx += P @ V ----
#pragma unroll
        for (int kc = 0; kc < 4; kc++) {
            unsigned pa[4];
            pa[0] = packh2(sc[2 * kc][0], sc[2 * kc][1]);
            pa[1] = packh2(sc[2 * kc][2], sc[2 * kc][3]);
            pa[2] = packh2(sc[2 * kc + 1][0], sc[2 * kc + 1][1]);
            pa[3] = packh2(sc[2 * kc + 1][2], sc[2 * kc + 1][3]);
            int krow = kc * 16 + tkl;
#pragma unroll
            for (int np = 0; np < 4; np++) {
                unsigned r0, r1, r2, r3;
                ldsm4t(vB + (krow * 72 + np * 16 + tnl) * 2, r0, r1, r2, r3);
                unsigned b0[2] = {r0, r1}, b1[2] = {r2, r3};
                mma_f16(ct[np * 2], pa, b0);
                mma_f16(ct[np * 2 + 1], pa, b1);
            }
        }
    }

    // ---- rowsum reduce, write inv, scale ctx, store as split planes ----
    rs_lo += __shfl_xor_sync(0xffffffffu, rs_lo, 1);
    rs_lo += __shfl_xor_sync(0xffffffffu, rs_lo, 2);
    rs_hi += __shfl_xor_sync(0xffffffffu, rs_hi, 1);
    rs_hi += __shfl_xor_sync(0xffffffffu, rs_hi, 2);
    float inv_lo = 1.f / rs_lo, inv_hi = 1.f / rs_hi;
    int r = l >> 2;
    if ((l & 3) == 0) {
        g_inv[bh * Lc + q0 + qs + r] = inv_lo;
        g_inv[bh * Lc + q0 + qs + r + 8] = inv_hi;
    }
    size_t cbase = ((size_t)(b * Lc + q0 + qs + r)) * 512 + h * 64 + ((l & 3) << 1);
#pragma unroll
    for (int nt = 0; nt < 8; nt++) {
        unsigned hh, lo;
        pack_split(ct[nt][0] * inv_lo, ct[nt][1] * inv_lo, hh, lo);
        *(unsigned*)&g_cth[cbase + nt * 8] = hh;
        *(unsigned*)&g_ctl[cbase + nt * 8] = lo;
        pack_split(ct[nt][2] * inv_hi, ct[nt][3] * inv_hi, hh, lo);
        *(unsigned*)&g_cth[cbase + 8 * 512 + nt * 8] = hh;
        *(unsigned*)&g_ctl[cbase + 8 * 512 + nt * 8] = lo;
    }
}

// ---------------------------------------------------------------------------
__global__ void norm_attn(float* __restrict__ attn) {
    size_t n4 = (size_t)ATTN_ELEMS / 4;
    for (size_t i = blockIdx.x * blockDim.x + threadIdx.x; i < n4;
         i += (size_t)gridDim.x * blockDim.x) {
        float inv = g_inv[i >> 8];
        float4 v = ((float4*)attn)[i];
        v.x *= inv; v.y *= inv; v.z *= inv; v.w *= inv;
        ((float4*)attn)[i] = v;
    }
}

// ---------------------------------------------------------------------------
extern "C" void kernel_launch(void* const* d_in, const int* in_sizes, int n_in,
                              void* d_out, int out_size) {
    const float* x    = (const float*)d_in[0];
    const float* pos  = (const float*)d_in[1];
    const float* wqkv = (const float*)d_in[2];
    const float* wpos = (const float*)d_in[3];
    const float* wout = (const float*)d_in[4];
    const float* bout = (const float*)d_in[5];
    const float* ub   = (const float*)d_in[6];
    const float* vb   = (const float*)d_in[7];
    float* out = (float*)d_out;

    int attn_in_out = ((long long)out_size >= (long long)OUT_ELEMS + ATTN_ELEMS);
    float* attn_buf = attn_in_out ? (out + OUT_ELEMS) : nullptr;

    // pre-split fp32 -> bf16 hi/lo planes
    cvt_split<<<8192, 256>>>(x, 0, 8192 * 256);
    cvt_split<<<1536, 256>>>(wqkv, 1, 1536 * 256);
    cvt_split<<<512, 256>>>(wpos, 2, 512 * 256);
    cvt_split<<<512, 256>>>(wout, 3, 512 * 256);
    cvt_split<<<2047, 256>>>(pos, 4, 2047 * 256);

    dim3 blk(256);
    cudaFuncSetAttribute(gemm_planes, cudaFuncAttributeMaxDynamicSharedMemorySize,
                         GSM);
    // proj = x @ wqkv^T : (8192,1536)
    gemm_planes<<<dim3(12, 64), blk, GSM>>>(0, 0, nullptr, nullptr, 1, 1536);
    // p_k = pos @ wpos^T : (2048 padded, 512)
    gemm_planes<<<dim3(4, 16), blk, GSM>>>(1, 1, nullptr, nullptr, 2, 512);

    cudaFuncSetAttribute(attn_kernel, cudaFuncAttributeMaxDynamicSharedMemorySize,
                         SM_BYTES_A);
    attn_kernel<<<dim3(8, 64), blk, SM_BYTES_A>>>(ub, vb, attn_buf,
                                                  attn_in_out ? 0 : 1);
    norm_attn<<<4096, 256>>>(attn_in_out ? attn_buf : g_attn_scratch);

    // out = ctx @ wout^T + bout : (8192,512)
    gemm_planes<<<dim3(4, 64), blk, GSM>>>(2, 2, bout, out, 0, 512);
}

// round 9
// speedup vs baseline: 4.7983x; 1.0202x over previous
#include <cuda_runtime.h>
#include <cuda_bf16.h>
#include <cuda_fp16.h>
#include <math.h>

#define Lc 1024
#define Pc 2047

#define OUT_ELEMS  (8 * 1024 * 512)
#define ATTN_ELEMS (64LL * 1024 * 1024)

__device__ float g_q[(size_t)8192 * 512];
__device__ float g_inv[65536];
__device__ float g_attn_scratch[(size_t)ATTN_ELEMS];
// fp16 single planes for attention operands
__device__ __half g_k[(size_t)64 * 1024 * 64];   // [bh][k][64]
__device__ __half g_v[(size_t)64 * 1024 * 64];   // [bh][k][64]
__device__ __half g_p[(size_t)8 * 2048 * 64];    // [h][p][64]; row 2047 stays zero
// split-bf16 planes (hi/lo) for GEMM operands
__device__ __nv_bfloat16 g_xh[(size_t)8192 * 512],  g_xl[(size_t)8192 * 512];
__device__ __nv_bfloat16 g_psh[(size_t)2048 * 512], g_psl[(size_t)2048 * 512];
__device__ __nv_bfloat16 g_cth[(size_t)8192 * 512], g_ctl[(size_t)8192 * 512];
__device__ __nv_bfloat16 g_wqh[(size_t)1536 * 512], g_wql[(size_t)1536 * 512];
__device__ __nv_bfloat16 g_wph[(size_t)512 * 512],  g_wpl[(size_t)512 * 512];
__device__ __nv_bfloat16 g_woh[(size_t)512 * 512],  g_wol[(size_t)512 * 512];

// ------------------------- helpers -------------------------------
__device__ __forceinline__ void mma_bf16(float* c, const unsigned* a,
                                         const unsigned* b) {
    asm volatile(
        "mma.sync.aligned.m16n8k16.row.col.f32.bf16.bf16.f32 "
        "{%0,%1,%2,%3}, {%4,%5,%6,%7}, {%8,%9}, {%0,%1,%2,%3};\n"
        : "+f"(c[0]), "+f"(c[1]), "+f"(c[2]), "+f"(c[3])
        : "r"(a[0]), "r"(a[1]), "r"(a[2]), "r"(a[3]), "r"(b[0]), "r"(b[1]));
}
__device__ __forceinline__ void mma_f16(float* c, const unsigned* a,
                                        const unsigned* b) {
    asm volatile(
        "mma.sync.aligned.m16n8k16.row.col.f32.f16.f16.f32 "
        "{%0,%1,%2,%3}, {%4,%5,%6,%7}, {%8,%9}, {%0,%1,%2,%3};\n"
        : "+f"(c[0]), "+f"(c[1]), "+f"(c[2]), "+f"(c[3])
        : "r"(a[0]), "r"(a[1]), "r"(a[2]), "r"(a[3]), "r"(b[0]), "r"(b[1]));
}
__device__ __forceinline__ void ldsm4(unsigned addr, unsigned& r0, unsigned& r1,
                                      unsigned& r2, unsigned& r3) {
    asm volatile("ldmatrix.sync.aligned.m8n8.x4.shared.b16 {%0,%1,%2,%3}, [%4];"
                 : "=r"(r0), "=r"(r1), "=r"(r2), "=r"(r3) : "r"(addr));
}
__device__ __forceinline__ void ldsm4t(unsigned addr, unsigned& r0, unsigned& r1,
                                       unsigned& r2, unsigned& r3) {
    asm volatile(
        "ldmatrix.sync.aligned.m8n8.x4.trans.shared.b16 {%0,%1,%2,%3}, [%4];"
        : "=r"(r0), "=r"(r1), "=r"(r2), "=r"(r3) : "r"(addr));
}
__device__ __forceinline__ unsigned s2u(const void* p) {
    return (unsigned)__cvta_generic_to_shared(p);
}
__device__ __forceinline__ void cpa16(unsigned dst, const void* src) {
    asm volatile("cp.async.cg.shared.global [%0], [%1], 16;\n" ::"r"(dst),
                 "l"(src));
}
__device__ __forceinline__ void pack_split(float x0, float x1, unsigned& h,
                                           unsigned& l) {
    __nv_bfloat162 hb = __floats2bfloat162_rn(x0, x1);
    float2 hf = __bfloat1622float2(hb);
    __nv_bfloat162 lb = __floats2bfloat162_rn(x0 - hf.x, x1 - hf.y);
    h = *(unsigned*)&hb; l = *(unsigned*)&lb;
}
__device__ __forceinline__ unsigned packh2(float x0, float x1) {
    __half2 t = __floats2half2_rn(x0, x1);
    return *(unsigned*)&t;
}

// ---------------------------------------------------------------------------
// One-shot conversion of all fp32 operands to split-bf16 planes.
// Block ranges: [0,8192) x | [8192,9728) wqkv | [9728,10240) wpos |
//               [10240,10752) wout | [10752,12799) pos.  All exact multiples.
// ---------------------------------------------------------------------------
__global__ __launch_bounds__(256) void cvt_all(
    const float* __restrict__ x, const float* __restrict__ wq,
    const float* __restrict__ wp, const float* __restrict__ wo,
    const float* __restrict__ pos) {
    int bid = blockIdx.x;
    const float* src; __nv_bfloat16 *dh, *dl; int base;
    if (bid < 8192)       { src = x;   dh = g_xh;  dl = g_xl;  base = bid; }
    else if (bid < 9728)  { src = wq;  dh = g_wqh; dl = g_wql; base = bid - 8192; }
    else if (bid < 10240) { src = wp;  dh = g_wph; dl = g_wpl; base = bid - 9728; }
    else if (bid < 10752) { src = wo;  dh = g_woh; dl = g_wol; base = bid - 10240; }
    else                  { src = pos; dh = g_psh; dl = g_psl; base = bid - 10752; }
    int i = base * 256 + threadIdx.x;
    float2 v = ((const float2*)src)[i];
    unsigned h, l;
    pack_split(v.x, v.y, h, l);
    ((unsigned*)dh)[i] = h;
    ((unsigned*)dl)[i] = l;
}

// ---------------------------------------------------------------------------
// GEMM main-loop macro body shared by the two GEMM kernels (K=512 fixed,
// 128x128 tile, split-bf16 3-term MMA, cp.async double buffered).
// ---------------------------------------------------------------------------
#define GT 10240
#define GSTAGE (4 * GT)
#define GSM (2 * GSTAGE)

#define GEMM_MAIN(Ah, Al, Wh, Wl, m0, n0, acc)                                  \
    {                                                                           \
        const unsigned sb = s2u(smem);                                          \
        const int lrow = tid >> 2, lc = (tid & 3) << 3;                         \
        auto issue = [&](int k0, int bb) {                                      \
            unsigned base = sb + bb * GSTAGE;                                   \
            _Pragma("unroll") for (int t = 0; t < 2; t++) {                     \
                int row = lrow + t * 64;                                        \
                unsigned so = (unsigned)row * 80 + ((unsigned)lc << 1);         \
                size_t ao = (size_t)(m0 + row) * 512 + k0 + lc;                 \
                size_t wo_ = (size_t)(n0 + row) * 512 + k0 + lc;                \
                cpa16(base + so, Ah + ao);                                      \
                cpa16(base + GT + so, Al + ao);                                 \
                cpa16(base + 2 * GT + so, Wh + wo_);                            \
                cpa16(base + 3 * GT + so, Wl + wo_);                            \
            }                                                                   \
            asm volatile("cp.async.commit_group;\n" ::: "memory");              \
        };                                                                      \
        issue(0, 0);                                                            \
        for (int s = 0; s < 16; s++) {                                          \
            const int bb = s & 1;                                               \
            __syncthreads();                                                    \
            if (s < 15) {                                                       \
                issue((s + 1) << 5, bb ^ 1);                                    \
                asm volatile("cp.async.wait_group 1;\n" ::: "memory");          \
            } else {                                                            \
                asm volatile("cp.async.wait_group 0;\n" ::: "memory");          \
            }                                                                   \
            __syncthreads();                                                    \
            unsigned base = sb + bb * GSTAGE;                                   \
            _Pragma("unroll") for (int kc = 0; kc < 2; kc++) {                  \
                const int kk = kc << 4;                                         \
                unsigned ah[4][4], al[4][4], bh[4][2], bl[4][2];                \
                _Pragma("unroll") for (int mt = 0; mt < 4; mt++) {              \
                    unsigned off = ((aRow + mt * 16) * 40 + kk + aCol) * 2;     \
                    ldsm4(base + off, ah[mt][0], ah[mt][1], ah[mt][2],          \
                          ah[mt][3]);                                           \
                    ldsm4(base + GT + off, al[mt][0], al[mt][1], al[mt][2],     \
                          al[mt][3]);                                           \
                }                                                               \
                _Pragma("unroll") for (int np = 0; np < 2; np++) {              \
                    unsigned off = ((bRow + np * 16) * 40 + kk + bCol) * 2;     \
                    unsigned r0, r1, r2, r3;                                    \
                    ldsm4(base + 2 * GT + off, r0, r1, r2, r3);                 \
                    bh[np * 2][0] = r0; bh[np * 2][1] = r1;                     \
                    bh[np * 2 + 1][0] = r2; bh[np * 2 + 1][1] = r3;             \
                    ldsm4(base + 3 * GT + off, r0, r1, r2, r3);                 \
                    bl[np * 2][0] = r0; bl[np * 2][1] = r1;                     \
                    bl[np * 2 + 1][0] = r2; bl[np * 2 + 1][1] = r3;             \
                }                                                               \
                _Pragma("unroll") for (int mt = 0; mt < 4; mt++)                \
                    _Pragma("unroll") for (int nt = 0; nt < 4; nt++) {          \
                        mma_bf16(acc[mt][nt], ah[mt], bh[nt]);                  \
                        mma_bf16(acc[mt][nt], al[mt], bh[nt]);                  \
                        mma_bf16(acc[mt][nt], ah[mt], bl[nt]);                  \
                    }                                                           \
            }                                                                   \
        }                                                                       \
    }

// ---------------------------------------------------------------------------
// Fused qkv-proj + pos-proj GEMM. Grid (12, 80):
//   by<64 : proj tile (m0=by*128, n0=bx*128, N=1536) -> qkv epilogue
//   by>=64: pos tile  (bx<4 only; m0=(by-64)*128, n0=bx*128) -> pos epilogue
// ---------------------------------------------------------------------------
__global__ __launch_bounds__(256, 1) void gemm_qkv_pos() {
    extern __shared__ char smem[];
    const int tid = threadIdx.x, l = tid & 31, w = tid >> 5;
    const int wm = w >> 2, wn = w & 3;
    const int aRow = wm * 64 + (l & 15);
    const int aCol = (l & 16) >> 1;
    const int bRow = wn * 32 + (l & 7) + ((l & 16) >> 1);
    const int bCol = l & 8;

    const int bx = blockIdx.x, by = blockIdx.y;
    const __nv_bfloat16 *Ah, *Al, *Wh, *Wl;
    int m0, n0, mode;
    if (by < 64) {
        Ah = g_xh; Al = g_xl; Wh = g_wqh; Wl = g_wql;
        m0 = by << 7; n0 = bx << 7; mode = 1;
    } else {
        if (bx >= 4) return;
        Ah = g_psh; Al = g_psl; Wh = g_wph; Wl = g_wpl;
        m0 = (by - 64) << 7; n0 = bx << 7; mode = 2;
    }

    float acc[4][4][4];
#pragma unroll
    for (int i = 0; i < 4; i++)
#pragma unroll
        for (int j = 0; j < 4; j++)
#pragma unroll
            for (int e = 0; e < 4; e++) acc[i][j][e] = 0.f;

    GEMM_MAIN(Ah, Al, Wh, Wl, m0, n0, acc);

    const int er = m0 + wm * 64 + (l >> 2);
    const int ec = n0 + wn * 32 + ((l & 3) << 1);
#pragma unroll
    for (int mt = 0; mt < 4; mt++) {
#pragma unroll
        for (int nt = 0; nt < 4; nt++) {
            int col = ec + nt * 8;
#pragma unroll
            for (int half = 0; half < 2; half++) {
                int r = er + mt * 16 + half * 8;
                float a0 = acc[mt][nt][half * 2];
                float a1 = acc[mt][nt][half * 2 + 1];
                if (mode == 1) {
                    int hh_ = col / 192;
                    int rem = col - hh_ * 192;
                    int part = rem >> 6, d = rem & 63;
                    if (part == 0) {
                        *(float2*)&g_q[(size_t)r * 512 + hh_ * 64 + d] =
                            make_float2(a0, a1);
                    } else {
                        int b = r >> 10, ll2 = r & 1023;
                        size_t idx =
                            (((size_t)(b * 8 + hh_)) * 1024 + ll2) * 64 + d;
                        __half2 hv = __floats2half2_rn(a0, a1);
                        if (part == 1) *(__half2*)&g_k[idx] = hv;
                        else           *(__half2*)&g_v[idx] = hv;
                    }
                } else {
                    int hh_ = col >> 6, d = col & 63;
                    size_t idx = (((size_t)hh_) * 2048 + r) * 64 + d;
                    *(__half2*)&g_p[idx] = __floats2half2_rn(a0, a1);
                }
            }
        }
    }
}

// ---------------------------------------------------------------------------
// Fused out-proj GEMM + attn normalize. Grid 2304 x 256:
//   blocks [0,256)   : out = ctx @ wout^T + bias (tensor-bound)
//   blocks [256,2304): attn normalize grid-stride (DRAM-bound) — runs
//   concurrently on the same chip, hiding the GEMM inside the norm.
// ---------------------------------------------------------------------------
#define NORM_T (2048 * 256)

__global__ __launch_bounds__(256, 1) void out_norm(
    const float* __restrict__ bias, float* __restrict__ C_ext,
    float* __restrict__ attn) {
    extern __shared__ char smem[];
    const int tid = threadIdx.x;

    if (blockIdx.x >= 256) {
        // ---- normalize path: 32 float4 per thread, 4-way MLP ----
        int t = (blockIdx.x - 256) * 256 + tid;
        float4* A4 = (float4*)attn;
#pragma unroll
        for (int it = 0; it < 8; it++) {
            size_t id[4]; float4 v[4]; float inv[4];
#pragma unroll
            for (int j = 0; j < 4; j++) {
                id[j] = (size_t)t + (size_t)(it * 4 + j) * NORM_T;
                v[j] = A4[id[j]];
            }
#pragma unroll
            for (int j = 0; j < 4; j++) inv[j] = g_inv[id[j] >> 8];
#pragma unroll
            for (int j = 0; j < 4; j++) {
                v[j].x *= inv[j]; v[j].y *= inv[j];
                v[j].z *= inv[j]; v[j].w *= inv[j];
                A4[id[j]] = v[j];
            }
        }
        return;
    }

    // ---- out-proj GEMM path ----
    const int l = tid & 31, w = tid >> 5;
    const int wm = w >> 2, wn = w & 3;
    const int aRow = wm * 64 + (l & 15);
    const int aCol = (l & 16) >> 1;
    const int bRow = wn * 32 + (l & 7) + ((l & 16) >> 1);
    const int bCol = l & 8;
    const int m0 = (blockIdx.x >> 2) << 7, n0 = (blockIdx.x & 3) << 7;

    float acc[4][4][4];
#pragma unroll
    for (int i = 0; i < 4; i++)
#pragma unroll
        for (int j = 0; j < 4; j++)
#pragma unroll
            for (int e = 0; e < 4; e++) acc[i][j][e] = 0.f;

    GEMM_MAIN(g_cth, g_ctl, g_woh, g_wol, m0, n0, acc);

    const int er = m0 + wm * 64 + (l >> 2);
    const int ec = n0 + wn * 32 + ((l & 3) << 1);
#pragma unroll
    for (int mt = 0; mt < 4; mt++) {
#pragma unroll
        for (int nt = 0; nt < 4; nt++) {
            int col = ec + nt * 8;
            float2 bb2 = *(const float2*)&bias[col];
#pragma unroll
            for (int half = 0; half < 2; half++) {
                int r = er + mt * 16 + half * 8;
                *(float2*)&C_ext[(size_t)r * 512 + col] =
                    make_float2(acc[mt][nt][half * 2] + bb2.x,
                                acc[mt][nt][half * 2 + 1] + bb2.y);
            }
        }
    }
}

// ---------------------------------------------------------------------------
// Fused attention, fp16 single-plane, cp.async double-buffered tiles.
// Grid (8, 64), 256 threads. Writes ctx as split-bf16 planes.
// ---------------------------------------------------------------------------
#define AQU 0
#define AQV 18432
#define AK0 36864
#define AV0 55296
#define AP0 73728
#define ASCR 129024
#define SM_BYTES_A (129024 + 47104)

__global__ __launch_bounds__(256, 1) void attn_kernel(
    const float* __restrict__ ubias, const float* __restrict__ vbias,
    float* __restrict__ attn_ext, int use_scratch) {
    extern __shared__ char smem[];
    float* attn = use_scratch ? g_attn_scratch : attn_ext;

    __half* QU = (__half*)(smem + AQU);
    __half* QV = (__half*)(smem + AQV);

    const int tid = threadIdx.x, l = tid & 31, w = tid >> 5;
    const int bh = blockIdx.y, b = bh >> 3, h = bh & 7;
    const int q0 = blockIdx.x << 7;
    const int qs = w << 4;
    const float scale = 0.04419417382415922f;  // 1/sqrt(512)

    const unsigned kB0 = s2u(smem + AK0);
    const unsigned vB0 = s2u(smem + AV0);
    const unsigned pB0 = s2u(smem + AP0);
    float* scr = (float*)(smem + ASCR) + w * 16 * 92;

    auto issue_tile = [&](int kt0, int bb) {
        size_t gb = (((size_t)bh) * 1024 + kt0) * 64;
        const uint4* GK = (const uint4*)(g_k + gb);
        const uint4* GV = (const uint4*)(g_v + gb);
        int pbase = kt0 - q0 + 896;
        const uint4* GP = (const uint4*)(g_p + (((size_t)h) * 2048 + pbase) * 64);
        unsigned kb = kB0 + bb * 9216;
        unsigned vb = vB0 + bb * 9216;
        unsigned pb = pB0 + bb * 27648;
#pragma unroll
        for (int t = 0; t < 2; t++) {
            int i = tid + t * 256;
            unsigned so = (unsigned)((i >> 3) * 9 + (i & 7)) * 16;
            cpa16(kb + so, GK + i);
            cpa16(vb + so, GV + i);
        }
#pragma unroll
        for (int t = 0; t < 6; t++) {
            int i = tid + t * 256;
            unsigned so = (unsigned)((i >> 3) * 9 + (i & 7)) * 16;
            cpa16(pb + so, GP + i);
        }
        asm volatile("cp.async.commit_group;\n" ::: "memory");
    };

    issue_tile(0, 0);

    for (int idx = tid; idx < 4096; idx += 256) {
        int qi = idx >> 5, d2 = (idx & 31) << 1;
        float2 qv =
            *(const float2*)&g_q[((size_t)(b * Lc + q0 + qi)) * 512 + h * 64 + d2];
        *(unsigned*)&QU[qi * 72 + d2] =
            packh2((qv.x + ubias[h * 64 + d2]) * scale,
                   (qv.y + ubias[h * 64 + d2 + 1]) * scale);
        *(unsigned*)&QV[qi * 72 + d2] =
            packh2((qv.x + vbias[h * 64 + d2]) * scale,
                   (qv.y + vbias[h * 64 + d2 + 1]) * scale);
    }
    __syncthreads();

    unsigned au[4][4], av[4][4];
    {
        unsigned baseU = s2u(QU), baseV = s2u(QV);
        int row = qs + (l & 15), colp = (l & 16) >> 1;
#pragma unroll
        for (int kc = 0; kc < 4; kc++) {
            unsigned off = (row * 72 + kc * 16 + colp) * 2;
            ldsm4(baseU + off, au[kc][0], au[kc][1], au[kc][2], au[kc][3]);
            ldsm4(baseV + off, av[kc][0], av[kc][1], av[kc][2], av[kc][3]);
        }
    }

    float ct[8][4];
#pragma unroll
    for (int nt = 0; nt < 8; nt++)
#pragma unroll
        for (int e = 0; e < 4; e++) ct[nt][e] = 0.f;
    float rs_lo = 0.f, rs_hi = 0.f;

    const int nlane = (l & 7) + ((l & 16) >> 1);
    const int klane = l & 8;
    const int tkl = (l & 7) + (l & 8);
    const int tnl = (l & 16) >> 1;
    const int r0w = 112 - qs;

    for (int kt = 0; kt < 16; kt++) {
        const int bb = kt & 1;
        const int kt0 = kt << 6;
        __syncthreads();
        if (kt < 15) {
            issue_tile(kt0 + 64, bb ^ 1);
            asm volatile("cp.async.wait_group 1;\n" ::: "memory");
        } else {
            asm volatile("cp.async.wait_group 0;\n" ::: "memory");
        }
        __syncthreads();

        const unsigned kB = kB0 + bb * 9216;
        const unsigned vB = vB0 + bb * 9216;
        const unsigned pB = pB0 + bb * 27648;

        float bd[10][4];
#pragma unroll
        for (int nt = 0; nt < 10; nt++)
#pragma unroll
            for (int e = 0; e < 4; e++) bd[nt][e] = 0.f;
#pragma unroll
        for (int np = 0; np < 5; np++) {
            int nb = r0w + np * 16 + nlane;
#pragma unroll
            for (int kc = 0; kc < 4; kc++) {
                unsigned r0, r1, r2, r3;
                ldsm4(pB + (nb * 72 + kc * 16 + klane) * 2, r0, r1, r2, r3);
                unsigned b0[2] = {r0, r1}, b1[2] = {r2, r3};
                mma_f16(bd[np * 2], av[kc], b0);
                mma_f16(bd[np * 2 + 1], av[kc], b1);
            }
        }
        {
            int r = l >> 2, col = ((l & 3) << 1);
#pragma unroll
            for (int nt = 0; nt < 10; nt++) {
                *(float2*)&scr[r * 92 + nt * 8 + col] =
                    make_float2(bd[nt][0], bd[nt][1]);
                *(float2*)&scr[(r + 8) * 92 + nt * 8 + col] =
                    make_float2(bd[nt][2], bd[nt][3]);
            }
        }
        __syncwarp();

        float sc[8][4];
#pragma unroll
        for (int nt = 0; nt < 8; nt++)
#pragma unroll
            for (int e = 0; e < 4; e++) sc[nt][e] = 0.f;
#pragma unroll
        for (int np = 0; np < 4; np++) {
            int nb = np * 16 + nlane;
#pragma unroll
            for (int kc = 0; kc < 4; kc++) {
                unsigned r0, r1, r2, r3;
                ldsm4(kB + (nb * 72 + kc * 16 + klane) * 2, r0, r1, r2, r3);
                unsigned b0[2] = {r0, r1}, b1[2] = {r2, r3};
                mma_f16(sc[np * 2], au[kc], b0);
                mma_f16(sc[np * 2 + 1], au[kc], b1);
            }
        }

        {
            int r = l >> 2;
#pragma unroll
            for (int nt = 0; nt < 8; nt++) {
                int kk = nt * 8 + ((l & 3) << 1);
                int j = kk - r + 15;
                sc[nt][0] += scr[r * 92 + j];
                sc[nt][1] += scr[r * 92 + j + 1];
                int j2 = kk - (r + 8) + 15;
                sc[nt][2] += scr[(r + 8) * 92 + j2];
                sc[nt][3] += scr[(r + 8) * 92 + j2 + 1];
            }
#pragma unroll
            for (int nt = 0; nt < 8; nt++) {
#pragma unroll
                for (int e = 0; e < 4; e++) sc[nt][e] = __expf(sc[nt][e]);
                rs_lo += sc[nt][0] + sc[nt][1];
                rs_hi += sc[nt][2] + sc[nt][3];
            }
            size_t rbase =
                ((size_t)bh * Lc + (q0 + qs + r)) * Lc + kt0 + ((l & 3) << 1);
#pragma unroll
            for (int nt = 0; nt < 8; nt++) {
                *(float2*)&attn[rbase + nt * 8] = make_float2(sc[nt][0], sc[nt][1]);
                *(float2*)&attn[rbase + 8 * Lc + nt * 8] =
                    make_float2(sc[nt][2], sc[nt][3]);
            }
        }

#pragma unroll
        for (int kc = 0; kc < 4; kc++) {
            unsigned pa[4];
            pa[0] = packh2(sc[2 * kc][0], sc[2 * kc][1]);
            pa[1] = packh2(sc[2 * kc][2], sc[2 * kc][3]);
            pa[2] = packh2(sc[2 * kc + 1][0], sc[2 * kc + 1][1]);
            pa[3] = packh2(sc[2 * kc + 1][2], sc[2 * kc + 1][3]);
            int krow = kc * 16 + tkl;
#pragma unroll
            for (int np = 0; np < 4; np++) {
                unsigned r0, r1, r2, r3;
                ldsm4t(vB + (krow * 72 + np * 16 + tnl) * 2, r0, r1, r2, r3);
                unsigned b0[2] = {r0, r1}, b1[2] = {r2, r3};
                mma_f16(ct[np * 2], pa, b0);
                mma_f16(ct[np * 2 + 1], pa, b1);
            }
        }
    }

    rs_lo += __shfl_xor_sync(0xffffffffu, rs_lo, 1);
    rs_lo += __shfl_xor_sync(0xffffffffu, rs_lo, 2);
    rs_hi += __shfl_xor_sync(0xffffffffu, rs_hi, 1);
    rs_hi += __shfl_xor_sync(0xffffffffu, rs_hi, 2);
    float inv_lo = 1.f / rs_lo, inv_hi = 1.f / rs_hi;
    int r = l >> 2;
    if ((l & 3) == 0) {
        g_inv[bh * Lc + q0 + qs + r] = inv_lo;
        g_inv[bh * Lc + q0 + qs + r + 8] = inv_hi;
    }
    size_t cbase = ((size_t)(b * Lc + q0 + qs + r)) * 512 + h * 64 + ((l & 3) << 1);
#pragma unroll
    for (int nt = 0; nt < 8; nt++) {
        unsigned hh, lo;
        pack_split(ct[nt][0] * inv_lo, ct[nt][1] * inv_lo, hh, lo);
        *(unsigned*)&g_cth[cbase + nt * 8] = hh;
        *(unsigned*)&g_ctl[cbase + nt * 8] = lo;
        pack_split(ct[nt][2] * inv_hi, ct[nt][3] * inv_hi, hh, lo);
        *(unsigned*)&g_cth[cbase + 8 * 512 + nt * 8] = hh;
        *(unsigned*)&g_ctl[cbase + 8 * 512 + nt * 8] = lo;
    }
}

// ---------------------------------------------------------------------------
extern "C" void kernel_launch(void* const* d_in, const int* in_sizes, int n_in,
                              void* d_out, int out_size) {
    const float* x    = (const float*)d_in[0];
    const float* pos  = (const float*)d_in[1];
    const float* wqkv = (const float*)d_in[2];
    const float* wpos = (const float*)d_in[3];
    const float* wout = (const float*)d_in[4];
    const float* bout = (const float*)d_in[5];
    const float* ub   = (const float*)d_in[6];
    const float* vb   = (const float*)d_in[7];
    float* out = (float*)d_out;

    int attn_in_out = ((long long)out_size >= (long long)OUT_ELEMS + ATTN_ELEMS);
    float* attn_buf = attn_in_out ? (out + OUT_ELEMS) : g_attn_scratch;

    cvt_all<<<12799, 256>>>(x, wqkv, wpos, wout, pos);

    cudaFuncSetAttribute(gemm_qkv_pos, cudaFuncAttributeMaxDynamicSharedMemorySize,
                         GSM);
    gemm_qkv_pos<<<dim3(12, 80), 256, GSM>>>();

    cudaFuncSetAttribute(attn_kernel, cudaFuncAttributeMaxDynamicSharedMemorySize,
                         SM_BYTES_A);
    attn_kernel<<<dim3(8, 64), 256, SM_BYTES_A>>>(ub, vb, attn_buf,
                                                  attn_in_out ? 0 : 1);

    cudaFuncSetAttribute(out_norm, cudaFuncAttributeMaxDynamicSharedMemorySize,
                         GSM);
    out_norm<<<2304, 256, GSM>>>(bout, out, attn_buf);
}

// round 10
// speedup vs baseline: 5.3908x; 1.1235x over previous
#include <cuda_runtime.h>
#include <cuda_bf16.h>
#include <cuda_fp16.h>
#include <math.h>

#define Lc 1024
#define Pc 2047

#define OUT_ELEMS  (8 * 1024 * 512)
#define ATTN_ELEMS (64LL * 1024 * 1024)

__device__ float g_q[(size_t)8192 * 512];
__device__ float g_attn_scratch[(size_t)ATTN_ELEMS];
// fp16 single planes for attention operands
__device__ __half g_k[(size_t)64 * 1024 * 64];   // [bh][k][64]
__device__ __half g_v[(size_t)64 * 1024 * 64];   // [bh][k][64]
__device__ __half g_p[(size_t)8 * 2048 * 64];    // [h][p][64]; row 2047 stays zero
// split-bf16 planes (hi/lo) for GEMM operands
__device__ __nv_bfloat16 g_xh[(size_t)8192 * 512],  g_xl[(size_t)8192 * 512];
__device__ __nv_bfloat16 g_psh[(size_t)2048 * 512], g_psl[(size_t)2048 * 512];
__device__ __nv_bfloat16 g_cth[(size_t)8192 * 512], g_ctl[(size_t)8192 * 512];
__device__ __nv_bfloat16 g_wqh[(size_t)1536 * 512], g_wql[(size_t)1536 * 512];
__device__ __nv_bfloat16 g_wph[(size_t)512 * 512],  g_wpl[(size_t)512 * 512];
__device__ __nv_bfloat16 g_woh[(size_t)512 * 512],  g_wol[(size_t)512 * 512];

// ------------------------- helpers -------------------------------
__device__ __forceinline__ void mma_bf16(float* c, const unsigned* a,
                                         const unsigned* b) {
    asm volatile(
        "mma.sync.aligned.m16n8k16.row.col.f32.bf16.bf16.f32 "
        "{%0,%1,%2,%3}, {%4,%5,%6,%7}, {%8,%9}, {%0,%1,%2,%3};\n"
        : "+f"(c[0]), "+f"(c[1]), "+f"(c[2]), "+f"(c[3])
        : "r"(a[0]), "r"(a[1]), "r"(a[2]), "r"(a[3]), "r"(b[0]), "r"(b[1]));
}
__device__ __forceinline__ void mma_f16(float* c, const unsigned* a,
                                        const unsigned* b) {
    asm volatile(
        "mma.sync.aligned.m16n8k16.row.col.f32.f16.f16.f32 "
        "{%0,%1,%2,%3}, {%4,%5,%6,%7}, {%8,%9}, {%0,%1,%2,%3};\n"
        : "+f"(c[0]), "+f"(c[1]), "+f"(c[2]), "+f"(c[3])
        : "r"(a[0]), "r"(a[1]), "r"(a[2]), "r"(a[3]), "r"(b[0]), "r"(b[1]));
}
__device__ __forceinline__ void ldsm4(unsigned addr, unsigned& r0, unsigned& r1,
                                      unsigned& r2, unsigned& r3) {
    asm volatile("ldmatrix.sync.aligned.m8n8.x4.shared.b16 {%0,%1,%2,%3}, [%4];"
                 : "=r"(r0), "=r"(r1), "=r"(r2), "=r"(r3) : "r"(addr));
}
__device__ __forceinline__ void ldsm4t(unsigned addr, unsigned& r0, unsigned& r1,
                                       unsigned& r2, unsigned& r3) {
    asm volatile(
        "ldmatrix.sync.aligned.m8n8.x4.trans.shared.b16 {%0,%1,%2,%3}, [%4];"
        : "=r"(r0), "=r"(r1), "=r"(r2), "=r"(r3) : "r"(addr));
}
__device__ __forceinline__ unsigned s2u(const void* p) {
    return (unsigned)__cvta_generic_to_shared(p);
}
__device__ __forceinline__ void cpa16(unsigned dst, const void* src) {
    asm volatile("cp.async.cg.shared.global [%0], [%1], 16;\n" ::"r"(dst),
                 "l"(src));
}
__device__ __forceinline__ void pack_split(float x0, float x1, unsigned& h,
                                           unsigned& l) {
    __nv_bfloat162 hb = __floats2bfloat162_rn(x0, x1);
    float2 hf = __bfloat1622float2(hb);
    __nv_bfloat162 lb = __floats2bfloat162_rn(x0 - hf.x, x1 - hf.y);
    h = *(unsigned*)&hb; l = *(unsigned*)&lb;
}
__device__ __forceinline__ unsigned packh2(float x0, float x1) {
    __half2 t = __floats2half2_rn(x0, x1);
    return *(unsigned*)&t;
}

// ---------------------------------------------------------------------------
// One-shot conversion of all fp32 operands to split-bf16 planes.
// ---------------------------------------------------------------------------
__global__ __launch_bounds__(256) void cvt_all(
    const float* __restrict__ x, const float* __restrict__ wq,
    const float* __restrict__ wp, const float* __restrict__ wo,
    const float* __restrict__ pos) {
    int bid = blockIdx.x;
    const float* src; __nv_bfloat16 *dh, *dl; int base;
    if (bid < 8192)       { src = x;   dh = g_xh;  dl = g_xl;  base = bid; }
    else if (bid < 9728)  { src = wq;  dh = g_wqh; dl = g_wql; base = bid - 8192; }
    else if (bid < 10240) { src = wp;  dh = g_wph; dl = g_wpl; base = bid - 9728; }
    else if (bid < 10752) { src = wo;  dh = g_woh; dl = g_wol; base = bid - 10240; }
    else                  { src = pos; dh = g_psh; dl = g_psl; base = bid - 10752; }
    int i = base * 256 + threadIdx.x;
    float2 v = ((const float2*)src)[i];
    unsigned h, l;
    pack_split(v.x, v.y, h, l);
    ((unsigned*)dh)[i] = h;
    ((unsigned*)dl)[i] = l;
}

// ---------------------------------------------------------------------------
// Shared GEMM mainloop (K=512, 128x128 tile, split-bf16, cp.async dbuf).
// ---------------------------------------------------------------------------
#define GT 10240
#define GSTAGE (4 * GT)
#define GSM (2 * GSTAGE)

#define GEMM_MAIN(Ah, Al, Wh, Wl, m0, n0, acc)                                  \
    {                                                                           \
        const unsigned sb = s2u(smem);                                          \
        const int lrow = tid >> 2, lc = (tid & 3) << 3;                         \
        auto issue = [&](int k0, int bb) {                                      \
            unsigned base = sb + bb * GSTAGE;                                   \
            _Pragma("unroll") for (int t = 0; t < 2; t++) {                     \
                int row = lrow + t * 64;                                        \
                unsigned so = (unsigned)row * 80 + ((unsigned)lc << 1);         \
                size_t ao = (size_t)(m0 + row) * 512 + k0 + lc;                 \
                size_t wo_ = (size_t)(n0 + row) * 512 + k0 + lc;                \
                cpa16(base + so, Ah + ao);                                      \
                cpa16(base + GT + so, Al + ao);                                 \
                cpa16(base + 2 * GT + so, Wh + wo_);                            \
                cpa16(base + 3 * GT + so, Wl + wo_);                            \
            }                                                                   \
            asm volatile("cp.async.commit_group;\n" ::: "memory");              \
        };                                                                      \
        issue(0, 0);                                                            \
        for (int s = 0; s < 16; s++) {                                          \
            const int bb = s & 1;                                               \
            __syncthreads();                                                    \
            if (s < 15) {                                                       \
                issue((s + 1) << 5, bb ^ 1);                                    \
                asm volatile("cp.async.wait_group 1;\n" ::: "memory");          \
            } else {                                                            \
                asm volatile("cp.async.wait_group 0;\n" ::: "memory");          \
            }                                                                   \
            __syncthreads();                                                    \
            unsigned base = sb + bb * GSTAGE;                                   \
            _Pragma("unroll") for (int kc = 0; kc < 2; kc++) {                  \
                const int kk = kc << 4;                                         \
                unsigned ah[4][4], al[4][4], bh[4][2], bl[4][2];                \
                _Pragma("unroll") for (int mt = 0; mt < 4; mt++) {              \
                    unsigned off = ((aRow + mt * 16) * 40 + kk + aCol) * 2;     \
                    ldsm4(base + off, ah[mt][0], ah[mt][1], ah[mt][2],          \
                          ah[mt][3]);                                           \
                    ldsm4(base + GT + off, al[mt][0], al[mt][1], al[mt][2],     \
                          al[mt][3]);                                           \
                }                                                               \
                _Pragma("unroll") for (int np = 0; np < 2; np++) {              \
                    unsigned off = ((bRow + np * 16) * 40 + kk + bCol) * 2;     \
                    unsigned r0, r1, r2, r3;                                    \
                    ldsm4(base + 2 * GT + off, r0, r1, r2, r3);                 \
                    bh[np * 2][0] = r0; bh[np * 2][1] = r1;                     \
                    bh[np * 2 + 1][0] = r2; bh[np * 2 + 1][1] = r3;             \
                    ldsm4(base + 3 * GT + off, r0, r1, r2, r3);                 \
                    bl[np * 2][0] = r0; bl[np * 2][1] = r1;                     \
                    bl[np * 2 + 1][0] = r2; bl[np * 2 + 1][1] = r3;             \
                }                                                               \
                _Pragma("unroll") for (int mt = 0; mt < 4; mt++)                \
                    _Pragma("unroll") for (int nt = 0; nt < 4; nt++) {          \
                        mma_bf16(acc[mt][nt], ah[mt], bh[nt]);                  \
                        mma_bf16(acc[mt][nt], al[mt], bh[nt]);                  \
                        mma_bf16(acc[mt][nt], ah[mt], bl[nt]);                  \
                    }                                                           \
            }                                                                   \
        }                                                                       \
    }

// ---------------------------------------------------------------------------
// Fused qkv-proj + pos-proj GEMM. Grid (12, 80).
// ---------------------------------------------------------------------------
__global__ __launch_bounds__(256, 1) void gemm_qkv_pos() {
    extern __shared__ char smem[];
    const int tid = threadIdx.x, l = tid & 31, w = tid >> 5;
    const int wm = w >> 2, wn = w & 3;
    const int aRow = wm * 64 + (l & 15);
    const int aCol = (l & 16) >> 1;
    const int bRow = wn * 32 + (l & 7) + ((l & 16) >> 1);
    const int bCol = l & 8;

    const int bx = blockIdx.x, by = blockIdx.y;
    const __nv_bfloat16 *Ah, *Al, *Wh, *Wl;
    int m0, n0, mode;
    if (by < 64) {
        Ah = g_xh; Al = g_xl; Wh = g_wqh; Wl = g_wql;
        m0 = by << 7; n0 = bx << 7; mode = 1;
    } else {
        if (bx >= 4) return;
        Ah = g_psh; Al = g_psl; Wh = g_wph; Wl = g_wpl;
        m0 = (by - 64) << 7; n0 = bx << 7; mode = 2;
    }

    float acc[4][4][4];
#pragma unroll
    for (int i = 0; i < 4; i++)
#pragma unroll
        for (int j = 0; j < 4; j++)
#pragma unroll
            for (int e = 0; e < 4; e++) acc[i][j][e] = 0.f;

    GEMM_MAIN(Ah, Al, Wh, Wl, m0, n0, acc);

    const int er = m0 + wm * 64 + (l >> 2);
    const int ec = n0 + wn * 32 + ((l & 3) << 1);
#pragma unroll
    for (int mt = 0; mt < 4; mt++) {
#pragma unroll
        for (int nt = 0; nt < 4; nt++) {
            int col = ec + nt * 8;
#pragma unroll
            for (int half = 0; half < 2; half++) {
                int r = er + mt * 16 + half * 8;
                float a0 = acc[mt][nt][half * 2];
                float a1 = acc[mt][nt][half * 2 + 1];
                if (mode == 1) {
                    int hh_ = col / 192;
                    int rem = col - hh_ * 192;
                    int part = rem >> 6, d = rem & 63;
                    if (part == 0) {
                        *(float2*)&g_q[(size_t)r * 512 + hh_ * 64 + d] =
                            make_float2(a0, a1);
                    } else {
                        int b = r >> 10, ll2 = r & 1023;
                        size_t idx =
                            (((size_t)(b * 8 + hh_)) * 1024 + ll2) * 64 + d;
                        __half2 hv = __floats2half2_rn(a0, a1);
                        if (part == 1) *(__half2*)&g_k[idx] = hv;
                        else           *(__half2*)&g_v[idx] = hv;
                    }
                } else {
                    int hh_ = col >> 6, d = col & 63;
                    size_t idx = (((size_t)hh_) * 2048 + r) * 64 + d;
                    *(__half2*)&g_p[idx] = __floats2half2_rn(a0, a1);
                }
            }
        }
    }
}

// ---------------------------------------------------------------------------
// Standalone out-proj GEMM: out = ctx @ wout^T + bias. Grid (4, 64).
// ---------------------------------------------------------------------------
__global__ __launch_bounds__(256, 1) void gemm_out(
    const float* __restrict__ bias, float* __restrict__ C_ext) {
    extern __shared__ char smem[];
    const int tid = threadIdx.x, l = tid & 31, w = tid >> 5;
    const int wm = w >> 2, wn = w & 3;
    const int aRow = wm * 64 + (l & 15);
    const int aCol = (l & 16) >> 1;
    const int bRow = wn * 32 + (l & 7) + ((l & 16) >> 1);
    const int bCol = l & 8;
    const int m0 = blockIdx.y << 7, n0 = blockIdx.x << 7;

    float acc[4][4][4];
#pragma unroll
    for (int i = 0; i < 4; i++)
#pragma unroll
        for (int j = 0; j < 4; j++)
#pragma unroll
            for (int e = 0; e < 4; e++) acc[i][j][e] = 0.f;

    GEMM_MAIN(g_cth, g_ctl, g_woh, g_wol, m0, n0, acc);

    const int er = m0 + wm * 64 + (l >> 2);
    const int ec = n0 + wn * 32 + ((l & 3) << 1);
#pragma unroll
    for (int mt = 0; mt < 4; mt++) {
#pragma unroll
        for (int nt = 0; nt < 4; nt++) {
            int col = ec + nt * 8;
            float2 bb2 = *(const float2*)&bias[col];
#pragma unroll
            for (int half = 0; half < 2; half++) {
                int r = er + mt * 16 + half * 8;
                *(float2*)&C_ext[(size_t)r * 512 + col] =
                    make_float2(acc[mt][nt][half * 2] + bb2.x,
                                acc[mt][nt][half * 2 + 1] + bb2.y);
            }
        }
    }
}

// ---------------------------------------------------------------------------
// Fused attention + in-kernel normalization (L2-resident rescale).
// Grid (8, 64), 256 threads.
// ---------------------------------------------------------------------------
#define AQU 0
#define AQV 18432
#define AK0 36864
#define AV0 55296
#define AP0 73728
#define ASCR 129024
#define AINV (129024 + 47104)          /* fresh 512B region for row inverses */
#define SM_BYTES_A (AINV + 512)

__global__ __launch_bounds__(256, 1) void attn_kernel(
    const float* __restrict__ ubias, const float* __restrict__ vbias,
    float* __restrict__ attn) {
    extern __shared__ char smem[];

    __half* QU = (__half*)(smem + AQU);
    __half* QV = (__half*)(smem + AQV);

    const int tid = threadIdx.x, l = tid & 31, w = tid >> 5;
    const int bh = blockIdx.y, b = bh >> 3, h = bh & 7;
    const int q0 = blockIdx.x << 7;
    const int qs = w << 4;
    const float scale = 0.04419417382415922f;  // 1/sqrt(512)

    const unsigned kB0 = s2u(smem + AK0);
    const unsigned vB0 = s2u(smem + AV0);
    const unsigned pB0 = s2u(smem + AP0);
    float* scr = (float*)(smem + ASCR) + w * 16 * 92;

    auto issue_tile = [&](int kt0, int bb) {
        size_t gb = (((size_t)bh) * 1024 + kt0) * 64;
        const uint4* GK = (const uint4*)(g_k + gb);
        const uint4* GV = (const uint4*)(g_v + gb);
        int pbase = kt0 - q0 + 896;
        const uint4* GP = (const uint4*)(g_p + (((size_t)h) * 2048 + pbase) * 64);
        unsigned kb = kB0 + bb * 9216;
        unsigned vb = vB0 + bb * 9216;
        unsigned pb = pB0 + bb * 27648;
#pragma unroll
        for (int t = 0; t < 2; t++) {
            int i = tid + t * 256;
            unsigned so = (unsigned)((i >> 3) * 9 + (i & 7)) * 16;
            cpa16(kb + so, GK + i);
            cpa16(vb + so, GV + i);
        }
#pragma unroll
        for (int t = 0; t < 6; t++) {
            int i = tid + t * 256;
            unsigned so = (unsigned)((i >> 3) * 9 + (i & 7)) * 16;
            cpa16(pb + so, GP + i);
        }
        asm volatile("cp.async.commit_group;\n" ::: "memory");
    };

    issue_tile(0, 0);

    for (int idx = tid; idx < 4096; idx += 256) {
        int qi = idx >> 5, d2 = (idx & 31) << 1;
        float2 qv =
            *(const float2*)&g_q[((size_t)(b * Lc + q0 + qi)) * 512 + h * 64 + d2];
        *(unsigned*)&QU[qi * 72 + d2] =
            packh2((qv.x + ubias[h * 64 + d2]) * scale,
                   (qv.y + ubias[h * 64 + d2 + 1]) * scale);
        *(unsigned*)&QV[qi * 72 + d2] =
            packh2((qv.x + vbias[h * 64 + d2]) * scale,
                   (qv.y + vbias[h * 64 + d2 + 1]) * scale);
    }
    __syncthreads();

    unsigned au[4][4], av[4][4];
    {
        unsigned baseU = s2u(QU), baseV = s2u(QV);
        int row = qs + (l & 15), colp = (l & 16) >> 1;
#pragma unroll
        for (int kc = 0; kc < 4; kc++) {
            unsigned off = (row * 72 + kc * 16 + colp) * 2;
            ldsm4(baseU + off, au[kc][0], au[kc][1], au[kc][2], au[kc][3]);
            ldsm4(baseV + off, av[kc][0], av[kc][1], av[kc][2], av[kc][3]);
        }
    }

    float ct[8][4];
#pragma unroll
    for (int nt = 0; nt < 8; nt++)
#pragma unroll
        for (int e = 0; e < 4; e++) ct[nt][e] = 0.f;
    float rs_lo = 0.f, rs_hi = 0.f;

    const int nlane = (l & 7) + ((l & 16) >> 1);
    const int klane = l & 8;
    const int tkl = (l & 7) + (l & 8);
    const int tnl = (l & 16) >> 1;
    const int r0w = 112 - qs;

    for (int kt = 0; kt < 16; kt++) {
        const int bb = kt & 1;
        const int kt0 = kt << 6;
        __syncthreads();
        if (kt < 15) {
            issue_tile(kt0 + 64, bb ^ 1);
            asm volatile("cp.async.wait_group 1;\n" ::: "memory");
        } else {
            asm volatile("cp.async.wait_group 0;\n" ::: "memory");
        }
        __syncthreads();

        const unsigned kB = kB0 + bb * 9216;
        const unsigned vB = vB0 + bb * 9216;
        const unsigned pB = pB0 + bb * 27648;

        float bd[10][4];
#pragma unroll
        for (int nt = 0; nt < 10; nt++)
#pragma unroll
            for (int e = 0; e < 4; e++) bd[nt][e] = 0.f;
#pragma unroll
        for (int np = 0; np < 5; np++) {
            int nb = r0w + np * 16 + nlane;
#pragma unroll
            for (int kc = 0; kc < 4; kc++) {
                unsigned r0, r1, r2, r3;
                ldsm4(pB + (nb * 72 + kc * 16 + klane) * 2, r0, r1, r2, r3);
                unsigned b0[2] = {r0, r1}, b1[2] = {r2, r3};
                mma_f16(bd[np * 2], av[kc], b0);
                mma_f16(bd[np * 2 + 1], av[kc], b1);
            }
        }
        {
            int r = l >> 2, col = ((l & 3) << 1);
#pragma unroll
            for (int nt = 0; nt < 10; nt++) {
                *(float2*)&scr[r * 92 + nt * 8 + col] =
                    make_float2(bd[nt][0], bd[nt][1]);
                *(float2*)&scr[(r + 8) * 92 + nt * 8 + col] =
                    make_float2(bd[nt][2], bd[nt][3]);
            }
        }
        __syncwarp();

        float sc[8][4];
#pragma unroll
        for (int nt = 0; nt < 8; nt++)
#pragma unroll
            for (int e = 0; e < 4; e++) sc[nt][e] = 0.f;
#pragma unroll
        for (int np = 0; np < 4; np++) {
            int nb = np * 16 + nlane;
#pragma unroll
            for (int kc = 0; kc < 4; kc++) {
                unsigned r0, r1, r2, r3;
                ldsm4(kB + (nb * 72 + kc * 16 + klane) * 2, r0, r1, r2, r3);
                unsigned b0[2] = {r0, r1}, b1[2] = {r2, r3};
                mma_f16(sc[np * 2], au[kc], b0);
                mma_f16(sc[np * 2 + 1], au[kc], b1);
            }
        }

        {
            int r = l >> 2;
#pragma unroll
            for (int nt = 0; nt < 8; nt++) {
                int kk = nt * 8 + ((l & 3) << 1);
                int j = kk - r + 15;
                sc[nt][0] += scr[r * 92 + j];
                sc[nt][1] += scr[r * 92 + j + 1];
                int j2 = kk - (r + 8) + 15;
                sc[nt][2] += scr[(r + 8) * 92 + j2];
                sc[nt][3] += scr[(r + 8) * 92 + j2 + 1];
            }
#pragma unroll
            for (int nt = 0; nt < 8; nt++) {
#pragma unroll
                for (int e = 0; e < 4; e++) sc[nt][e] = __expf(sc[nt][e]);
                rs_lo += sc[nt][0] + sc[nt][1];
                rs_hi += sc[nt][2] + sc[nt][3];
            }
            size_t rbase =
                ((size_t)bh * Lc + (q0 + qs + r)) * Lc + kt0 + ((l & 3) << 1);
#pragma unroll
            for (int nt = 0; nt < 8; nt++) {
                *(float2*)&attn[rbase + nt * 8] = make_float2(sc[nt][0], sc[nt][1]);
                *(float2*)&attn[rbase + 8 * Lc + nt * 8] =
                    make_float2(sc[nt][2], sc[nt][3]);
            }
        }

#pragma unroll
        for (int kc = 0; kc < 4; kc++) {
            unsigned pa[4];
            pa[0] = packh2(sc[2 * kc][0], sc[2 * kc][1]);
            pa[1] = packh2(sc[2 * kc][2], sc[2 * kc][3]);
            pa[2] = packh2(sc[2 * kc + 1][0], sc[2 * kc + 1][1]);
            pa[3] = packh2(sc[2 * kc + 1][2], sc[2 * kc + 1][3]);
            int krow = kc * 16 + tkl;
#pragma unroll
            for (int np = 0; np < 4; np++) {
                unsigned r0, r1, r2, r3;
                ldsm4t(vB + (krow * 72 + np * 16 + tnl) * 2, r0, r1, r2, r3);
                unsigned b0[2] = {r0, r1}, b1[2] = {r2, r3};
                mma_f16(ct[np * 2], pa, b0);
                mma_f16(ct[np * 2 + 1], pa, b1);
            }
        }
    }

    // ---- rowsum reduce; broadcast inverses; store ctx planes ----
    rs_lo += __shfl_xor_sync(0xffffffffu, rs_lo, 1);
    rs_lo += __shfl_xor_sync(0xffffffffu, rs_lo, 2);
    rs_hi += __shfl_xor_sync(0xffffffffu, rs_hi, 1);
    rs_hi += __shfl_xor_sync(0xffffffffu, rs_hi, 2);
    float inv_lo = 1.f / rs_lo, inv_hi = 1.f / rs_hi;
    float* INV = (float*)(smem + AINV);
    int r = l >> 2;
    if ((l & 3) == 0) {
        INV[qs + r] = inv_lo;
        INV[qs + r + 8] = inv_hi;
    }
    size_t cbase = ((size_t)(b * Lc + q0 + qs + r)) * 512 + h * 64 + ((l & 3) << 1);
#pragma unroll
    for (int nt = 0; nt < 8; nt++) {
        unsigned hh, lo;
        pack_split(ct[nt][0] * inv_lo, ct[nt][1] * inv_lo, hh, lo);
        *(unsigned*)&g_cth[cbase + nt * 8] = hh;
        *(unsigned*)&g_ctl[cbase + nt * 8] = lo;
        pack_split(ct[nt][2] * inv_hi, ct[nt][3] * inv_hi, hh, lo);
        *(unsigned*)&g_cth[cbase + 8 * 512 + nt * 8] = hh;
        *(unsigned*)&g_ctl[cbase + 8 * 512 + nt * 8] = lo;
    }

    // ---- in-kernel normalization: rescale this CTA's 128x1024 block.
    // Lines are still dirty in L2 (resident set ~74MB < 126MB L2), so the
    // re-read is L2-fed and unnormalized values never reach DRAM.
    __syncthreads();
    float4* A4 = (float4*)(attn + ((size_t)bh * Lc + q0) * Lc);
#pragma unroll
    for (int it = 0; it < 16; it++) {
        int id[8]; float4 v[8]; float iv[8];
#pragma unroll
        for (int j = 0; j < 8; j++) {
            id[j] = tid + (it * 8 + j) * 256;
            v[j] = A4[id[j]];
        }
#pragma unroll
        for (int j = 0; j < 8; j++) iv[j] = INV[id[j] >> 8];
#pragma unroll
        for (int j = 0; j < 8; j++) {
            v[j].x *= iv[j]; v[j].y *= iv[j]; v[j].z *= iv[j]; v[j].w *= iv[j];
            A4[id[j]] = v[j];
        }
    }
}

// ---------------------------------------------------------------------------
extern "C" void kernel_launch(void* const* d_in, const int* in_sizes, int n_in,
                              void* d_out, int out_size) {
    const float* x    = (const float*)d_in[0];
    const float* pos  = (const float*)d_in[1];
    const float* wqkv = (const float*)d_in[2];
    const float* wpos = (const float*)d_in[3];
    const float* wout = (const float*)d_in[4];
    const float* bout = (const float*)d_in[5];
    const float* ub   = (const float*)d_in[6];
    const float* vb   = (const float*)d_in[7];
    float* out = (float*)d_out;

    int attn_in_out = ((long long)out_size >= (long long)OUT_ELEMS + ATTN_ELEMS);
    float* attn_buf = attn_in_out ? (out + OUT_ELEMS) : g_attn_scratch;

    cvt_all<<<12799, 256>>>(x, wqkv, wpos, wout, pos);

    cudaFuncSetAttribute(gemm_qkv_pos, cudaFuncAttributeMaxDynamicSharedMemorySize,
                         GSM);
    gemm_qkv_pos<<<dim3(12, 80), 256, GSM>>>();

    cudaFuncSetAttribute(attn_kernel, cudaFuncAttributeMaxDynamicSharedMemorySize,
                         SM_BYTES_A);
    attn_kernel<<<dim3(8, 64), 256, SM_BYTES_A>>>(ub, vb, attn_buf);

    cudaFuncSetAttribute(gemm_out, cudaFuncAttributeMaxDynamicSharedMemorySize,
                         GSM);
    gemm_out<<<dim3(4, 64), 256, GSM>>>(bout, out);
}

// round 11
// speedup vs baseline: 5.8130x; 1.0783x over previous
#include <cuda_runtime.h>
#include <cuda_bf16.h>
#include <cuda_fp16.h>
#include <math.h>

#define Lc 1024
#define Pc 2047

#define OUT_ELEMS  (8 * 1024 * 512)
#define ATTN_ELEMS (64LL * 1024 * 1024)

__device__ float g_q[(size_t)8192 * 512];
__device__ float g_attn_scratch[(size_t)ATTN_ELEMS];
// fp16 single planes for attention operands
__device__ __half g_k[(size_t)64 * 1024 * 64];   // [bh][k][64]
__device__ __half g_v[(size_t)64 * 1024 * 64];   // [bh][k][64]
__device__ __half g_p[(size_t)8 * 2048 * 64];    // [h][p][64]; row 2047 stays zero
// split-bf16 planes (hi/lo) for GEMM operands
__device__ __nv_bfloat16 g_xh[(size_t)8192 * 512],  g_xl[(size_t)8192 * 512];
__device__ __nv_bfloat16 g_psh[(size_t)2048 * 512], g_psl[(size_t)2048 * 512];
__device__ __nv_bfloat16 g_cth[(size_t)8192 * 512], g_ctl[(size_t)8192 * 512];
__device__ __nv_bfloat16 g_wqh[(size_t)1536 * 512], g_wql[(size_t)1536 * 512];
__device__ __nv_bfloat16 g_wph[(size_t)512 * 512],  g_wpl[(size_t)512 * 512];
__device__ __nv_bfloat16 g_woh[(size_t)512 * 512],  g_wol[(size_t)512 * 512];

// ------------------------- helpers -------------------------------
__device__ __forceinline__ void mma_bf16(float* c, const unsigned* a,
                                         const unsigned* b) {
    asm volatile(
        "mma.sync.aligned.m16n8k16.row.col.f32.bf16.bf16.f32 "
        "{%0,%1,%2,%3}, {%4,%5,%6,%7}, {%8,%9}, {%0,%1,%2,%3};\n"
        : "+f"(c[0]), "+f"(c[1]), "+f"(c[2]), "+f"(c[3])
        : "r"(a[0]), "r"(a[1]), "r"(a[2]), "r"(a[3]), "r"(b[0]), "r"(b[1]));
}
__device__ __forceinline__ void mma_f16(float* c, const unsigned* a,
                                        const unsigned* b) {
    asm volatile(
        "mma.sync.aligned.m16n8k16.row.col.f32.f16.f16.f32 "
        "{%0,%1,%2,%3}, {%4,%5,%6,%7}, {%8,%9}, {%0,%1,%2,%3};\n"
        : "+f"(c[0]), "+f"(c[1]), "+f"(c[2]), "+f"(c[3])
        : "r"(a[0]), "r"(a[1]), "r"(a[2]), "r"(a[3]), "r"(b[0]), "r"(b[1]));
}
__device__ __forceinline__ void ldsm4(unsigned addr, unsigned& r0, unsigned& r1,
                                      unsigned& r2, unsigned& r3) {
    asm volatile("ldmatrix.sync.aligned.m8n8.x4.shared.b16 {%0,%1,%2,%3}, [%4];"
                 : "=r"(r0), "=r"(r1), "=r"(r2), "=r"(r3) : "r"(addr));
}
__device__ __forceinline__ void ldsm4t(unsigned addr, unsigned& r0, unsigned& r1,
                                       unsigned& r2, unsigned& r3) {
    asm volatile(
        "ldmatrix.sync.aligned.m8n8.x4.trans.shared.b16 {%0,%1,%2,%3}, [%4];"
        : "=r"(r0), "=r"(r1), "=r"(r2), "=r"(r3) : "r"(addr));
}
__device__ __forceinline__ unsigned s2u(const void* p) {
    return (unsigned)__cvta_generic_to_shared(p);
}
__device__ __forceinline__ void cpa16(unsigned dst, const void* src) {
    asm volatile("cp.async.cg.shared.global [%0], [%1], 16;\n" ::"r"(dst),
                 "l"(src));
}
__device__ __forceinline__ void pack_split(float x0, float x1, unsigned& h,
                                           unsigned& l) {
    __nv_bfloat162 hb = __floats2bfloat162_rn(x0, x1);
    float2 hf = __bfloat1622float2(hb);
    __nv_bfloat162 lb = __floats2bfloat162_rn(x0 - hf.x, x1 - hf.y);
    h = *(unsigned*)&hb; l = *(unsigned*)&lb;
}
__device__ __forceinline__ unsigned packh2(float x0, float x1) {
    __half2 t = __floats2half2_rn(x0, x1);
    return *(unsigned*)&t;
}

// ---------------------------------------------------------------------------
// One-shot conversion of all fp32 operands to split-bf16 planes.
// ---------------------------------------------------------------------------
__global__ __launch_bounds__(256) void cvt_all(
    const float* __restrict__ x, const float* __restrict__ wq,
    const float* __restrict__ wp, const float* __restrict__ wo,
    const float* __restrict__ pos) {
    int bid = blockIdx.x;
    const float* src; __nv_bfloat16 *dh, *dl; int base;
    if (bid < 8192)       { src = x;   dh = g_xh;  dl = g_xl;  base = bid; }
    else if (bid < 9728)  { src = wq;  dh = g_wqh; dl = g_wql; base = bid - 8192; }
    else if (bid < 10240) { src = wp;  dh = g_wph; dl = g_wpl; base = bid - 9728; }
    else if (bid < 10752) { src = wo;  dh = g_woh; dl = g_wol; base = bid - 10240; }
    else                  { src = pos; dh = g_psh; dl = g_psl; base = bid - 10752; }
    int i = base * 256 + threadIdx.x;
    float2 v = ((const float2*)src)[i];
    unsigned h, l;
    pack_split(v.x, v.y, h, l);
    ((unsigned*)dh)[i] = h;
    ((unsigned*)dl)[i] = l;
}

// ---------------------------------------------------------------------------
// Shared GEMM mainloop (K=512, 128x128 tile, split-bf16, cp.async dbuf).
// ---------------------------------------------------------------------------
#define GT 10240
#define GSTAGE (4 * GT)
#define GSM (2 * GSTAGE)

#define GEMM_MAIN(Ah, Al, Wh, Wl, m0, n0, acc)                                  \
    {                                                                           \
        const unsigned sb = s2u(smem);                                          \
        const int lrow = tid >> 2, lc = (tid & 3) << 3;                         \
        auto issue = [&](int k0, int bb) {                                      \
            unsigned base = sb + bb * GSTAGE;                                   \
            _Pragma("unroll") for (int t = 0; t < 2; t++) {                     \
                int row = lrow + t * 64;                                        \
                unsigned so = (unsigned)row * 80 + ((unsigned)lc << 1);         \
                size_t ao = (size_t)(m0 + row) * 512 + k0 + lc;                 \
                size_t wo_ = (size_t)(n0 + row) * 512 + k0 + lc;                \
                cpa16(base + so, Ah + ao);                                      \
                cpa16(base + GT + so, Al + ao);                                 \
                cpa16(base + 2 * GT + so, Wh + wo_);                            \
                cpa16(base + 3 * GT + so, Wl + wo_);                            \
            }                                                                   \
            asm volatile("cp.async.commit_group;\n" ::: "memory");              \
        };                                                                      \
        issue(0, 0);                                                            \
        for (int s = 0; s < 16; s++) {                                          \
            const int bb = s & 1;                                               \
            __syncthreads();                                                    \
            if (s < 15) {                                                       \
                issue((s + 1) << 5, bb ^ 1);                                    \
                asm volatile("cp.async.wait_group 1;\n" ::: "memory");          \
            } else {                                                            \
                asm volatile("cp.async.wait_group 0;\n" ::: "memory");          \
            }                                                                   \
            __syncthreads();                                                    \
            unsigned base = sb + bb * GSTAGE;                                   \
            _Pragma("unroll") for (int kc = 0; kc < 2; kc++) {                  \
                const int kk = kc << 4;                                         \
                unsigned ah[4][4], al[4][4], bh[4][2], bl[4][2];                \
                _Pragma("unroll") for (int mt = 0; mt < 4; mt++) {              \
                    unsigned off = ((aRow + mt * 16) * 40 + kk + aCol) * 2;     \
                    ldsm4(base + off, ah[mt][0], ah[mt][1], ah[mt][2],          \
                          ah[mt][3]);                                           \
                    ldsm4(base + GT + off, al[mt][0], al[mt][1], al[mt][2],     \
                          al[mt][3]);                                           \
                }                                                               \
                _Pragma("unroll") for (int np = 0; np < 2; np++) {              \
                    unsigned off = ((bRow + np * 16) * 40 + kk + bCol) * 2;     \
                    unsigned r0, r1, r2, r3;                                    \
                    ldsm4(base + 2 * GT + off, r0, r1, r2, r3);                 \
                    bh[np * 2][0] = r0; bh[np * 2][1] = r1;                     \
                    bh[np * 2 + 1][0] = r2; bh[np * 2 + 1][1] = r3;             \
                    ldsm4(base + 3 * GT + off, r0, r1, r2, r3);                 \
                    bl[np * 2][0] = r0; bl[np * 2][1] = r1;                     \
                    bl[np * 2 + 1][0] = r2; bl[np * 2 + 1][1] = r3;             \
                }                                                               \
                _Pragma("unroll") for (int mt = 0; mt < 4; mt++)                \
                    _Pragma("unroll") for (int nt = 0; nt < 4; nt++) {          \
                        mma_bf16(acc[mt][nt], ah[mt], bh[nt]);                  \
                        mma_bf16(acc[mt][nt], al[mt], bh[nt]);                  \
                        mma_bf16(acc[mt][nt], ah[mt], bl[nt]);                  \
                    }                                                           \
            }                                                                   \
        }                                                                       \
    }

// ---------------------------------------------------------------------------
// Fused qkv-proj + pos-proj GEMM. 1-D grid, 832 blocks exactly:
//   bid < 768 : proj tile (m0=(bid/12)*128, n0=(bid%12)*128) -> qkv epilogue
//   bid >= 768: pos tile  (t=bid-768; m0=(t>>2)*128, n0=(t&3)*128) -> pos epi
// 2 CTAs/SM (regs capped at 128, 2x80KB smem).
// ---------------------------------------------------------------------------
__global__ __launch_bounds__(256, 2) void gemm_qkv_pos() {
    extern __shared__ char smem[];
    const int tid = threadIdx.x, l = tid & 31, w = tid >> 5;
    const int wm = w >> 2, wn = w & 3;
    const int aRow = wm * 64 + (l & 15);
    const int aCol = (l & 16) >> 1;
    const int bRow = wn * 32 + (l & 7) + ((l & 16) >> 1);
    const int bCol = l & 8;

    const int bid = blockIdx.x;
    const __nv_bfloat16 *Ah, *Al, *Wh, *Wl;
    int m0, n0, mode;
    if (bid < 768) {
        Ah = g_xh; Al = g_xl; Wh = g_wqh; Wl = g_wql;
        m0 = (bid / 12) << 7; n0 = (bid % 12) << 7; mode = 1;
    } else {
        int t = bid - 768;
        Ah = g_psh; Al = g_psl; Wh = g_wph; Wl = g_wpl;
        m0 = (t >> 2) << 7; n0 = (t & 3) << 7; mode = 2;
    }

    float acc[4][4][4];
#pragma unroll
    for (int i = 0; i < 4; i++)
#pragma unroll
        for (int j = 0; j < 4; j++)
#pragma unroll
            for (int e = 0; e < 4; e++) acc[i][j][e] = 0.f;

    GEMM_MAIN(Ah, Al, Wh, Wl, m0, n0, acc);

    const int er = m0 + wm * 64 + (l >> 2);
    const int ec = n0 + wn * 32 + ((l & 3) << 1);
#pragma unroll
    for (int mt = 0; mt < 4; mt++) {
#pragma unroll
        for (int nt = 0; nt < 4; nt++) {
            int col = ec + nt * 8;
#pragma unroll
            for (int half = 0; half < 2; half++) {
                int r = er + mt * 16 + half * 8;
                float a0 = acc[mt][nt][half * 2];
                float a1 = acc[mt][nt][half * 2 + 1];
                if (mode == 1) {
                    int hh_ = col / 192;
                    int rem = col - hh_ * 192;
                    int part = rem >> 6, d = rem & 63;
                    if (part == 0) {
                        *(float2*)&g_q[(size_t)r * 512 + hh_ * 64 + d] =
                            make_float2(a0, a1);
                    } else {
                        int b = r >> 10, ll2 = r & 1023;
                        size_t idx =
                            (((size_t)(b * 8 + hh_)) * 1024 + ll2) * 64 + d;
                        __half2 hv = __floats2half2_rn(a0, a1);
                        if (part == 1) *(__half2*)&g_k[idx] = hv;
                        else           *(__half2*)&g_v[idx] = hv;
                    }
                } else {
                    int hh_ = col >> 6, d = col & 63;
                    size_t idx = (((size_t)hh_) * 2048 + r) * 64 + d;
                    *(__half2*)&g_p[idx] = __floats2half2_rn(a0, a1);
                }
            }
        }
    }
}

// ---------------------------------------------------------------------------
// Standalone out-proj GEMM: out = ctx @ wout^T + bias. Grid (4, 64), 2 CTA/SM.
// ---------------------------------------------------------------------------
__global__ __launch_bounds__(256, 2) void gemm_out(
    const float* __restrict__ bias, float* __restrict__ C_ext) {
    extern __shared__ char smem[];
    const int tid = threadIdx.x, l = tid & 31, w = tid >> 5;
    const int wm = w >> 2, wn = w & 3;
    const int aRow = wm * 64 + (l & 15);
    const int aCol = (l & 16) >> 1;
    const int bRow = wn * 32 + (l & 7) + ((l & 16) >> 1);
    const int bCol = l & 8;
    const int m0 = blockIdx.y << 7, n0 = blockIdx.x << 7;

    float acc[4][4][4];
#pragma unroll
    for (int i = 0; i < 4; i++)
#pragma unroll
        for (int j = 0; j < 4; j++)
#pragma unroll
            for (int e = 0; e < 4; e++) acc[i][j][e] = 0.f;

    GEMM_MAIN(g_cth, g_ctl, g_woh, g_wol, m0, n0, acc);

    const int er = m0 + wm * 64 + (l >> 2);
    const int ec = n0 + wn * 32 + ((l & 3) << 1);
#pragma unroll
    for (int mt = 0; mt < 4; mt++) {
#pragma unroll
        for (int nt = 0; nt < 4; nt++) {
            int col = ec + nt * 8;
            float2 bb2 = *(const float2*)&bias[col];
#pragma unroll
            for (int half = 0; half < 2; half++) {
                int r = er + mt * 16 + half * 8;
                *(float2*)&C_ext[(size_t)r * 512 + col] =
                    make_float2(acc[mt][nt][half * 2] + bb2.x,
                                acc[mt][nt][half * 2 + 1] + bb2.y);
            }
        }
    }
}

// ---------------------------------------------------------------------------
// Fused attention + in-kernel normalization (L2-resident rescale).
// Grid (8, 64), 256 threads.
// ---------------------------------------------------------------------------
#define AQU 0
#define AQV 18432
#define AK0 36864
#define AV0 55296
#define AP0 73728
#define ASCR 129024
#define AINV (129024 + 47104)
#define SM_BYTES_A (AINV + 512)

__global__ __launch_bounds__(256, 1) void attn_kernel(
    const float* __restrict__ ubias, const float* __restrict__ vbias,
    float* __restrict__ attn) {
    extern __shared__ char smem[];

    __half* QU = (__half*)(smem + AQU);
    __half* QV = (__half*)(smem + AQV);

    const int tid = threadIdx.x, l = tid & 31, w = tid >> 5;
    const int bh = blockIdx.y, b = bh >> 3, h = bh & 7;
    const int q0 = blockIdx.x << 7;
    const int qs = w << 4;
    const float scale = 0.04419417382415922f;  // 1/sqrt(512)

    const unsigned kB0 = s2u(smem + AK0);
    const unsigned vB0 = s2u(smem + AV0);
    const unsigned pB0 = s2u(smem + AP0);
    float* scr = (float*)(smem + ASCR) + w * 16 * 92;

    auto issue_tile = [&](int kt0, int bb) {
        size_t gb = (((size_t)bh) * 1024 + kt0) * 64;
        const uint4* GK = (const uint4*)(g_k + gb);
        const uint4* GV = (const uint4*)(g_v + gb);
        int pbase = kt0 - q0 + 896;
        const uint4* GP = (const uint4*)(g_p + (((size_t)h) * 2048 + pbase) * 64);
        unsigned kb = kB0 + bb * 9216;
        unsigned vb = vB0 + bb * 9216;
        unsigned pb = pB0 + bb * 27648;
#pragma unroll
        for (int t = 0; t < 2; t++) {
            int i = tid + t * 256;
            unsigned so = (unsigned)((i >> 3) * 9 + (i & 7)) * 16;
            cpa16(kb + so, GK + i);
            cpa16(vb + so, GV + i);
        }
#pragma unroll
        for (int t = 0; t < 6; t++) {
            int i = tid + t * 256;
            unsigned so = (unsigned)((i >> 3) * 9 + (i & 7)) * 16;
            cpa16(pb + so, GP + i);
        }
        asm volatile("cp.async.commit_group;\n" ::: "memory");
    };

    issue_tile(0, 0);

    for (int idx = tid; idx < 4096; idx += 256) {
        int qi = idx >> 5, d2 = (idx & 31) << 1;
        float2 qv =
            *(const float2*)&g_q[((size_t)(b * Lc + q0 + qi)) * 512 + h * 64 + d2];
        *(unsigned*)&QU[qi * 72 + d2] =
            packh2((qv.x + ubias[h * 64 + d2]) * scale,
                   (qv.y + ubias[h * 64 + d2 + 1]) * scale);
        *(unsigned*)&QV[qi * 72 + d2] =
            packh2((qv.x + vbias[h * 64 + d2]) * scale,
                   (qv.y + vbias[h * 64 + d2 + 1]) * scale);
    }
    __syncthreads();

    unsigned au[4][4], av[4][4];
    {
        unsigned baseU = s2u(QU), baseV = s2u(QV);
        int row = qs + (l & 15), colp = (l & 16) >> 1;
#pragma unroll
        for (int kc = 0; kc < 4; kc++) {
            unsigned off = (row * 72 + kc * 16 + colp) * 2;
            ldsm4(baseU + off, au[kc][0], au[kc][1], au[kc][2], au[kc][3]);
            ldsm4(baseV + off, av[kc][0], av[kc][1], av[kc][2], av[kc][3]);
        }
    }

    float ct[8][4];
#pragma unroll
    for (int nt = 0; nt < 8; nt++)
#pragma unroll
        for (int e = 0; e < 4; e++) ct[nt][e] = 0.f;
    float rs_lo = 0.f, rs_hi = 0.f;

    const int nlane = (l & 7) + ((l & 16) >> 1);
    const int klane = l & 8;
    const int tkl = (l & 7) + (l & 8);
    const int tnl = (l & 16) >> 1;
    const int r0w = 112 - qs;

    for (int kt = 0; kt < 16; kt++) {
        const int bb = kt & 1;
        const int kt0 = kt << 6;
        __syncthreads();
        if (kt < 15) {
            issue_tile(kt0 + 64, bb ^ 1);
            asm volatile("cp.async.wait_group 1;\n" ::: "memory");
        } else {
            asm volatile("cp.async.wait_group 0;\n" ::: "memory");
        }
        __syncthreads();

        const unsigned kB = kB0 + bb * 9216;
        const unsigned vB = vB0 + bb * 9216;
        const unsigned pB = pB0 + bb * 27648;

        float bd[10][4];
#pragma unroll
        for (int nt = 0; nt < 10; nt++)
#pragma unroll
            for (int e = 0; e < 4; e++) bd[nt][e] = 0.f;
#pragma unroll
        for (int np = 0; np < 5; np++) {
            int nb = r0w + np * 16 + nlane;
#pragma unroll
            for (int kc = 0; kc < 4; kc++) {
                unsigned r0, r1, r2, r3;
                ldsm4(pB + (nb * 72 + kc * 16 + klane) * 2, r0, r1, r2, r3);
                unsigned b0[2] = {r0, r1}, b1[2] = {r2, r3};
                mma_f16(bd[np * 2], av[kc], b0);
                mma_f16(bd[np * 2 + 1], av[kc], b1);
            }
        }
        {
            int r = l >> 2, col = ((l & 3) << 1);
#pragma unroll
            for (int nt = 0; nt < 10; nt++) {
                *(float2*)&scr[r * 92 + nt * 8 + col] =
                    make_float2(bd[nt][0], bd[nt][1]);
                *(float2*)&scr[(r + 8) * 92 + nt * 8 + col] =
                    make_float2(bd[nt][2], bd[nt][3]);
            }
        }
        __syncwarp();

        float sc[8][4];
#pragma unroll
        for (int nt = 0; nt < 8; nt++)
#pragma unroll
            for (int e = 0; e < 4; e++) sc[nt][e] = 0.f;
#pragma unroll
        for (int np = 0; np < 4; np++) {
            int nb = np * 16 + nlane;
#pragma unroll
            for (int kc = 0; kc < 4; kc++) {
                unsigned r0, r1, r2, r3;
                ldsm4(kB + (nb * 72 + kc * 16 + klane) * 2, r0, r1, r2, r3);
                unsigned b0[2] = {r0, r1}, b1[2] = {r2, r3};
                mma_f16(sc[np * 2], au[kc], b0);
                mma_f16(sc[np * 2 + 1], au[kc], b1);
            }
        }

        {
            int r = l >> 2;
#pragma unroll
            for (int nt = 0; nt < 8; nt++) {
                int kk = nt * 8 + ((l & 3) << 1);
                int j = kk - r + 15;
                sc[nt][0] += scr[r * 92 + j];
                sc[nt][1] += scr[r * 92 + j + 1];
                int j2 = kk - (r + 8) + 15;
                sc[nt][2] += scr[(r + 8) * 92 + j2];
                sc[nt][3] += scr[(r + 8) * 92 + j2 + 1];
            }
#pragma unroll
            for (int nt = 0; nt < 8; nt++) {
#pragma unroll
                for (int e = 0; e < 4; e++) sc[nt][e] = __expf(sc[nt][e]);
                rs_lo += sc[nt][0] + sc[nt][1];
                rs_hi += sc[nt][2] + sc[nt][3];
            }
            size_t rbase =
                ((size_t)bh * Lc + (q0 + qs + r)) * Lc + kt0 + ((l & 3) << 1);
#pragma unroll
            for (int nt = 0; nt < 8; nt++) {
                *(float2*)&attn[rbase + nt * 8] = make_float2(sc[nt][0], sc[nt][1]);
                *(float2*)&attn[rbase + 8 * Lc + nt * 8] =
                    make_float2(sc[nt][2], sc[nt][3]);
            }
        }

#pragma unroll
        for (int kc = 0; kc < 4; kc++) {
            unsigned pa[4];
            pa[0] = packh2(sc[2 * kc][0], sc[2 * kc][1]);
            pa[1] = packh2(sc[2 * kc][2], sc[2 * kc][3]);
            pa[2] = packh2(sc[2 * kc + 1][0], sc[2 * kc + 1][1]);
            pa[3] = packh2(sc[2 * kc + 1][2], sc[2 * kc + 1][3]);
            int krow = kc * 16 + tkl;
#pragma unroll
            for (int np = 0; np < 4; np++) {
                unsigned r0, r1, r2, r3;
                ldsm4t(vB + (krow * 72 + np * 16 + tnl) * 2, r0, r1, r2, r3);
                unsigned b0[2] = {r0, r1}, b1[2] = {r2, r3};
                mma_f16(ct[np * 2], pa, b0);
                mma_f16(ct[np * 2 + 1], pa, b1);
            }
        }
    }

    // ---- rowsum reduce; broadcast inverses; store ctx planes ----
    rs_lo += __shfl_xor_sync(0xffffffffu, rs_lo, 1);
    rs_lo += __shfl_xor_sync(0xffffffffu, rs_lo, 2);
    rs_hi += __shfl_xor_sync(0xffffffffu, rs_hi, 1);
    rs_hi += __shfl_xor_sync(0xffffffffu, rs_hi, 2);
    float inv_lo = 1.f / rs_lo, inv_hi = 1.f / rs_hi;
    float* INV = (float*)(smem + AINV);
    int r = l >> 2;
    if ((l & 3) == 0) {
        INV[qs + r] = inv_lo;
        INV[qs + r + 8] = inv_hi;
    }
    size_t cbase = ((size_t)(b * Lc + q0 + qs + r)) * 512 + h * 64 + ((l & 3) << 1);
#pragma unroll
    for (int nt = 0; nt < 8; nt++) {
        unsigned hh, lo;
        pack_split(ct[nt][0] * inv_lo, ct[nt][1] * inv_lo, hh, lo);
        *(unsigned*)&g_cth[cbase + nt * 8] = hh;
        *(unsigned*)&g_ctl[cbase + nt * 8] = lo;
        pack_split(ct[nt][2] * inv_hi, ct[nt][3] * inv_hi, hh, lo);
        *(unsigned*)&g_cth[cbase + 8 * 512 + nt * 8] = hh;
        *(unsigned*)&g_ctl[cbase + 8 * 512 + nt * 8] = lo;
    }

    // ---- in-kernel normalization: rescale this CTA's 128x1024 block (L2).
    __syncthreads();
    float4* A4 = (float4*)(attn + ((size_t)bh * Lc + q0) * Lc);
#pragma unroll
    for (int it = 0; it < 16; it++) {
        int id[8]; float4 v[8]; float iv[8];
#pragma unroll
        for (int j = 0; j < 8; j++) {
            id[j] = tid + (it * 8 + j) * 256;
            v[j] = A4[id[j]];
        }
#pragma unroll
        for (int j = 0; j < 8; j++) iv[j] = INV[id[j] >> 8];
#pragma unroll
        for (int j = 0; j < 8; j++) {
            v[j].x *= iv[j]; v[j].y *= iv[j]; v[j].z *= iv[j]; v[j].w *= iv[j];
            A4[id[j]] = v[j];
        }
    }
}

// ---------------------------------------------------------------------------
extern "C" void kernel_launch(void* const* d_in, const int* in_sizes, int n_in,
                              void* d_out, int out_size) {
    const float* x    = (const float*)d_in[0];
    const float* pos  = (const float*)d_in[1];
    const float* wqkv = (const float*)d_in[2];
    const float* wpos = (const float*)d_in[3];
    const float* wout = (const float*)d_in[4];
    const float* bout = (const float*)d_in[5];
    const float* ub   = (const float*)d_in[6];
    const float* vb   = (const float*)d_in[7];
    float* out = (float*)d_out;

    int attn_in_out = ((long long)out_size >= (long long)OUT_ELEMS + ATTN_ELEMS);
    float* attn_buf = attn_in_out ? (out + OUT_ELEMS) : g_attn_scratch;

    cvt_all<<<12799, 256>>>(x, wqkv, wpos, wout, pos);

    cudaFuncSetAttribute(gemm_qkv_pos, cudaFuncAttributeMaxDynamicSharedMemorySize,
                         GSM);
    gemm_qkv_pos<<<832, 256, GSM>>>();

    cudaFuncSetAttribute(attn_kernel, cudaFuncAttributeMaxDynamicSharedMemorySize,
                         SM_BYTES_A);
    attn_kernel<<<dim3(8, 64), 256, SM_BYTES_A>>>(ub, vb, attn_buf);

    cudaFuncSetAttribute(gemm_out, cudaFuncAttributeMaxDynamicSharedMemorySize,
                         GSM);
    gemm_out<<<dim3(4, 64), 256, GSM>>>(bout, out);
}

// round 12
// speedup vs baseline: 5.9858x; 1.0297x over previous
#include <cuda_runtime.h>
#include <cuda_bf16.h>
#include <cuda_fp16.h>
#include <math.h>

#define Lc 1024
#define Pc 2047

#define OUT_ELEMS  (8 * 1024 * 512)
#define ATTN_ELEMS (64LL * 1024 * 1024)

__device__ float g_q[(size_t)8192 * 512];
__device__ float g_attn_scratch[(size_t)ATTN_ELEMS];
// fp16 single planes for attention operands
__device__ __half g_k[(size_t)64 * 1024 * 64];   // [bh][k][64]
__device__ __half g_v[(size_t)64 * 1024 * 64];   // [bh][k][64]
__device__ __half g_p[(size_t)8 * 2048 * 64];    // [h][p][64]; row 2047 stays zero
// split-bf16 planes (hi/lo) for GEMM operands
__device__ __nv_bfloat16 g_xh[(size_t)8192 * 512],  g_xl[(size_t)8192 * 512];
__device__ __nv_bfloat16 g_psh[(size_t)2048 * 512], g_psl[(size_t)2048 * 512];
__device__ __nv_bfloat16 g_cth[(size_t)8192 * 512], g_ctl[(size_t)8192 * 512];
__device__ __nv_bfloat16 g_wqh[(size_t)1536 * 512], g_wql[(size_t)1536 * 512];
__device__ __nv_bfloat16 g_wph[(size_t)512 * 512],  g_wpl[(size_t)512 * 512];
__device__ __nv_bfloat16 g_woh[(size_t)512 * 512],  g_wol[(size_t)512 * 512];

// ------------------------- helpers -------------------------------
__device__ __forceinline__ void mma_bf16(float* c, const unsigned* a,
                                         const unsigned* b) {
    asm volatile(
        "mma.sync.aligned.m16n8k16.row.col.f32.bf16.bf16.f32 "
        "{%0,%1,%2,%3}, {%4,%5,%6,%7}, {%8,%9}, {%0,%1,%2,%3};\n"
        : "+f"(c[0]), "+f"(c[1]), "+f"(c[2]), "+f"(c[3])
        : "r"(a[0]), "r"(a[1]), "r"(a[2]), "r"(a[3]), "r"(b[0]), "r"(b[1]));
}
__device__ __forceinline__ void mma_f16(float* c, const unsigned* a,
                                        const unsigned* b) {
    asm volatile(
        "mma.sync.aligned.m16n8k16.row.col.f32.f16.f16.f32 "
        "{%0,%1,%2,%3}, {%4,%5,%6,%7}, {%8,%9}, {%0,%1,%2,%3};\n"
        : "+f"(c[0]), "+f"(c[1]), "+f"(c[2]), "+f"(c[3])
        : "r"(a[0]), "r"(a[1]), "r"(a[2]), "r"(a[3]), "r"(b[0]), "r"(b[1]));
}
__device__ __forceinline__ void ldsm4(unsigned addr, unsigned& r0, unsigned& r1,
                                      unsigned& r2, unsigned& r3) {
    asm volatile("ldmatrix.sync.aligned.m8n8.x4.shared.b16 {%0,%1,%2,%3}, [%4];"
                 : "=r"(r0), "=r"(r1), "=r"(r2), "=r"(r3) : "r"(addr));
}
__device__ __forceinline__ void ldsm4t(unsigned addr, unsigned& r0, unsigned& r1,
                                       unsigned& r2, unsigned& r3) {
    asm volatile(
        "ldmatrix.sync.aligned.m8n8.x4.trans.shared.b16 {%0,%1,%2,%3}, [%4];"
        : "=r"(r0), "=r"(r1), "=r"(r2), "=r"(r3) : "r"(addr));
}
__device__ __forceinline__ unsigned s2u(const void* p) {
    return (unsigned)__cvta_generic_to_shared(p);
}
__device__ __forceinline__ void cpa16(unsigned dst, const void* src) {
    asm volatile("cp.async.cg.shared.global [%0], [%1], 16;\n" ::"r"(dst),
                 "l"(src));
}
__device__ __forceinline__ void pack_split(float x0, float x1, unsigned& h,
                                           unsigned& l) {
    __nv_bfloat162 hb = __floats2bfloat162_rn(x0, x1);
    float2 hf = __bfloat1622float2(hb);
    __nv_bfloat162 lb = __floats2bfloat162_rn(x0 - hf.x, x1 - hf.y);
    h = *(unsigned*)&hb; l = *(unsigned*)&lb;
}
__device__ __forceinline__ unsigned packh2(float x0, float x1) {
    __half2 t = __floats2half2_rn(x0, x1);
    return *(unsigned*)&t;
}

// ---------------------------------------------------------------------------
// One-shot conversion of all fp32 operands to split-bf16 planes.
// ---------------------------------------------------------------------------
__global__ __launch_bounds__(256) void cvt_all(
    const float* __restrict__ x, const float* __restrict__ wq,
    const float* __restrict__ wp, const float* __restrict__ wo,
    const float* __restrict__ pos) {
    int bid = blockIdx.x;
    const float* src; __nv_bfloat16 *dh, *dl; int base;
    if (bid < 8192)       { src = x;   dh = g_xh;  dl = g_xl;  base = bid; }
    else if (bid < 9728)  { src = wq;  dh = g_wqh; dl = g_wql; base = bid - 8192; }
    else if (bid < 10240) { src = wp;  dh = g_wph; dl = g_wpl; base = bid - 9728; }
    else if (bid < 10752) { src = wo;  dh = g_woh; dl = g_wol; base = bid - 10240; }
    else                  { src = pos; dh = g_psh; dl = g_psl; base = bid - 10752; }
    int i = base * 256 + threadIdx.x;
    float2 v = ((const float2*)src)[i];
    unsigned h, l;
    pack_split(v.x, v.y, h, l);
    ((unsigned*)dh)[i] = h;
    ((unsigned*)dl)[i] = l;
}

// ---------------------------------------------------------------------------
// Shared GEMM mainloop (K=512, 128x128 tile, split-bf16, cp.async dbuf).
// ---------------------------------------------------------------------------
#define GT 10240
#define GSTAGE (4 * GT)
#define GSM (2 * GSTAGE)

#define GEMM_MAIN(Ah, Al, Wh, Wl, m0, n0, acc)                                  \
    {                                                                           \
        const unsigned sb = s2u(smem);                                          \
        const int lrow = tid >> 2, lc = (tid & 3) << 3;                         \
        auto issue = [&](int k0, int bb) {                                      \
            unsigned base = sb + bb * GSTAGE;                                   \
            _Pragma("unroll") for (int t = 0; t < 2; t++) {                     \
                int row = lrow + t * 64;                                        \
                unsigned so = (unsigned)row * 80 + ((unsigned)lc << 1);         \
                size_t ao = (size_t)(m0 + row) * 512 + k0 + lc;                 \
                size_t wo_ = (size_t)(n0 + row) * 512 + k0 + lc;                \
                cpa16(base + so, Ah + ao);                                      \
                cpa16(base + GT + so, Al + ao);                                 \
                cpa16(base + 2 * GT + so, Wh + wo_);                            \
                cpa16(base + 3 * GT + so, Wl + wo_);                            \
            }                                                                   \
            asm volatile("cp.async.commit_group;\n" ::: "memory");              \
        };                                                                      \
        issue(0, 0);                                                            \
        for (int s = 0; s < 16; s++) {                                          \
            const int bb = s & 1;                                               \
            __syncthreads();                                                    \
            if (s < 15) {                                                       \
                issue((s + 1) << 5, bb ^ 1);                                    \
                asm volatile("cp.async.wait_group 1;\n" ::: "memory");          \
            } else {                                                            \
                asm volatile("cp.async.wait_group 0;\n" ::: "memory");          \
            }                                                                   \
            __syncthreads();                                                    \
            unsigned base = sb + bb * GSTAGE;                                   \
            _Pragma("unroll") for (int kc = 0; kc < 2; kc++) {                  \
                const int kk = kc << 4;                                         \
                unsigned ah[4][4], al[4][4], bh[4][2], bl[4][2];                \
                _Pragma("unroll") for (int mt = 0; mt < 4; mt++) {              \
                    unsigned off = ((aRow + mt * 16) * 40 + kk + aCol) * 2;     \
                    ldsm4(base + off, ah[mt][0], ah[mt][1], ah[mt][2],          \
                          ah[mt][3]);                                           \
                    ldsm4(base + GT + off, al[mt][0], al[mt][1], al[mt][2],     \
                          al[mt][3]);                                           \
                }                                                               \
                _Pragma("unroll") for (int np = 0; np < 2; np++) {              \
                    unsigned off = ((bRow + np * 16) * 40 + kk + bCol) * 2;     \
                    unsigned r0, r1, r2, r3;                                    \
                    ldsm4(base + 2 * GT + off, r0, r1, r2, r3);                 \
                    bh[np * 2][0] = r0; bh[np * 2][1] = r1;                     \
                    bh[np * 2 + 1][0] = r2; bh[np * 2 + 1][1] = r3;             \
                    ldsm4(base + 3 * GT + off, r0, r1, r2, r3);                 \
                    bl[np * 2][0] = r0; bl[np * 2][1] = r1;                     \
                    bl[np * 2 + 1][0] = r2; bl[np * 2 + 1][1] = r3;             \
                }                                                               \
                _Pragma("unroll") for (int mt = 0; mt < 4; mt++)                \
                    _Pragma("unroll") for (int nt = 0; nt < 4; nt++) {          \
                        mma_bf16(acc[mt][nt], ah[mt], bh[nt]);                  \
                        mma_bf16(acc[mt][nt], al[mt], bh[nt]);                  \
                        mma_bf16(acc[mt][nt], ah[mt], bl[nt]);                  \
                    }                                                           \
            }                                                                   \
        }                                                                       \
    }

// ---------------------------------------------------------------------------
// Fused qkv-proj + pos-proj GEMM. 1-D grid, 832 blocks. 2 CTAs/SM.
// ---------------------------------------------------------------------------
__global__ __launch_bounds__(256, 2) void gemm_qkv_pos() {
    extern __shared__ char smem[];
    const int tid = threadIdx.x, l = tid & 31, w = tid >> 5;
    const int wm = w >> 2, wn = w & 3;
    const int aRow = wm * 64 + (l & 15);
    const int aCol = (l & 16) >> 1;
    const int bRow = wn * 32 + (l & 7) + ((l & 16) >> 1);
    const int bCol = l & 8;

    const int bid = blockIdx.x;
    const __nv_bfloat16 *Ah, *Al, *Wh, *Wl;
    int m0, n0, mode;
    if (bid < 768) {
        Ah = g_xh; Al = g_xl; Wh = g_wqh; Wl = g_wql;
        m0 = (bid / 12) << 7; n0 = (bid % 12) << 7; mode = 1;
    } else {
        int t = bid - 768;
        Ah = g_psh; Al = g_psl; Wh = g_wph; Wl = g_wpl;
        m0 = (t >> 2) << 7; n0 = (t & 3) << 7; mode = 2;
    }

    float acc[4][4][4];
#pragma unroll
    for (int i = 0; i < 4; i++)
#pragma unroll
        for (int j = 0; j < 4; j++)
#pragma unroll
            for (int e = 0; e < 4; e++) acc[i][j][e] = 0.f;

    GEMM_MAIN(Ah, Al, Wh, Wl, m0, n0, acc);

    const int er = m0 + wm * 64 + (l >> 2);
    const int ec = n0 + wn * 32 + ((l & 3) << 1);
#pragma unroll
    for (int mt = 0; mt < 4; mt++) {
#pragma unroll
        for (int nt = 0; nt < 4; nt++) {
            int col = ec + nt * 8;
#pragma unroll
            for (int half = 0; half < 2; half++) {
                int r = er + mt * 16 + half * 8;
                float a0 = acc[mt][nt][half * 2];
                float a1 = acc[mt][nt][half * 2 + 1];
                if (mode == 1) {
                    int hh_ = col / 192;
                    int rem = col - hh_ * 192;
                    int part = rem >> 6, d = rem & 63;
                    if (part == 0) {
                        *(float2*)&g_q[(size_t)r * 512 + hh_ * 64 + d] =
                            make_float2(a0, a1);
                    } else {
                        int b = r >> 10, ll2 = r & 1023;
                        size_t idx =
                            (((size_t)(b * 8 + hh_)) * 1024 + ll2) * 64 + d;
                        __half2 hv = __floats2half2_rn(a0, a1);
                        if (part == 1) *(__half2*)&g_k[idx] = hv;
                        else           *(__half2*)&g_v[idx] = hv;
                    }
                } else {
                    int hh_ = col >> 6, d = col & 63;
                    size_t idx = (((size_t)hh_) * 2048 + r) * 64 + d;
                    *(__half2*)&g_p[idx] = __floats2half2_rn(a0, a1);
                }
            }
        }
    }
}

// ---------------------------------------------------------------------------
// Standalone out-proj GEMM: out = ctx @ wout^T + bias. Grid (4, 64), 2 CTA/SM.
// ---------------------------------------------------------------------------
__global__ __launch_bounds__(256, 2) void gemm_out(
    const float* __restrict__ bias, float* __restrict__ C_ext) {
    extern __shared__ char smem[];
    const int tid = threadIdx.x, l = tid & 31, w = tid >> 5;
    const int wm = w >> 2, wn = w & 3;
    const int aRow = wm * 64 + (l & 15);
    const int aCol = (l & 16) >> 1;
    const int bRow = wn * 32 + (l & 7) + ((l & 16) >> 1);
    const int bCol = l & 8;
    const int m0 = blockIdx.y << 7, n0 = blockIdx.x << 7;

    float acc[4][4][4];
#pragma unroll
    for (int i = 0; i < 4; i++)
#pragma unroll
        for (int j = 0; j < 4; j++)
#pragma unroll
            for (int e = 0; e < 4; e++) acc[i][j][e] = 0.f;

    GEMM_MAIN(g_cth, g_ctl, g_woh, g_wol, m0, n0, acc);

    const int er = m0 + wm * 64 + (l >> 2);
    const int ec = n0 + wn * 32 + ((l & 3) << 1);
#pragma unroll
    for (int mt = 0; mt < 4; mt++) {
#pragma unroll
        for (int nt = 0; nt < 4; nt++) {
            int col = ec + nt * 8;
            float2 bb2 = *(const float2*)&bias[col];
#pragma unroll
            for (int half = 0; half < 2; half++) {
                int r = er + mt * 16 + half * 8;
                *(float2*)&C_ext[(size_t)r * 512 + col] =
                    make_float2(acc[mt][nt][half * 2] + bb2.x,
                                acc[mt][nt][half * 2 + 1] + bb2.y);
            }
        }
    }
}

// ---------------------------------------------------------------------------
// Fused attention + in-kernel normalization. Grid (8, 64), 256 thr, 2 CTA/SM.
// smem (113664 B): P dbuf [0,55296) | K dbuf [55296,73728) |
//   V dbuf [73728,92160) | scr fp16 [92160,113664) ; INV reuses scr base.
// QU/QV staging overlaps P region (dead after register fragment preload).
// ---------------------------------------------------------------------------
#define AP0 0
#define AK0 55296
#define AV0 73728
#define ASCRH 92160
#define AINV ASCRH
#define SM_BYTES_A 113664

__global__ __launch_bounds__(256, 2) void attn_kernel(
    const float* __restrict__ ubias, const float* __restrict__ vbias,
    float* __restrict__ attn) {
    extern __shared__ char smem[];

    const int tid = threadIdx.x, l = tid & 31, w = tid >> 5;
    const int bh = blockIdx.y, b = bh >> 3, h = bh & 7;
    const int q0 = blockIdx.x << 7;
    const int qs = w << 4;
    const float scale = 0.04419417382415922f;  // 1/sqrt(512)

    const unsigned pB0 = s2u(smem + AP0);
    const unsigned kB0 = s2u(smem + AK0);
    const unsigned vB0 = s2u(smem + AV0);
    __half* scrh = (__half*)(smem + ASCRH) + w * 16 * 84;

    // ---- QU/QV staging (overlaps P buffers; consumed before first tile) ----
    {
        __half* QU = (__half*)(smem + 0);
        __half* QV = (__half*)(smem + 18432);
        for (int idx = tid; idx < 4096; idx += 256) {
            int qi = idx >> 5, d2 = (idx & 31) << 1;
            float2 qv = *(const float2*)&g_q[((size_t)(b * Lc + q0 + qi)) * 512 +
                                             h * 64 + d2];
            *(unsigned*)&QU[qi * 72 + d2] =
                packh2((qv.x + ubias[h * 64 + d2]) * scale,
                       (qv.y + ubias[h * 64 + d2 + 1]) * scale);
            *(unsigned*)&QV[qi * 72 + d2] =
                packh2((qv.x + vbias[h * 64 + d2]) * scale,
                       (qv.y + vbias[h * 64 + d2 + 1]) * scale);
        }
    }
    __syncthreads();

    unsigned au[4][4], av[4][4];
    {
        unsigned baseU = s2u(smem + 0), baseV = s2u(smem + 18432);
        int row = qs + (l & 15), colp = (l & 16) >> 1;
#pragma unroll
        for (int kc = 0; kc < 4; kc++) {
            unsigned off = (row * 72 + kc * 16 + colp) * 2;
            ldsm4(baseU + off, au[kc][0], au[kc][1], au[kc][2], au[kc][3]);
            ldsm4(baseV + off, av[kc][0], av[kc][1], av[kc][2], av[kc][3]);
        }
    }
    __syncthreads();   // all fragments read before P overwrites staging

    auto issue_tile = [&](int kt0, int bb) {
        size_t gb = (((size_t)bh) * 1024 + kt0) * 64;
        const uint4* GK = (const uint4*)(g_k + gb);
        const uint4* GV = (const uint4*)(g_v + gb);
        int pbase = kt0 - q0 + 896;
        const uint4* GP = (const uint4*)(g_p + (((size_t)h) * 2048 + pbase) * 64);
        unsigned kb = kB0 + bb * 9216;
        unsigned vb = vB0 + bb * 9216;
        unsigned pb = pB0 + bb * 27648;
#pragma unroll
        for (int t = 0; t < 2; t++) {
            int i = tid + t * 256;
            unsigned so = (unsigned)((i >> 3) * 9 + (i & 7)) * 16;
            cpa16(kb + so, GK + i);
            cpa16(vb + so, GV + i);
        }
#pragma unroll
        for (int t = 0; t < 6; t++) {
            int i = tid + t * 256;
            unsigned so = (unsigned)((i >> 3) * 9 + (i & 7)) * 16;
            cpa16(pb + so, GP + i);
        }
        asm volatile("cp.async.commit_group;\n" ::: "memory");
    };

    issue_tile(0, 0);

    float ct[8][4];
#pragma unroll
    for (int nt = 0; nt < 8; nt++)
#pragma unroll
        for (int e = 0; e < 4; e++) ct[nt][e] = 0.f;
    float rs_lo = 0.f, rs_hi = 0.f;

    const int nlane = (l & 7) + ((l & 16) >> 1);
    const int klane = l & 8;
    const int tkl = (l & 7) + (l & 8);
    const int tnl = (l & 16) >> 1;
    const int r0w = 112 - qs;

    for (int kt = 0; kt < 16; kt++) {
        const int bb = kt & 1;
        const int kt0 = kt << 6;
        __syncthreads();
        if (kt < 15) {
            issue_tile(kt0 + 64, bb ^ 1);
            asm volatile("cp.async.wait_group 1;\n" ::: "memory");
        } else {
            asm volatile("cp.async.wait_group 0;\n" ::: "memory");
        }
        __syncthreads();

        const unsigned kB = kB0 + bb * 9216;
        const unsigned vB = vB0 + bb * 9216;
        const unsigned pB = pB0 + bb * 27648;

        // ---- bd strip: 16x80 per warp, scratch in fp16 ----
        float bd[10][4];
#pragma unroll
        for (int nt = 0; nt < 10; nt++)
#pragma unroll
            for (int e = 0; e < 4; e++) bd[nt][e] = 0.f;
#pragma unroll
        for (int np = 0; np < 5; np++) {
            int nb = r0w + np * 16 + nlane;
#pragma unroll
            for (int kc = 0; kc < 4; kc++) {
                unsigned r0, r1, r2, r3;
                ldsm4(pB + (nb * 72 + kc * 16 + klane) * 2, r0, r1, r2, r3);
                unsigned b0[2] = {r0, r1}, b1[2] = {r2, r3};
                mma_f16(bd[np * 2], av[kc], b0);
                mma_f16(bd[np * 2 + 1], av[kc], b1);
            }
        }
        {
            int r = l >> 2, col = ((l & 3) << 1);
#pragma unroll
            for (int nt = 0; nt < 10; nt++) {
                *(__half2*)&scrh[r * 84 + nt * 8 + col] =
                    __floats2half2_rn(bd[nt][0], bd[nt][1]);
                *(__half2*)&scrh[(r + 8) * 84 + nt * 8 + col] =
                    __floats2half2_rn(bd[nt][2], bd[nt][3]);
            }
        }
        __syncwarp();

        // ---- ac ----
        float sc[8][4];
#pragma unroll
        for (int nt = 0; nt < 8; nt++)
#pragma unroll
            for (int e = 0; e < 4; e++) sc[nt][e] = 0.f;
#pragma unroll
        for (int np = 0; np < 4; np++) {
            int nb = np * 16 + nlane;
#pragma unroll
            for (int kc = 0; kc < 4; kc++) {
                unsigned r0, r1, r2, r3;
                ldsm4(kB + (nb * 72 + kc * 16 + klane) * 2, r0, r1, r2, r3);
                unsigned b0[2] = {r0, r1}, b1[2] = {r2, r3};
                mma_f16(sc[np * 2], au[kc], b0);
                mma_f16(sc[np * 2 + 1], au[kc], b1);
            }
        }

        // ---- add banded bd, exp, rowsum, store unnormalized probs ----
        {
            int r = l >> 2;
#pragma unroll
            for (int nt = 0; nt < 8; nt++) {
                int kk = nt * 8 + ((l & 3) << 1);
                int j = kk - r + 15;
                sc[nt][0] += __half2float(scrh[r * 84 + j]);
                sc[nt][1] += __half2float(scrh[r * 84 + j + 1]);
                int j2 = kk - (r + 8) + 15;
                sc[nt][2] += __half2float(scrh[(r + 8) * 84 + j2]);
                sc[nt][3] += __half2float(scrh[(r + 8) * 84 + j2 + 1]);
            }
#pragma unroll
            for (int nt = 0; nt < 8; nt++) {
#pragma unroll
                for (int e = 0; e < 4; e++) sc[nt][e] = __expf(sc[nt][e]);
                rs_lo += sc[nt][0] + sc[nt][1];
                rs_hi += sc[nt][2] + sc[nt][3];
            }
            size_t rbase =
                ((size_t)bh * Lc + (q0 + qs + r)) * Lc + kt0 + ((l & 3) << 1);
#pragma unroll
            for (int nt = 0; nt < 8; nt++) {
                *(float2*)&attn[rbase + nt * 8] = make_float2(sc[nt][0], sc[nt][1]);
                *(float2*)&attn[rbase + 8 * Lc + nt * 8] =
                    make_float2(sc[nt][2], sc[nt][3]);
            }
        }

        // ---- ctx += P @ V ----
#pragma unroll
        for (int kc = 0; kc < 4; kc++) {
            unsigned pa[4];
            pa[0] = packh2(sc[2 * kc][0], sc[2 * kc][1]);
            pa[1] = packh2(sc[2 * kc][2], sc[2 * kc][3]);
            pa[2] = packh2(sc[2 * kc + 1][0], sc[2 * kc + 1][1]);
            pa[3] = packh2(sc[2 * kc + 1][2], sc[2 * kc + 1][3]);
            int krow = kc * 16 + tkl;
#pragma unroll
            for (int np = 0; np < 4; np++) {
                unsigned r0, r1, r2, r3;
                ldsm4t(vB + (krow * 72 + np * 16 + tnl) * 2, r0, r1, r2, r3);
                unsigned b0[2] = {r0, r1}, b1[2] = {r2, r3};
                mma_f16(ct[np * 2], pa, b0);
                mma_f16(ct[np * 2 + 1], pa, b1);
            }
        }
    }

    // ---- rowsum reduce; broadcast inverses (INV reuses scr); ctx planes ----
    rs_lo += __shfl_xor_sync(0xffffffffu, rs_lo, 1);
    rs_lo += __shfl_xor_sync(0xffffffffu, rs_lo, 2);
    rs_hi += __shfl_xor_sync(0xffffffffu, rs_hi, 1);
    rs_hi += __shfl_xor_sync(0xffffffffu, rs_hi, 2);
    float inv_lo = 1.f / rs_lo, inv_hi = 1.f / rs_hi;
    float* INV = (float*)(smem + AINV);
    int r = l >> 2;
    if ((l & 3) == 0) {
        INV[qs + r] = inv_lo;
        INV[qs + r + 8] = inv_hi;
    }
    size_t cbase = ((size_t)(b * Lc + q0 + qs + r)) * 512 + h * 64 + ((l & 3) << 1);
#pragma unroll
    for (int nt = 0; nt < 8; nt++) {
        unsigned hh, lo;
        pack_split(ct[nt][0] * inv_lo, ct[nt][1] * inv_lo, hh, lo);
        *(unsigned*)&g_cth[cbase + nt * 8] = hh;
        *(unsigned*)&g_ctl[cbase + nt * 8] = lo;
        pack_split(ct[nt][2] * inv_hi, ct[nt][3] * inv_hi, hh, lo);
        *(unsigned*)&g_cth[cbase + 8 * 512 + nt * 8] = hh;
        *(unsigned*)&g_ctl[cbase + 8 * 512 + nt * 8] = lo;
    }

    // ---- in-kernel normalization: rescale this CTA's 128x1024 block ----
    __syncthreads();
    float4* A4 = (float4*)(attn + ((size_t)bh * Lc + q0) * Lc);
#pragma unroll
    for (int it = 0; it < 16; it++) {
        int id[8]; float4 v[8]; float iv[8];
#pragma unroll
        for (int j = 0; j < 8; j++) {
            id[j] = tid + (it * 8 + j) * 256;
            v[j] = A4[id[j]];
        }
#pragma unroll
        for (int j = 0; j < 8; j++) iv[j] = INV[id[j] >> 8];
#pragma unroll
        for (int j = 0; j < 8; j++) {
            v[j].x *= iv[j]; v[j].y *= iv[j]; v[j].z *= iv[j]; v[j].w *= iv[j];
            A4[id[j]] = v[j];
        }
    }
}

// ---------------------------------------------------------------------------
extern "C" void kernel_launch(void* const* d_in, const int* in_sizes, int n_in,
                              void* d_out, int out_size) {
    const float* x    = (const float*)d_in[0];
    const float* pos  = (const float*)d_in[1];
    const float* wqkv = (const float*)d_in[2];
    const float* wpos = (const float*)d_in[3];
    const float* wout = (const float*)d_in[4];
    const float* bout = (const float*)d_in[5];
    const float* ub   = (const float*)d_in[6];
    const float* vb   = (const float*)d_in[7];
    float* out = (float*)d_out;

    int attn_in_out = ((long long)out_size >= (long long)OUT_ELEMS + ATTN_ELEMS);
    float* attn_buf = attn_in_out ? (out + OUT_ELEMS) : g_attn_scratch;

    cvt_all<<<12799, 256>>>(x, wqkv, wpos, wout, pos);

    cudaFuncSetAttribute(gemm_qkv_pos, cudaFuncAttributeMaxDynamicSharedMemorySize,
                         GSM);
    gemm_qkv_pos<<<832, 256, GSM>>>();

    cudaFuncSetAttribute(attn_kernel, cudaFuncAttributeMaxDynamicSharedMemorySize,
                         SM_BYTES_A);
    attn_kernel<<<dim3(8, 64), 256, SM_BYTES_A>>>(ub, vb, attn_buf);

    cudaFuncSetAttribute(gemm_out, cudaFuncAttributeMaxDynamicSharedMemorySize,
                         GSM);
    gemm_out<<<dim3(4, 64), 256, GSM>>>(bout, out);
}

// round 13
// speedup vs baseline: 7.1352x; 1.1920x over previous
#include <cuda_runtime.h>
#include <cuda_bf16.h>
#include <cuda_fp16.h>
#include <math.h>

#define Lc 1024
#define Pc 2047

#define OUT_ELEMS  (8 * 1024 * 512)
#define ATTN_ELEMS (64LL * 1024 * 1024)

__device__ float g_q[(size_t)8192 * 512];
__device__ float g_attn_scratch[(size_t)ATTN_ELEMS];
// fp16 single planes for attention operands
__device__ __half g_k[(size_t)64 * 1024 * 64];   // [bh][k][64]
__device__ __half g_v[(size_t)64 * 1024 * 64];   // [bh][k][64]
__device__ __half g_p[(size_t)8 * 2048 * 64];    // [h][p][64]; row 2047 stays zero
// fp16 single planes for qkv/pos GEMM operands (outputs get fp16-quantized anyway)
__device__ __half g_xf[(size_t)8192 * 512];
__device__ __half g_wqf[(size_t)1536 * 512];
__device__ __half g_wpf[(size_t)512 * 512];
__device__ __half g_psf[(size_t)2048 * 512];
// split-bf16 planes (hi/lo) for the out-proj GEMM (errors land in output)
__device__ __nv_bfloat16 g_cth[(size_t)8192 * 512], g_ctl[(size_t)8192 * 512];
__device__ __nv_bfloat16 g_woh[(size_t)512 * 512],  g_wol[(size_t)512 * 512];

// ------------------------- helpers -------------------------------
__device__ __forceinline__ void mma_bf16(float* c, const unsigned* a,
                                         const unsigned* b) {
    asm volatile(
        "mma.sync.aligned.m16n8k16.row.col.f32.bf16.bf16.f32 "
        "{%0,%1,%2,%3}, {%4,%5,%6,%7}, {%8,%9}, {%0,%1,%2,%3};\n"
        : "+f"(c[0]), "+f"(c[1]), "+f"(c[2]), "+f"(c[3])
        : "r"(a[0]), "r"(a[1]), "r"(a[2]), "r"(a[3]), "r"(b[0]), "r"(b[1]));
}
__device__ __forceinline__ void mma_f16(float* c, const unsigned* a,
                                        const unsigned* b) {
    asm volatile(
        "mma.sync.aligned.m16n8k16.row.col.f32.f16.f16.f32 "
        "{%0,%1,%2,%3}, {%4,%5,%6,%7}, {%8,%9}, {%0,%1,%2,%3};\n"
        : "+f"(c[0]), "+f"(c[1]), "+f"(c[2]), "+f"(c[3])
        : "r"(a[0]), "r"(a[1]), "r"(a[2]), "r"(a[3]), "r"(b[0]), "r"(b[1]));
}
__device__ __forceinline__ void ldsm4(unsigned addr, unsigned& r0, unsigned& r1,
                                      unsigned& r2, unsigned& r3) {
    asm volatile("ldmatrix.sync.aligned.m8n8.x4.shared.b16 {%0,%1,%2,%3}, [%4];"
                 : "=r"(r0), "=r"(r1), "=r"(r2), "=r"(r3) : "r"(addr));
}
__device__ __forceinline__ void ldsm4t(unsigned addr, unsigned& r0, unsigned& r1,
                                       unsigned& r2, unsigned& r3) {
    asm volatile(
        "ldmatrix.sync.aligned.m8n8.x4.trans.shared.b16 {%0,%1,%2,%3}, [%4];"
        : "=r"(r0), "=r"(r1), "=r"(r2), "=r"(r3) : "r"(addr));
}
__device__ __forceinline__ unsigned s2u(const void* p) {
    return (unsigned)__cvta_generic_to_shared(p);
}
__device__ __forceinline__ void cpa16(unsigned dst, const void* src) {
    asm volatile("cp.async.cg.shared.global [%0], [%1], 16;\n" ::"r"(dst),
                 "l"(src));
}
__device__ __forceinline__ void pack_split(float x0, float x1, unsigned& h,
                                           unsigned& l) {
    __nv_bfloat162 hb = __floats2bfloat162_rn(x0, x1);
    float2 hf = __bfloat1622float2(hb);
    __nv_bfloat162 lb = __floats2bfloat162_rn(x0 - hf.x, x1 - hf.y);
    h = *(unsigned*)&hb; l = *(unsigned*)&lb;
}
__device__ __forceinline__ unsigned packh2(float x0, float x1) {
    __half2 t = __floats2half2_rn(x0, x1);
    return *(unsigned*)&t;
}

// ---------------------------------------------------------------------------
// One-shot conversion. fp16 single: x, wqkv, wpos, pos. split-bf16: wout.
// Block ranges: [0,8192) x | [8192,9728) wqkv | [9728,10240) wpos |
//               [10240,10752) wout | [10752,12799) pos.
// ---------------------------------------------------------------------------
__global__ __launch_bounds__(256) void cvt_all(
    const float* __restrict__ x, const float* __restrict__ wq,
    const float* __restrict__ wp, const float* __restrict__ wo,
    const float* __restrict__ pos) {
    int bid = blockIdx.x;
    if (bid < 10240 || bid >= 10752) {
        const float* src; __half* d; int base;
        if (bid < 8192)       { src = x;   d = g_xf;  base = bid; }
        else if (bid < 9728)  { src = wq;  d = g_wqf; base = bid - 8192; }
        else if (bid < 10240) { src = wp;  d = g_wpf; base = bid - 9728; }
        else                  { src = pos; d = g_psf; base = bid - 10752; }
        int i = base * 256 + threadIdx.x;
        float2 v = ((const float2*)src)[i];
        ((unsigned*)d)[i] = packh2(v.x, v.y);
    } else {
        int i = (bid - 10240) * 256 + threadIdx.x;
        float2 v = ((const float2*)wo)[i];
        unsigned h, l;
        pack_split(v.x, v.y, h, l);
        ((unsigned*)g_woh)[i] = h;
        ((unsigned*)g_wol)[i] = l;
    }
}

// ---------------------------------------------------------------------------
// Split-bf16 GEMM mainloop (K=512, 128x128 tile, cp.async dbuf) — out-proj.
// ---------------------------------------------------------------------------
#define GT 10240
#define GSTAGE (4 * GT)
#define GSM (2 * GSTAGE)

#define GEMM_MAIN(Ah, Al, Wh, Wl, m0, n0, acc)                                  \
    {                                                                           \
        const unsigned sb = s2u(smem);                                          \
        const int lrow = tid >> 2, lc = (tid & 3) << 3;                         \
        auto issue = [&](int k0, int bb) {                                      \
            unsigned base = sb + bb * GSTAGE;                                   \
            _Pragma("unroll") for (int t = 0; t < 2; t++) {                     \
                int row = lrow + t * 64;                                        \
                unsigned so = (unsigned)row * 80 + ((unsigned)lc << 1);         \
                size_t ao = (size_t)(m0 + row) * 512 + k0 + lc;                 \
                size_t wo_ = (size_t)(n0 + row) * 512 + k0 + lc;                \
                cpa16(base + so, Ah + ao);                                      \
                cpa16(base + GT + so, Al + ao);                                 \
                cpa16(base + 2 * GT + so, Wh + wo_);                            \
                cpa16(base + 3 * GT + so, Wl + wo_);                            \
            }                                                                   \
            asm volatile("cp.async.commit_group;\n" ::: "memory");              \
        };                                                                      \
        issue(0, 0);                                                            \
        for (int s = 0; s < 16; s++) {                                          \
            const int bb = s & 1;                                               \
            __syncthreads();                                                    \
            if (s < 15) {                                                       \
                issue((s + 1) << 5, bb ^ 1);                                    \
                asm volatile("cp.async.wait_group 1;\n" ::: "memory");          \
            } else {                                                            \
                asm volatile("cp.async.wait_group 0;\n" ::: "memory");          \
            }                                                                   \
            __syncthreads();                                                    \
            unsigned base = sb + bb * GSTAGE;                                   \
            _Pragma("unroll") for (int kc = 0; kc < 2; kc++) {                  \
                const int kk = kc << 4;                                         \
                unsigned ah[4][4], al[4][4], bh[4][2], bl[4][2];                \
                _Pragma("unroll") for (int mt = 0; mt < 4; mt++) {              \
                    unsigned off = ((aRow + mt * 16) * 40 + kk + aCol) * 2;     \
                    ldsm4(base + off, ah[mt][0], ah[mt][1], ah[mt][2],          \
                          ah[mt][3]);                                           \
                    ldsm4(base + GT + off, al[mt][0], al[mt][1], al[mt][2],     \
                          al[mt][3]);                                           \
                }                                                               \
                _Pragma("unroll") for (int np = 0; np < 2; np++) {              \
                    unsigned off = ((bRow + np * 16) * 40 + kk + bCol) * 2;     \
                    unsigned r0, r1, r2, r3;                                    \
                    ldsm4(base + 2 * GT + off, r0, r1, r2, r3);                 \
                    bh[np * 2][0] = r0; bh[np * 2][1] = r1;                     \
                    bh[np * 2 + 1][0] = r2; bh[np * 2 + 1][1] = r3;             \
                    ldsm4(base + 3 * GT + off, r0, r1, r2, r3);                 \
                    bl[np * 2][0] = r0; bl[np * 2][1] = r1;                     \
                    bl[np * 2 + 1][0] = r2; bl[np * 2 + 1][1] = r3;             \
                }                                                               \
                _Pragma("unroll") for (int mt = 0; mt < 4; mt++)                \
                    _Pragma("unroll") for (int nt = 0; nt < 4; nt++) {          \
                        mma_bf16(acc[mt][nt], ah[mt], bh[nt]);                  \
                        mma_bf16(acc[mt][nt], al[mt], bh[nt]);                  \
                        mma_bf16(acc[mt][nt], ah[mt], bl[nt]);                  \
                    }                                                           \
            }                                                                   \
        }                                                                       \
    }

// ---------------------------------------------------------------------------
// fp16-single GEMM mainloop (K=512, 128x128 tile, cp.async dbuf) — qkv/pos.
// 2 planes per stage instead of 4; 1 MMA per product instead of 3.
// ---------------------------------------------------------------------------
#define FT 10240
#define FSTAGE (2 * FT)
#define FSM (2 * FSTAGE)

#define GEMM_MAIN_F16(Af, Wf, m0, n0, acc)                                      \
    {                                                                           \
        const unsigned sb = s2u(smem);                                          \
        const int lrow = tid >> 2, lc = (tid & 3) << 3;                         \
        auto issue = [&](int k0, int bb) {                                      \
            unsigned base = sb + bb * FSTAGE;                                   \
            _Pragma("unroll") for (int t = 0; t < 2; t++) {                     \
                int row = lrow + t * 64;                                        \
                unsigned so = (unsigned)row * 80 + ((unsigned)lc << 1);         \
                cpa16(base + so, Af + (size_t)(m0 + row) * 512 + k0 + lc);      \
                cpa16(base + FT + so, Wf + (size_t)(n0 + row) * 512 + k0 + lc); \
            }                                                                   \
            asm volatile("cp.async.commit_group;\n" ::: "memory");              \
        };                                                                      \
        issue(0, 0);                                                            \
        for (int s = 0; s < 16; s++) {                                          \
            const int bb = s & 1;                                               \
            __syncthreads();                                                    \
            if (s < 15) {                                                       \
                issue((s + 1) << 5, bb ^ 1);                                    \
                asm volatile("cp.async.wait_group 1;\n" ::: "memory");          \
            } else {                                                            \
                asm volatile("cp.async.wait_group 0;\n" ::: "memory");          \
            }                                                                   \
            __syncthreads();                                                    \
            unsigned base = sb + bb * FSTAGE;                                   \
            _Pragma("unroll") for (int kc = 0; kc < 2; kc++) {                  \
                const int kk = kc << 4;                                         \
                unsigned af[4][4], bf[4][2];                                    \
                _Pragma("unroll") for (int mt = 0; mt < 4; mt++) {              \
                    unsigned off = ((aRow + mt * 16) * 40 + kk + aCol) * 2;     \
                    ldsm4(base + off, af[mt][0], af[mt][1], af[mt][2],          \
                          af[mt][3]);                                           \
                }                                                               \
                _Pragma("unroll") for (int np = 0; np < 2; np++) {              \
                    unsigned off = ((bRow + np * 16) * 40 + kk + bCol) * 2;     \
                    unsigned r0, r1, r2, r3;                                    \
                    ldsm4(base + FT + off, r0, r1, r2, r3);                     \
                    bf[np * 2][0] = r0; bf[np * 2][1] = r1;                     \
                    bf[np * 2 + 1][0] = r2; bf[np * 2 + 1][1] = r3;             \
                }                                                               \
                _Pragma("unroll") for (int mt = 0; mt < 4; mt++)                \
                    _Pragma("unroll") for (int nt = 0; nt < 4; nt++)            \
                        mma_f16(acc[mt][nt], af[mt], bf[nt]);                   \
            }                                                                   \
        }                                                                       \
    }

// ---------------------------------------------------------------------------
// Fused qkv-proj + pos-proj GEMM (fp16 single). 1-D grid, 832 blocks.
// ---------------------------------------------------------------------------
__global__ __launch_bounds__(256, 2) void gemm_qkv_pos() {
    extern __shared__ char smem[];
    const int tid = threadIdx.x, l = tid & 31, w = tid >> 5;
    const int wm = w >> 2, wn = w & 3;
    const int aRow = wm * 64 + (l & 15);
    const int aCol = (l & 16) >> 1;
    const int bRow = wn * 32 + (l & 7) + ((l & 16) >> 1);
    const int bCol = l & 8;

    const int bid = blockIdx.x;
    const __half *Af, *Wf;
    int m0, n0, mode;
    if (bid < 768) {
        Af = g_xf; Wf = g_wqf;
        m0 = (bid / 12) << 7; n0 = (bid % 12) << 7; mode = 1;
    } else {
        int t = bid - 768;
        Af = g_psf; Wf = g_wpf;
        m0 = (t >> 2) << 7; n0 = (t & 3) << 7; mode = 2;
    }

    float acc[4][4][4];
#pragma unroll
    for (int i = 0; i < 4; i++)
#pragma unroll
        for (int j = 0; j < 4; j++)
#pragma unroll
            for (int e = 0; e < 4; e++) acc[i][j][e] = 0.f;

    GEMM_MAIN_F16(Af, Wf, m0, n0, acc);

    const int er = m0 + wm * 64 + (l >> 2);
    const int ec = n0 + wn * 32 + ((l & 3) << 1);
#pragma unroll
    for (int mt = 0; mt < 4; mt++) {
#pragma unroll
        for (int nt = 0; nt < 4; nt++) {
            int col = ec + nt * 8;
#pragma unroll
            for (int half = 0; half < 2; half++) {
                int r = er + mt * 16 + half * 8;
                float a0 = acc[mt][nt][half * 2];
                float a1 = acc[mt][nt][half * 2 + 1];
                if (mode == 1) {
                    int hh_ = col / 192;
                    int rem = col - hh_ * 192;
                    int part = rem >> 6, d = rem & 63;
                    if (part == 0) {
                        *(float2*)&g_q[(size_t)r * 512 + hh_ * 64 + d] =
                            make_float2(a0, a1);
                    } else {
                        int b = r >> 10, ll2 = r & 1023;
                        size_t idx =
                            (((size_t)(b * 8 + hh_)) * 1024 + ll2) * 64 + d;
                        __half2 hv = __floats2half2_rn(a0, a1);
                        if (part == 1) *(__half2*)&g_k[idx] = hv;
                        else           *(__half2*)&g_v[idx] = hv;
                    }
                } else {
                    int hh_ = col >> 6, d = col & 63;
                    size_t idx = (((size_t)hh_) * 2048 + r) * 64 + d;
                    *(__half2*)&g_p[idx] = __floats2half2_rn(a0, a1);
                }
            }
        }
    }
}

// ---------------------------------------------------------------------------
// Standalone out-proj GEMM (split bf16): out = ctx @ wout^T + bias.
// ---------------------------------------------------------------------------
__global__ __launch_bounds__(256, 2) void gemm_out(
    const float* __restrict__ bias, float* __restrict__ C_ext) {
    extern __shared__ char smem[];
    const int tid = threadIdx.x, l = tid & 31, w = tid >> 5;
    const int wm = w >> 2, wn = w & 3;
    const int aRow = wm * 64 + (l & 15);
    const int aCol = (l & 16) >> 1;
    const int bRow = wn * 32 + (l & 7) + ((l & 16) >> 1);
    const int bCol = l & 8;
    const int m0 = blockIdx.y << 7, n0 = blockIdx.x << 7;

    float acc[4][4][4];
#pragma unroll
    for (int i = 0; i < 4; i++)
#pragma unroll
        for (int j = 0; j < 4; j++)
#pragma unroll
            for (int e = 0; e < 4; e++) acc[i][j][e] = 0.f;

    GEMM_MAIN(g_cth, g_ctl, g_woh, g_wol, m0, n0, acc);

    const int er = m0 + wm * 64 + (l >> 2);
    const int ec = n0 + wn * 32 + ((l & 3) << 1);
#pragma unroll
    for (int mt = 0; mt < 4; mt++) {
#pragma unroll
        for (int nt = 0; nt < 4; nt++) {
            int col = ec + nt * 8;
            float2 bb2 = *(const float2*)&bias[col];
#pragma unroll
            for (int half = 0; half < 2; half++) {
                int r = er + mt * 16 + half * 8;
                *(float2*)&C_ext[(size_t)r * 512 + col] =
                    make_float2(acc[mt][nt][half * 2] + bb2.x,
                                acc[mt][nt][half * 2 + 1] + bb2.y);
            }
        }
    }
}

// ---------------------------------------------------------------------------
// Fused attention + in-kernel normalization. Grid (8, 64), 256 thr, 2 CTA/SM.
// ---------------------------------------------------------------------------
#define AP0 0
#define AK0 55296
#define AV0 73728
#define ASCRH 92160
#define AINV ASCRH
#define SM_BYTES_A 113664

__global__ __launch_bounds__(256, 2) void attn_kernel(
    const float* __restrict__ ubias, const float* __restrict__ vbias,
    float* __restrict__ attn) {
    extern __shared__ char smem[];

    const int tid = threadIdx.x, l = tid & 31, w = tid >> 5;
    const int bh = blockIdx.y, b = bh >> 3, h = bh & 7;
    const int q0 = blockIdx.x << 7;
    const int qs = w << 4;
    const float scale = 0.04419417382415922f;  // 1/sqrt(512)

    const unsigned pB0 = s2u(smem + AP0);
    const unsigned kB0 = s2u(smem + AK0);
    const unsigned vB0 = s2u(smem + AV0);
    __half* scrh = (__half*)(smem + ASCRH) + w * 16 * 84;

    // ---- QU/QV staging (overlaps P buffers; consumed before first tile) ----
    {
        __half* QU = (__half*)(smem + 0);
        __half* QV = (__half*)(smem + 18432);
        for (int idx = tid; idx < 4096; idx += 256) {
            int qi = idx >> 5, d2 = (idx & 31) << 1;
            float2 qv = *(const float2*)&g_q[((size_t)(b * Lc + q0 + qi)) * 512 +
                                             h * 64 + d2];
            *(unsigned*)&QU[qi * 72 + d2] =
                packh2((qv.x + ubias[h * 64 + d2]) * scale,
                       (qv.y + ubias[h * 64 + d2 + 1]) * scale);
            *(unsigned*)&QV[qi * 72 + d2] =
                packh2((qv.x + vbias[h * 64 + d2]) * scale,
                       (qv.y + vbias[h * 64 + d2 + 1]) * scale);
        }
    }
    __syncthreads();

    unsigned au[4][4], av[4][4];
    {
        unsigned baseU = s2u(smem + 0), baseV = s2u(smem + 18432);
        int row = qs + (l & 15), colp = (l & 16) >> 1;
#pragma unroll
        for (int kc = 0; kc < 4; kc++) {
            unsigned off = (row * 72 + kc * 16 + colp) * 2;
            ldsm4(baseU + off, au[kc][0], au[kc][1], au[kc][2], au[kc][3]);
            ldsm4(baseV + off, av[kc][0], av[kc][1], av[kc][2], av[kc][3]);
        }
    }
    __syncthreads();

    auto issue_tile = [&](int kt0, int bb) {
        size_t gb = (((size_t)bh) * 1024 + kt0) * 64;
        const uint4* GK = (const uint4*)(g_k + gb);
        const uint4* GV = (const uint4*)(g_v + gb);
        int pbase = kt0 - q0 + 896;
        const uint4* GP = (const uint4*)(g_p + (((size_t)h) * 2048 + pbase) * 64);
        unsigned kb = kB0 + bb * 9216;
        unsigned vb = vB0 + bb * 9216;
        unsigned pb = pB0 + bb * 27648;
#pragma unroll
        for (int t = 0; t < 2; t++) {
            int i = tid + t * 256;
            unsigned so = (unsigned)((i >> 3) * 9 + (i & 7)) * 16;
            cpa16(kb + so, GK + i);
            cpa16(vb + so, GV + i);
        }
#pragma unroll
        for (int t = 0; t < 6; t++) {
            int i = tid + t * 256;
            unsigned so = (unsigned)((i >> 3) * 9 + (i & 7)) * 16;
            cpa16(pb + so, GP + i);
        }
        asm volatile("cp.async.commit_group;\n" ::: "memory");
    };

    issue_tile(0, 0);

    float ct[8][4];
#pragma unroll
    for (int nt = 0; nt < 8; nt++)
#pragma unroll
        for (int e = 0; e < 4; e++) ct[nt][e] = 0.f;
    float rs_lo = 0.f, rs_hi = 0.f;

    const int nlane = (l & 7) + ((l & 16) >> 1);
    const int klane = l & 8;
    const int tkl = (l & 7) + (l & 8);
    const int tnl = (l & 16) >> 1;
    const int r0w = 112 - qs;

    for (int kt = 0; kt < 16; kt++) {
        const int bb = kt & 1;
        const int kt0 = kt << 6;
        __syncthreads();
        if (kt < 15) {
            issue_tile(kt0 + 64, bb ^ 1);
            asm volatile("cp.async.wait_group 1;\n" ::: "memory");
        } else {
            asm volatile("cp.async.wait_group 0;\n" ::: "memory");
        }
        __syncthreads();

        const unsigned kB = kB0 + bb * 9216;
        const unsigned vB = vB0 + bb * 9216;
        const unsigned pB = pB0 + bb * 27648;

        float bd[10][4];
#pragma unroll
        for (int nt = 0; nt < 10; nt++)
#pragma unroll
            for (int e = 0; e < 4; e++) bd[nt][e] = 0.f;
#pragma unroll
        for (int np = 0; np < 5; np++) {
            int nb = r0w + np * 16 + nlane;
#pragma unroll
            for (int kc = 0; kc < 4; kc++) {
                unsigned r0, r1, r2, r3;
                ldsm4(pB + (nb * 72 + kc * 16 + klane) * 2, r0, r1, r2, r3);
                unsigned b0[2] = {r0, r1}, b1[2] = {r2, r3};
                mma_f16(bd[np * 2], av[kc], b0);
                mma_f16(bd[np * 2 + 1], av[kc], b1);
            }
        }
        {
            int r = l >> 2, col = ((l & 3) << 1);
#pragma unroll
            for (int nt = 0; nt < 10; nt++) {
                *(__half2*)&scrh[r * 84 + nt * 8 + col] =
                    __floats2half2_rn(bd[nt][0], bd[nt][1]);
                *(__half2*)&scrh[(r + 8) * 84 + nt * 8 + col] =
                    __floats2half2_rn(bd[nt][2], bd[nt][3]);
            }
        }
        __syncwarp();

        float sc[8][4];
#pragma unroll
        for (int nt = 0; nt < 8; nt++)
#pragma unroll
            for (int e = 0; e < 4; e++) sc[nt][e] = 0.f;
#pragma unroll
        for (int np = 0; np < 4; np++) {
            int nb = np * 16 + nlane;
#pragma unroll
            for (int kc = 0; kc < 4; kc++) {
                unsigned r0, r1, r2, r3;
                ldsm4(kB + (nb * 72 + kc * 16 + klane) * 2, r0, r1, r2, r3);
                unsigned b0[2] = {r0, r1}, b1[2] = {r2, r3};
                mma_f16(sc[np * 2], au[kc], b0);
                mma_f16(sc[np * 2 + 1], au[kc], b1);
            }
        }

        {
            int r = l >> 2;
#pragma unroll
            for (int nt = 0; nt < 8; nt++) {
                int kk = nt * 8 + ((l & 3) << 1);
                int j = kk - r + 15;
                sc[nt][0] += __half2float(scrh[r * 84 + j]);
                sc[nt][1] += __half2float(scrh[r * 84 + j + 1]);
                int j2 = kk - (r + 8) + 15;
                sc[nt][2] += __half2float(scrh[(r + 8) * 84 + j2]);
                sc[nt][3] += __half2float(scrh[(r + 8) * 84 + j2 + 1]);
            }
#pragma unroll
            for (int nt = 0; nt < 8; nt++) {
#pragma unroll
                for (int e = 0; e < 4; e++) sc[nt][e] = __expf(sc[nt][e]);
                rs_lo += sc[nt][0] + sc[nt][1];
                rs_hi += sc[nt][2] + sc[nt][3];
            }
            size_t rbase =
                ((size_t)bh * Lc + (q0 + qs + r)) * Lc + kt0 + ((l & 3) << 1);
#pragma unroll
            for (int nt = 0; nt < 8; nt++) {
                *(float2*)&attn[rbase + nt * 8] = make_float2(sc[nt][0], sc[nt][1]);
                *(float2*)&attn[rbase + 8 * Lc + nt * 8] =
                    make_float2(sc[nt][2], sc[nt][3]);
            }
        }

#pragma unroll
        for (int kc = 0; kc < 4; kc++) {
            unsigned pa[4];
            pa[0] = packh2(sc[2 * kc][0], sc[2 * kc][1]);
            pa[1] = packh2(sc[2 * kc][2], sc[2 * kc][3]);
            pa[2] = packh2(sc[2 * kc + 1][0], sc[2 * kc + 1][1]);
            pa[3] = packh2(sc[2 * kc + 1][2], sc[2 * kc + 1][3]);
            int krow = kc * 16 + tkl;
#pragma unroll
            for (int np = 0; np < 4; np++) {
                unsigned r0, r1, r2, r3;
                ldsm4t(vB + (krow * 72 + np * 16 + tnl) * 2, r0, r1, r2, r3);
                unsigned b0[2] = {r0, r1}, b1[2] = {r2, r3};
                mma_f16(ct[np * 2], pa, b0);
                mma_f16(ct[np * 2 + 1], pa, b1);
            }
        }
    }

    rs_lo += __shfl_xor_sync(0xffffffffu, rs_lo, 1);
    rs_lo += __shfl_xor_sync(0xffffffffu, rs_lo, 2);
    rs_hi += __shfl_xor_sync(0xffffffffu, rs_hi, 1);
    rs_hi += __shfl_xor_sync(0xffffffffu, rs_hi, 2);
    float inv_lo = 1.f / rs_lo, inv_hi = 1.f / rs_hi;
    float* INV = (float*)(smem + AINV);
    int r = l >> 2;
    if ((l & 3) == 0) {
        INV[qs + r] = inv_lo;
        INV[qs + r + 8] = inv_hi;
    }
    size_t cbase = ((size_t)(b * Lc + q0 + qs + r)) * 512 + h * 64 + ((l & 3) << 1);
#pragma unroll
    for (int nt = 0; nt < 8; nt++) {
        unsigned hh, lo;
        pack_split(ct[nt][0] * inv_lo, ct[nt][1] * inv_lo, hh, lo);
        *(unsigned*)&g_cth[cbase + nt * 8] = hh;
        *(unsigned*)&g_ctl[cbase + nt * 8] = lo;
        pack_split(ct[nt][2] * inv_hi, ct[nt][3] * inv_hi, hh, lo);
        *(unsigned*)&g_cth[cbase + 8 * 512 + nt * 8] = hh;
        *(unsigned*)&g_ctl[cbase + 8 * 512 + nt * 8] = lo;
    }

    // ---- in-kernel normalization: rescale this CTA's 128x1024 block ----
    __syncthreads();
    float4* A4 = (float4*)(attn + ((size_t)bh * Lc + q0) * Lc);
#pragma unroll
    for (int it = 0; it < 16; it++) {
        int id[8]; float4 v[8]; float iv[8];
#pragma unroll
        for (int j = 0; j < 8; j++) {
            id[j] = tid + (it * 8 + j) * 256;
            v[j] = A4[id[j]];
        }
#pragma unroll
        for (int j = 0; j < 8; j++) iv[j] = INV[id[j] >> 8];
#pragma unroll
        for (int j = 0; j < 8; j++) {
            v[j].x *= iv[j]; v[j].y *= iv[j]; v[j].z *= iv[j]; v[j].w *= iv[j];
            A4[id[j]] = v[j];
        }
    }
}

// ---------------------------------------------------------------------------
extern "C" void kernel_launch(void* const* d_in, const int* in_sizes, int n_in,
                              void* d_out, int out_size) {
    const float* x    = (const float*)d_in[0];
    const float* pos  = (const float*)d_in[1];
    const float* wqkv = (const float*)d_in[2];
    const float* wpos = (const float*)d_in[3];
    const float* wout = (const float*)d_in[4];
    const float* bout = (const float*)d_in[5];
    const float* ub   = (const float*)d_in[6];
    const float* vb   = (const float*)d_in[7];
    float* out = (float*)d_out;

    int attn_in_out = ((long long)out_size >= (long long)OUT_ELEMS + ATTN_ELEMS);
    float* attn_buf = attn_in_out ? (out + OUT_ELEMS) : g_attn_scratch;

    cvt_all<<<12799, 256>>>(x, wqkv, wpos, wout, pos);

    cudaFuncSetAttribute(gemm_qkv_pos, cudaFuncAttributeMaxDynamicSharedMemorySize,
                         FSM);
    gemm_qkv_pos<<<832, 256, FSM>>>();

    cudaFuncSetAttribute(attn_kernel, cudaFuncAttributeMaxDynamicSharedMemorySize,
                         SM_BYTES_A);
    attn_kernel<<<dim3(8, 64), 256, SM_BYTES_A>>>(ub, vb, attn_buf);

    cudaFuncSetAttribute(gemm_out, cudaFuncAttributeMaxDynamicSharedMemorySize,
                         GSM);
    gemm_out<<<dim3(4, 64), 256, GSM>>>(bout, out);
}